// round 9
// baseline (speedup 1.0000x reference)
#include <cuda_runtime.h>
#include <math.h>

#define Nn 50000
#define Ee 800000

// ---------------- device scratch (static, no allocation) ----------------
__device__ float        g_x[Nn * 64];     // current node features (pre-BN)
__device__ float        g_u[Nn * 64];     // u = x@A + b1   (dst side)
__device__ float        g_v[Nn * 64];     // v = x@B        (src side)
__device__ unsigned int g_agg[Nn * 64];   // encoded segment-max accumulator
__device__ int          g_hist[Nn];       // zero at entry (invariant)
__device__ int          g_cur[Nn];
__device__ int          g_sdst[Ee];       // edges sorted by dst
__device__ int          g_ssrc[Ee];
__device__ float        g_sum[64];
__device__ float        g_sumsq[64];

// ---------------- helpers ----------------
__device__ __forceinline__ unsigned int encf(float f) {
    unsigned int b = __float_as_uint(f);
    return (b & 0x80000000u) ? ~b : (b | 0x80000000u);
}
__device__ __forceinline__ float decf(unsigned int u) {
    return (u & 0x80000000u) ? __uint_as_float(u & 0x7FFFFFFFu)
                             : __uint_as_float(~u);
}
// mish(x) = x * (t^2+2t)/(t^2+2t+2), t=e^x
__device__ __forceinline__ float mishf(float x) {
    float xc = fminf(x, 40.0f);
    float t = __expf(xc);
    float num = fmaf(t, t, 2.0f * t);
    float r = __fdividef(num, num + 2.0f);
    return x * r;
}
__device__ __forceinline__ unsigned int tf32_of(float f) {
    unsigned int r;
    asm("cvt.rna.tf32.f32 %0, %1;" : "=r"(r) : "f"(f));
    return r;
}
__device__ __forceinline__ float tf32f(float f) {
    return __uint_as_float(tf32_of(f));
}
__device__ __forceinline__ void mma_tf32(float c[4],
    unsigned a0, unsigned a1, unsigned a2, unsigned a3,
    unsigned b0, unsigned b1) {
    asm volatile(
        "mma.sync.aligned.m16n8k8.row.col.f32.tf32.tf32.f32 "
        "{%0,%1,%2,%3}, {%4,%5,%6,%7}, {%8,%9}, {%0,%1,%2,%3};"
        : "+f"(c[0]), "+f"(c[1]), "+f"(c[2]), "+f"(c[3])
        : "r"(a0), "r"(a1), "r"(a2), "r"(a3), "r"(b0), "r"(b1));
}

// ---------------- sorting (counting sort by dst, once per call) ----------------
__global__ void k_hist(const int* __restrict__ dst) {
    int e = blockIdx.x * blockDim.x + threadIdx.x;
    if (e < Ee) atomicAdd(&g_hist[dst[e]], 1);
}
// 1 block, 1024 threads; consumes g_hist and re-zeroes it (entry invariant)
__global__ void k_scan() {
    __shared__ int ssum[1024];
    int t = threadIdx.x;
    const int CH = (Nn + 1023) / 1024;
    int base = t * CH;
    int s = 0;
    for (int i = 0; i < CH; i++) {
        int idx = base + i;
        if (idx < Nn) s += g_hist[idx];
    }
    ssum[t] = s;
    __syncthreads();
    for (int off = 1; off < 1024; off <<= 1) {
        int v = (t >= off) ? ssum[t - off] : 0;
        __syncthreads();
        ssum[t] += v;
        __syncthreads();
    }
    int prefix = (t == 0) ? 0 : ssum[t - 1];
    for (int i = 0; i < CH; i++) {
        int idx = base + i;
        if (idx < Nn) {
            int h = g_hist[idx];
            g_cur[idx] = prefix;
            g_hist[idx] = 0;            // restore zero for the next call
            prefix += h;
        }
    }
}
__global__ void k_scatter(const int* __restrict__ src, const int* __restrict__ dst) {
    int e = blockIdx.x * blockDim.x + threadIdx.x;
    if (e < Ee) {
        int d = dst[e];
        int p = atomicAdd(&g_cur[d], 1);
        g_sdst[p] = d;
        g_ssrc[p] = src[e];
    }
}

// ---------------- per-layer kernels ----------------
// node GEMM via TF32 mma: u = xn@(w1top - w1bot) + b1, v = xn@w1bot
// xn = BN(prev stats) folded input. Also zeroes g_agg for this layer.
#define NG_XST 68
#define NG_WST 132
#define NG_OFF_W   (64 * NG_XST)
#define NG_OFF_SC  (NG_OFF_W + 64 * NG_WST)
#define NG_OFF_SH  (NG_OFF_SC + 64)
#define NG_OFF_B1  (NG_OFF_SH + 64)
#define NG_SMEM    ((NG_OFF_B1 + 64) * 4)
__global__ void __launch_bounds__(256) k_node_gemm64(
    const float* __restrict__ x_in,  // null -> read g_x
    const float* __restrict__ w1, const float* __restrict__ b1,
    const float* __restrict__ g, const float* __restrict__ be) {
    extern __shared__ __align__(16) float smem[];
    float* sX = smem;                 // [64][68] tf32
    float* sW = smem + NG_OFF_W;      // [64][132] tf32 (cols 0-63 A, 64-127 B)
    float* s_sc = smem + NG_OFF_SC;
    float* s_sh = smem + NG_OFF_SH;
    float* s_b1 = smem + NG_OFF_B1;
    const float* x = x_in ? x_in : g_x;
    int t = threadIdx.x;
    int n0 = blockIdx.x * 64;
    // fused: zero the segment-max accumulator for this layer
    {
        int stride = gridDim.x * blockDim.x;
        for (int i = blockIdx.x * blockDim.x + t; i < Nn * 64; i += stride)
            g_agg[i] = 0u;
    }
    if (t < 64) {
        float sc = 1.0f, sh = 0.0f;
        if (g) {
            float mu = g_sum[t] * (1.0f / Nn);
            float var = g_sumsq[t] * (1.0f / Nn) - mu * mu;
            sc = rsqrtf(var + 1e-5f) * g[t];
            sh = be[t] - mu * sc;
        }
        s_sc[t] = sc;
        s_sh[t] = sh;
        s_b1[t] = b1[t];
    }
    // stage w1 -> sW (tf32)
#pragma unroll
    for (int r = 0; r < 8; r++) {
        int idx = r * 256 + t;           // 2048 float4 tasks
        int k = idx >> 5, c4 = idx & 31;
        float4 val;
        int col;
        if (c4 < 16) {                   // A = w1top - w1bot, cols 0-63
            col = c4 * 4;
            float4 tp = *(const float4*)(w1 + k * 64 + col);
            float4 bt = *(const float4*)(w1 + (k + 64) * 64 + col);
            val.x = tp.x - bt.x; val.y = tp.y - bt.y;
            val.z = tp.z - bt.z; val.w = tp.w - bt.w;
        } else {                         // B = w1bot, cols 64-127
            col = (c4 - 16) * 4;
            val = *(const float4*)(w1 + (k + 64) * 64 + col);
            col += 64;
        }
        float* dp = sW + k * NG_WST + col;
        dp[0] = tf32f(val.x); dp[1] = tf32f(val.y);
        dp[2] = tf32f(val.z); dp[3] = tf32f(val.w);
    }
    __syncthreads();
    // stage x (BN fold, tf32) -> sX
#pragma unroll
    for (int r = 0; r < 4; r++) {
        int idx = r * 256 + t;
        int nl = idx >> 4, k4 = (idx & 15) << 2;
        int n = n0 + nl;
        float4 xv = (n < Nn) ? *(const float4*)(x + n * 64 + k4)
                             : make_float4(0.f, 0.f, 0.f, 0.f);
        float4 scv = *(const float4*)(s_sc + k4);
        float4 shv = *(const float4*)(s_sh + k4);
        float* dp = sX + nl * NG_XST + k4;
        dp[0] = tf32f(fmaf(xv.x, scv.x, shv.x));
        dp[1] = tf32f(fmaf(xv.y, scv.y, shv.y));
        dp[2] = tf32f(fmaf(xv.z, scv.z, shv.z));
        dp[3] = tf32f(fmaf(xv.w, scv.w, shv.w));
    }
    __syncthreads();
    // MMA: warp w handles rows (w&3)*16 and col half (w>>2)*64
    int lane = t & 31;
    int gid = lane >> 2, tig = lane & 3;
    int w = t >> 5;
    int r0 = (w & 3) * 16;
    int ch = (w >> 2) * 64;
    float acc[8][4];
#pragma unroll
    for (int i = 0; i < 8; i++)
#pragma unroll
        for (int j = 0; j < 4; j++) acc[i][j] = 0.f;
#pragma unroll
    for (int kt = 0; kt < 8; kt++) {
        int k0 = kt * 8;
        unsigned a0 = __float_as_uint(sX[(r0 + gid)     * NG_XST + k0 + tig]);
        unsigned a1 = __float_as_uint(sX[(r0 + gid + 8) * NG_XST + k0 + tig]);
        unsigned a2 = __float_as_uint(sX[(r0 + gid)     * NG_XST + k0 + tig + 4]);
        unsigned a3 = __float_as_uint(sX[(r0 + gid + 8) * NG_XST + k0 + tig + 4]);
#pragma unroll
        for (int nt = 0; nt < 8; nt++) {
            unsigned b0 = __float_as_uint(sW[(k0 + tig)     * NG_WST + ch + nt * 8 + gid]);
            unsigned b1v = __float_as_uint(sW[(k0 + tig + 4) * NG_WST + ch + nt * 8 + gid]);
            mma_tf32(acc[nt], a0, a1, a2, a3, b0, b1v);
        }
    }
    // store: cols<64 -> u (+b1), cols>=64 -> v
    int nA = n0 + r0 + gid;
    int nB = nA + 8;
#pragma unroll
    for (int nt = 0; nt < 8; nt++) {
        int col = ch + nt * 8 + 2 * tig;
        float add0 = 0.f, add1 = 0.f;
        float* basep;
        int cc;
        if (col < 64) {
            add0 = s_b1[col]; add1 = s_b1[col + 1];
            basep = g_u; cc = col;
        } else {
            basep = g_v; cc = col - 64;
        }
        if (nA < Nn)
            *(float2*)(basep + nA * 64 + cc) =
                make_float2(acc[nt][0] + add0, acc[nt][1] + add1);
        if (nB < Nn)
            *(float2*)(basep + nB * 64 + cc) =
                make_float2(acc[nt][2] + add0, acc[nt][3] + add1);
    }
}

// layer-3 node GEMM: dout=8, BN(layer2) folded; zeroes g_agg[0..Nn*8)
__global__ void __launch_bounds__(256) k_node_gemm8(
    const float* __restrict__ w1, const float* __restrict__ b1,
    const float* __restrict__ g, const float* __restrict__ be) {
    __shared__ float sW[64 * 16];
    __shared__ float s_sc[64], s_sh[64];
    int t = threadIdx.x;
    {
        int stride = gridDim.x * blockDim.x;
        for (int i = blockIdx.x * blockDim.x + t; i < Nn * 8; i += stride)
            g_agg[i] = 0u;
    }
    if (t < 64) {
        float mu = g_sum[t] * (1.0f / Nn);
        float var = g_sumsq[t] * (1.0f / Nn) - mu * mu;
        float sc = rsqrtf(var + 1e-5f) * g[t];
        s_sc[t] = sc;
        s_sh[t] = be[t] - mu * sc;
    }
#pragma unroll
    for (int r = 0; r < 4; r++) {
        int idx = r * 256 + t;
        int k = idx >> 4, cc = idx & 15;
        float wB = w1[(k + 64) * 8 + (cc & 7)];
        sW[idx] = (cc < 8) ? (w1[k * 8 + cc] - wB) : wB;
    }
    __syncthreads();
    int n = blockIdx.x * 16 + (t >> 4);
    int cc = t & 15;
    if (n >= Nn) return;
    const float* xr = g_x + n * 64;
    float acc = 0.f;
#pragma unroll 16
    for (int k = 0; k < 64; k++) {
        float xn = fmaf(__ldg(xr + k), s_sc[k], s_sh[k]);
        acc = fmaf(xn, sW[k * 16 + cc], acc);
    }
    if (cc < 8) g_u[n * 8 + cc] = acc + b1[cc];
    else        g_v[n * 8 + cc - 8] = acc;
}

// edge kernel (dout=64): PERSISTENT. Each CTA loops over 128-edge tiles.
// TF32 mma + per-segment block reduction; interior segments -> plain store.
#define EB     128
#define NTILE  (Ee / EB)     // 6250
#define EGRID  592           // 148 SMs x 4 CTAs
#define SA_ST 68
#define OFF_W    (EB * SA_ST)
#define OFF_SST  (OFF_W + 64 * SA_ST)
#define OFF_NSEG (OFF_SST + 132)
#define EDGE_SMEM ((OFF_NSEG + 4) * 4)
__global__ void __launch_bounds__(256) k_edge64(const float* __restrict__ w2) {
    extern __shared__ __align__(16) float smem[];
    float* sA = smem;
    float* sW = smem + OFF_W;
    int* sSstart = (int*)(smem + OFF_SST);
    int* sNseg = (int*)(smem + OFF_NSEG);
    int t = threadIdx.x;
    int lane = t & 31;
    int gid = lane >> 2, tig = lane & 3;
    int ebase = (t >> 5) * 16;

    // zero BN stat accumulators once per layer
    if (blockIdx.x == 0 && t < 128) {
        if (t < 64) g_sum[t] = 0.f;
        else        g_sumsq[t - 64] = 0.f;
    }
    // stage w2 (tf32) ONCE per CTA
#pragma unroll
    for (int r = 0; r < 4; r++) {
        int idx = r * 256 + t;
        int k = idx >> 4, n4 = (idx & 15) << 2;
        float4 wv = *(const float4*)(w2 + k * 64 + n4);
        float* dp = sW + k * SA_ST + n4;
        dp[0] = tf32f(wv.x); dp[1] = tf32f(wv.y);
        dp[2] = tf32f(wv.z); dp[3] = tf32f(wv.w);
    }

    for (int tile = blockIdx.x; tile < NTILE; tile += EGRID) {
        int e0 = tile * EB;
        __syncthreads();   // smem reuse guard (covers w2 stage on iter 0)
        // warp 0: segment starts via flags + warp scan (dsts sorted)
        if (t < 32) {
            int base = t * 4;
            int d0 = __ldg(g_sdst + e0 + base);
            int d1 = __ldg(g_sdst + e0 + base + 1);
            int d2 = __ldg(g_sdst + e0 + base + 2);
            int d3 = __ldg(g_sdst + e0 + base + 3);
            int dm1 = (base > 0) ? __ldg(g_sdst + e0 + base - 1) : (d0 ^ 1);
            int h0 = (d0 != dm1), h1 = (d1 != d0), h2 = (d2 != d1), h3 = (d3 != d2);
            int lc0 = h0, lc1 = lc0 + h1, lc2 = lc1 + h2, lc3 = lc2 + h3;
            int c = lc3;
            int v = c;
#pragma unroll
            for (int o = 1; o < 32; o <<= 1) {
                int y = __shfl_up_sync(0xffffffffu, v, o);
                if (t >= o) v += y;
            }
            int off = v - c;
            if (h0) sSstart[off + lc0 - 1] = base;
            if (h1) sSstart[off + lc1 - 1] = base + 1;
            if (h2) sSstart[off + lc2 - 1] = base + 2;
            if (h3) sSstart[off + lc3 - 1] = base + 3;
            if (t == 31) {
                *sNseg = off + c;
                sSstart[off + c] = EB;
            }
        }
        // gather + mish -> sA (tf32)
#pragma unroll
        for (int r = 0; r < 8; r++) {
            int idx = r * 256 + t;
            int el = idx >> 4;
            int k4 = (idx & 15) << 2;
            int d = __ldg(g_sdst + e0 + el);
            int s = __ldg(g_ssrc + e0 + el);
            float4 uu = *(const float4*)(g_u + d * 64 + k4);
            float4 vv = *(const float4*)(g_v + s * 64 + k4);
            float4 o;
            o.x = tf32f(mishf(uu.x + vv.x));
            o.y = tf32f(mishf(uu.y + vv.y));
            o.z = tf32f(mishf(uu.z + vv.z));
            o.w = tf32f(mishf(uu.w + vv.w));
            *(float4*)(sA + el * SA_ST + k4) = o;
        }
        __syncthreads();
        // MMA: warp w -> C[16][64] for edges [w*16, w*16+16)
        float acc[8][4];
#pragma unroll
        for (int i = 0; i < 8; i++)
#pragma unroll
            for (int j = 0; j < 4; j++) acc[i][j] = 0.f;
#pragma unroll
        for (int kt = 0; kt < 8; kt++) {
            int k0 = kt * 8;
            unsigned a0 = __float_as_uint(sA[(ebase + gid)     * SA_ST + k0 + tig]);
            unsigned a1 = __float_as_uint(sA[(ebase + gid + 8) * SA_ST + k0 + tig]);
            unsigned a2 = __float_as_uint(sA[(ebase + gid)     * SA_ST + k0 + tig + 4]);
            unsigned a3 = __float_as_uint(sA[(ebase + gid + 8) * SA_ST + k0 + tig + 4]);
#pragma unroll
            for (int nt = 0; nt < 8; nt++) {
                unsigned b0 = __float_as_uint(sW[(k0 + tig)     * SA_ST + nt * 8 + gid]);
                unsigned b1 = __float_as_uint(sW[(k0 + tig + 4) * SA_ST + nt * 8 + gid]);
                mma_tf32(acc[nt], a0, a1, a2, a3, b0, b1);
            }
        }
        __syncwarp();
        // write C back over sA
#pragma unroll
        for (int nt = 0; nt < 8; nt++) {
            int col = nt * 8 + 2 * tig;
            *(float2*)(sA + (ebase + gid)     * SA_ST + col) = make_float2(acc[nt][0], acc[nt][1]);
            *(float2*)(sA + (ebase + gid + 8) * SA_ST + col) = make_float2(acc[nt][2], acc[nt][3]);
        }
        __syncthreads();
        // per-(segment, colgroup) reduction; interior segments -> plain store
        int S = *sNseg;
        for (int task = t; task < S * 16; task += 256) {
            int s = task >> 4, txx = task & 15;
            int st = sSstart[s], en = sSstart[s + 1];
            const float* aP = sA + st * SA_ST + txx * 4;
            float4 m = *(const float4*)aP;
            for (int i = 1; i < en - st; i++) {
                float4 h = *(const float4*)(aP + i * SA_ST);
                m.x = fmaxf(m.x, h.x);
                m.y = fmaxf(m.y, h.y);
                m.z = fmaxf(m.z, h.z);
                m.w = fmaxf(m.w, h.w);
            }
            int dd = __ldg(g_sdst + e0 + st);
            unsigned int* p = g_agg + dd * 64 + txx * 4;
            unsigned int ex = encf(m.x), ey = encf(m.y), ez = encf(m.z), ew = encf(m.w);
            if (s == 0 || s == S - 1) {
                atomicMax(p + 0, ex);
                atomicMax(p + 1, ey);
                atomicMax(p + 2, ez);
                atomicMax(p + 3, ew);
            } else {
                *(uint4*)p = make_uint4(ex, ey, ez, ew);
            }
        }
    }
}

// edge kernel (dout=8): thread handles 8 consecutive sorted edges (fp32)
__global__ void k_edge8(const float* __restrict__ w2) {
    __shared__ float sW[64];
    int t = threadIdx.x;
    if (t < 64) sW[t] = w2[t];
    __syncthreads();
    int base = (blockIdx.x * blockDim.x + t) * 8;
    if (base >= Ee) return;
    int curd = -1;
    float m[8];
#pragma unroll
    for (int j = 0; j < 8; j++) {
        int e = base + j;
        int d = g_sdst[e], s = g_ssrc[e];
        float4 u0 = *(const float4*)(g_u + d * 8);
        float4 u1 = *(const float4*)(g_u + d * 8 + 4);
        float4 v0 = *(const float4*)(g_v + s * 8);
        float4 v1 = *(const float4*)(g_v + s * 8 + 4);
        float pre[8];
        pre[0] = mishf(u0.x + v0.x); pre[1] = mishf(u0.y + v0.y);
        pre[2] = mishf(u0.z + v0.z); pre[3] = mishf(u0.w + v0.w);
        pre[4] = mishf(u1.x + v1.x); pre[5] = mishf(u1.y + v1.y);
        pre[6] = mishf(u1.z + v1.z); pre[7] = mishf(u1.w + v1.w);
        float h[8];
#pragma unroll
        for (int c = 0; c < 8; c++) {
            float a = 0.f;
#pragma unroll
            for (int k = 0; k < 8; k++) a = fmaf(pre[k], sW[k * 8 + c], a);
            h[c] = a;
        }
        if (d != curd) {
            if (curd >= 0) {
#pragma unroll
                for (int c = 0; c < 8; c++)
                    atomicMax(g_agg + curd * 8 + c, encf(m[c]));
            }
            curd = d;
#pragma unroll
            for (int c = 0; c < 8; c++) m[c] = h[c];
        } else {
#pragma unroll
            for (int c = 0; c < 8; c++) m[c] = fmaxf(m[c], h[c]);
        }
    }
#pragma unroll
    for (int c = 0; c < 8; c++) atomicMax(g_agg + curd * 8 + c, encf(m[c]));
}

// decode agg -> g_x (+b2, empty->0), accumulate BN stats
__global__ void k_decode_stats64(const float* __restrict__ b2) {
    __shared__ float ss[64], sq[64];
    int t = threadIdx.x;
    if (t < 64) { ss[t] = 0.f; sq[t] = 0.f; }
    __syncthreads();
    int c = t & 63;
    float b2c = b2[c];
    float ls = 0.f, lq = 0.f;
    int stride = gridDim.x * blockDim.x;
    for (int i = blockIdx.x * blockDim.x + t; i < Nn * 64; i += stride) {
        unsigned int a = g_agg[i];
        float val = (a == 0u) ? 0.f : (decf(a) + b2c);
        g_x[i] = val;
        ls += val;
        lq += val * val;
    }
    atomicAdd(&ss[c], ls);
    atomicAdd(&sq[c], lq);
    __syncthreads();
    if (t < 64) {
        atomicAdd(&g_sum[t], ss[t]);
        atomicAdd(&g_sumsq[t], sq[t]);
    }
}

__global__ void k_decode_out(float* __restrict__ out, const float* __restrict__ b2) {
    int i = blockIdx.x * blockDim.x + threadIdx.x;
    if (i < Nn * 8) {
        unsigned int a = g_agg[i];
        out[i] = (a == 0u) ? 0.f : (decf(a) + b2[i & 7]);
    }
}

// ---------------- launch ----------------
extern "C" void kernel_launch(void* const* d_in, const int* in_sizes, int n_in,
                              void* d_out, int out_size) {
    const float* x  = (const float*)d_in[0];
    const int*   ei = (const int*)d_in[1];
    const int* src = ei;        // edge_index[0]
    const int* dst = ei + Ee;   // edge_index[1]

    const float* W1[4] = {(const float*)d_in[3], (const float*)d_in[9],
                          (const float*)d_in[15], (const float*)d_in[21]};
    const float* B1[4] = {(const float*)d_in[4], (const float*)d_in[10],
                          (const float*)d_in[16], (const float*)d_in[22]};
    const float* W2[4] = {(const float*)d_in[5], (const float*)d_in[11],
                          (const float*)d_in[17], (const float*)d_in[23]};
    const float* B2[4] = {(const float*)d_in[6], (const float*)d_in[12],
                          (const float*)d_in[18], (const float*)d_in[24]};
    const float* G[3]  = {(const float*)d_in[7], (const float*)d_in[13],
                          (const float*)d_in[19]};
    const float* BE[3] = {(const float*)d_in[8], (const float*)d_in[14],
                          (const float*)d_in[20]};

    cudaFuncSetAttribute(k_edge64, cudaFuncAttributeMaxDynamicSharedMemorySize,
                         EDGE_SMEM);
    cudaFuncSetAttribute(k_node_gemm64, cudaFuncAttributeMaxDynamicSharedMemorySize,
                         NG_SMEM);

    // sort edges by dst (counting sort; g_hist is zero at entry by invariant)
    k_hist<<<(Ee + 255) / 256, 256>>>(dst);
    k_scan<<<1, 1024>>>();
    k_scatter<<<(Ee + 255) / 256, 256>>>(src, dst);

    // layers 0..2 (din=dout=64); BN of layer l-1 folded into node GEMM of l
    for (int l = 0; l < 3; l++) {
        k_node_gemm64<<<(Nn + 63) / 64, 256, NG_SMEM>>>(
            l == 0 ? x : nullptr, W1[l], B1[l],
            l == 0 ? nullptr : G[l - 1], l == 0 ? nullptr : BE[l - 1]);
        k_edge64<<<EGRID, 256, EDGE_SMEM>>>(W2[l]);
        k_decode_stats64<<<592, 256>>>(B2[l]);
    }

    // layer 3 (din=64, dout=8, BN of layer2 folded) -> d_out
    k_node_gemm8<<<(Nn + 15) / 16, 256>>>(W1[3], B1[3], G[2], BE[2]);
    k_edge8<<<(Ee / 8 + 255) / 256, 256>>>(W2[3]);
    k_decode_out<<<(Nn * 8 + 255) / 256, 256>>>((float*)d_out, B2[3]);
}

// round 10
// speedup vs baseline: 1.0244x; 1.0244x over previous
#include <cuda_runtime.h>
#include <math.h>

#define Nn 50000
#define Ee 800000

// ---------------- device scratch (static, no allocation) ----------------
__device__ float        g_x[Nn * 64];     // current node features (pre-BN)
__device__ float        g_u[Nn * 64];     // u = x@A + b1   (dst side)
__device__ float        g_v[Nn * 64];     // v = x@B        (src side)
__device__ __align__(16) unsigned int g_agg[Nn * 64];  // encoded seg-max acc
__device__ int          g_hist[Nn];       // zero at entry (invariant)
__device__ int          g_cur[Nn];
__device__ int          g_sdst[Ee];       // edges sorted by dst
__device__ int          g_ssrc[Ee];
__device__ float        g_sum[64];
__device__ float        g_sumsq[64];

// ---------------- helpers ----------------
__device__ __forceinline__ unsigned int encf(float f) {
    unsigned int b = __float_as_uint(f);
    return (b & 0x80000000u) ? ~b : (b | 0x80000000u);
}
__device__ __forceinline__ float decf(unsigned int u) {
    return (u & 0x80000000u) ? __uint_as_float(u & 0x7FFFFFFFu)
                             : __uint_as_float(~u);
}
// mish(x) = x * (t^2+2t)/(t^2+2t+2), t=e^x
__device__ __forceinline__ float mishf(float x) {
    float xc = fminf(x, 40.0f);
    float t = __expf(xc);
    float num = fmaf(t, t, 2.0f * t);
    float r = __fdividef(num, num + 2.0f);
    return x * r;
}
__device__ __forceinline__ unsigned int tf32_of(float f) {
    unsigned int r;
    asm("cvt.rna.tf32.f32 %0, %1;" : "=r"(r) : "f"(f));
    return r;
}
__device__ __forceinline__ float tf32f(float f) {
    return __uint_as_float(tf32_of(f));
}
__device__ __forceinline__ void mma_tf32(float c[4],
    unsigned a0, unsigned a1, unsigned a2, unsigned a3,
    unsigned b0, unsigned b1) {
    asm volatile(
        "mma.sync.aligned.m16n8k8.row.col.f32.tf32.tf32.f32 "
        "{%0,%1,%2,%3}, {%4,%5,%6,%7}, {%8,%9}, {%0,%1,%2,%3};"
        : "+f"(c[0]), "+f"(c[1]), "+f"(c[2]), "+f"(c[3])
        : "r"(a0), "r"(a1), "r"(a2), "r"(a3), "r"(b0), "r"(b1));
}

// ---------------- sorting (counting sort by dst, once per call) ----------------
__global__ void k_hist(const int* __restrict__ dst) {
    int e = blockIdx.x * blockDim.x + threadIdx.x;
    if (e < Ee) atomicAdd(&g_hist[dst[e]], 1);
}
// 1 block, 1024 threads; consumes g_hist and re-zeroes it (entry invariant)
__global__ void k_scan() {
    __shared__ int ssum[1024];
    int t = threadIdx.x;
    const int CH = (Nn + 1023) / 1024;
    int base = t * CH;
    int s = 0;
    for (int i = 0; i < CH; i++) {
        int idx = base + i;
        if (idx < Nn) s += g_hist[idx];
    }
    ssum[t] = s;
    __syncthreads();
    for (int off = 1; off < 1024; off <<= 1) {
        int v = (t >= off) ? ssum[t - off] : 0;
        __syncthreads();
        ssum[t] += v;
        __syncthreads();
    }
    int prefix = (t == 0) ? 0 : ssum[t - 1];
    for (int i = 0; i < CH; i++) {
        int idx = base + i;
        if (idx < Nn) {
            int h = g_hist[idx];
            g_cur[idx] = prefix;
            g_hist[idx] = 0;            // restore zero for the next call
            prefix += h;
        }
    }
}
__global__ void k_scatter(const int* __restrict__ src, const int* __restrict__ dst) {
    int e = blockIdx.x * blockDim.x + threadIdx.x;
    if (e < Ee) {
        int d = dst[e];
        int p = atomicAdd(&g_cur[d], 1);
        g_sdst[p] = d;
        g_ssrc[p] = src[e];
    }
}

// ---------------- per-layer kernels ----------------
// node GEMM via TF32 mma: u = xn@(w1top - w1bot) + b1, v = xn@w1bot
// xn = BN(prev stats) folded input. Also zeroes g_agg (uint4) for this layer.
#define NG_XST 68
#define NG_WST 132
#define NG_OFF_W   (64 * NG_XST)
#define NG_OFF_SC  (NG_OFF_W + 64 * NG_WST)
#define NG_OFF_SH  (NG_OFF_SC + 64)
#define NG_OFF_B1  (NG_OFF_SH + 64)
#define NG_SMEM    ((NG_OFF_B1 + 64) * 4)
__global__ void __launch_bounds__(256) k_node_gemm64(
    const float* __restrict__ x_in,  // null -> read g_x
    const float* __restrict__ w1, const float* __restrict__ b1,
    const float* __restrict__ g, const float* __restrict__ be) {
    extern __shared__ __align__(16) float smem[];
    float* sX = smem;                 // [64][68] tf32
    float* sW = smem + NG_OFF_W;      // [64][132] tf32 (cols 0-63 A, 64-127 B)
    float* s_sc = smem + NG_OFF_SC;
    float* s_sh = smem + NG_OFF_SH;
    float* s_b1 = smem + NG_OFF_B1;
    const float* x = x_in ? x_in : g_x;
    int t = threadIdx.x;
    int n0 = blockIdx.x * 64;
    // fused: zero the segment-max accumulator with STG.128
    {
        uint4* ap = (uint4*)g_agg;
        uint4 z = make_uint4(0u, 0u, 0u, 0u);
        int stride = gridDim.x * blockDim.x;
        for (int i = blockIdx.x * blockDim.x + t; i < Nn * 16; i += stride)
            ap[i] = z;
    }
    if (t < 64) {
        float sc = 1.0f, sh = 0.0f;
        if (g) {
            float mu = g_sum[t] * (1.0f / Nn);
            float var = g_sumsq[t] * (1.0f / Nn) - mu * mu;
            sc = rsqrtf(var + 1e-5f) * g[t];
            sh = be[t] - mu * sc;
        }
        s_sc[t] = sc;
        s_sh[t] = sh;
        s_b1[t] = b1[t];
    }
    // stage w1 -> sW (tf32)
#pragma unroll
    for (int r = 0; r < 8; r++) {
        int idx = r * 256 + t;           // 2048 float4 tasks
        int k = idx >> 5, c4 = idx & 31;
        float4 val;
        int col;
        if (c4 < 16) {                   // A = w1top - w1bot, cols 0-63
            col = c4 * 4;
            float4 tp = *(const float4*)(w1 + k * 64 + col);
            float4 bt = *(const float4*)(w1 + (k + 64) * 64 + col);
            val.x = tp.x - bt.x; val.y = tp.y - bt.y;
            val.z = tp.z - bt.z; val.w = tp.w - bt.w;
        } else {                         // B = w1bot, cols 64-127
            col = (c4 - 16) * 4;
            val = *(const float4*)(w1 + (k + 64) * 64 + col);
            col += 64;
        }
        float* dp = sW + k * NG_WST + col;
        dp[0] = tf32f(val.x); dp[1] = tf32f(val.y);
        dp[2] = tf32f(val.z); dp[3] = tf32f(val.w);
    }
    __syncthreads();
    // stage x (BN fold, tf32) -> sX
#pragma unroll
    for (int r = 0; r < 4; r++) {
        int idx = r * 256 + t;
        int nl = idx >> 4, k4 = (idx & 15) << 2;
        int n = n0 + nl;
        float4 xv = (n < Nn) ? *(const float4*)(x + n * 64 + k4)
                             : make_float4(0.f, 0.f, 0.f, 0.f);
        float4 scv = *(const float4*)(s_sc + k4);
        float4 shv = *(const float4*)(s_sh + k4);
        float* dp = sX + nl * NG_XST + k4;
        dp[0] = tf32f(fmaf(xv.x, scv.x, shv.x));
        dp[1] = tf32f(fmaf(xv.y, scv.y, shv.y));
        dp[2] = tf32f(fmaf(xv.z, scv.z, shv.z));
        dp[3] = tf32f(fmaf(xv.w, scv.w, shv.w));
    }
    __syncthreads();
    // MMA: warp w handles rows (w&3)*16 and col half (w>>2)*64
    int lane = t & 31;
    int gid = lane >> 2, tig = lane & 3;
    int w = t >> 5;
    int r0 = (w & 3) * 16;
    int ch = (w >> 2) * 64;
    float acc[8][4];
#pragma unroll
    for (int i = 0; i < 8; i++)
#pragma unroll
        for (int j = 0; j < 4; j++) acc[i][j] = 0.f;
#pragma unroll
    for (int kt = 0; kt < 8; kt++) {
        int k0 = kt * 8;
        unsigned a0 = __float_as_uint(sX[(r0 + gid)     * NG_XST + k0 + tig]);
        unsigned a1 = __float_as_uint(sX[(r0 + gid + 8) * NG_XST + k0 + tig]);
        unsigned a2 = __float_as_uint(sX[(r0 + gid)     * NG_XST + k0 + tig + 4]);
        unsigned a3 = __float_as_uint(sX[(r0 + gid + 8) * NG_XST + k0 + tig + 4]);
#pragma unroll
        for (int nt = 0; nt < 8; nt++) {
            unsigned b0 = __float_as_uint(sW[(k0 + tig)     * NG_WST + ch + nt * 8 + gid]);
            unsigned b1v = __float_as_uint(sW[(k0 + tig + 4) * NG_WST + ch + nt * 8 + gid]);
            mma_tf32(acc[nt], a0, a1, a2, a3, b0, b1v);
        }
    }
    // store: cols<64 -> u (+b1), cols>=64 -> v
    int nA = n0 + r0 + gid;
    int nB = nA + 8;
#pragma unroll
    for (int nt = 0; nt < 8; nt++) {
        int col = ch + nt * 8 + 2 * tig;
        float add0 = 0.f, add1 = 0.f;
        float* basep;
        int cc;
        if (col < 64) {
            add0 = s_b1[col]; add1 = s_b1[col + 1];
            basep = g_u; cc = col;
        } else {
            basep = g_v; cc = col - 64;
        }
        if (nA < Nn)
            *(float2*)(basep + nA * 64 + cc) =
                make_float2(acc[nt][0] + add0, acc[nt][1] + add1);
        if (nB < Nn)
            *(float2*)(basep + nB * 64 + cc) =
                make_float2(acc[nt][2] + add0, acc[nt][3] + add1);
    }
}

// layer-3 node GEMM: dout=8, BN(layer2) folded; zeroes g_agg[0..Nn*8) (uint4)
__global__ void __launch_bounds__(256) k_node_gemm8(
    const float* __restrict__ w1, const float* __restrict__ b1,
    const float* __restrict__ g, const float* __restrict__ be) {
    __shared__ float sW[64 * 16];
    __shared__ float s_sc[64], s_sh[64];
    int t = threadIdx.x;
    {
        uint4* ap = (uint4*)g_agg;
        uint4 z = make_uint4(0u, 0u, 0u, 0u);
        int stride = gridDim.x * blockDim.x;
        for (int i = blockIdx.x * blockDim.x + t; i < Nn * 2; i += stride)
            ap[i] = z;
    }
    if (t < 64) {
        float mu = g_sum[t] * (1.0f / Nn);
        float var = g_sumsq[t] * (1.0f / Nn) - mu * mu;
        float sc = rsqrtf(var + 1e-5f) * g[t];
        s_sc[t] = sc;
        s_sh[t] = be[t] - mu * sc;
    }
#pragma unroll
    for (int r = 0; r < 4; r++) {
        int idx = r * 256 + t;
        int k = idx >> 4, cc = idx & 15;
        float wB = w1[(k + 64) * 8 + (cc & 7)];
        sW[idx] = (cc < 8) ? (w1[k * 8 + cc] - wB) : wB;
    }
    __syncthreads();
    int n = blockIdx.x * 16 + (t >> 4);
    int cc = t & 15;
    if (n >= Nn) return;
    const float* xr = g_x + n * 64;
    float acc = 0.f;
#pragma unroll 16
    for (int k = 0; k < 64; k++) {
        float xn = fmaf(__ldg(xr + k), s_sc[k], s_sh[k]);
        acc = fmaf(xn, sW[k * 16 + cc], acc);
    }
    if (cc < 8) g_u[n * 8 + cc] = acc + b1[cc];
    else        g_v[n * 8 + cc - 8] = acc;
}

// edge kernel (dout=64): 128-edge tile, TF32 mma, per-segment block reduction.
// Interior segments -> plain final store; boundary segments -> atomicMax.
#define EB    128
#define SA_ST 68
#define OFF_W    (EB * SA_ST)
#define OFF_SST  (OFF_W + 64 * SA_ST)
#define OFF_NSEG (OFF_SST + 132)
#define EDGE_SMEM ((OFF_NSEG + 4) * 4)
__global__ void __launch_bounds__(256) k_edge64(const float* __restrict__ w2) {
    extern __shared__ __align__(16) float smem[];
    float* sA = smem;
    float* sW = smem + OFF_W;
    int* sSstart = (int*)(smem + OFF_SST);
    int* sNseg = (int*)(smem + OFF_NSEG);
    int t = threadIdx.x;
    int e0 = blockIdx.x * EB;

    // zero BN stat accumulators once per layer (before this layer's decode)
    if (blockIdx.x == 0 && t < 128) {
        if (t < 64) g_sum[t] = 0.f;
        else        g_sumsq[t - 64] = 0.f;
    }
    // warp 0: segment starts via flags + warp scan (dsts sorted)
    if (t < 32) {
        int base = t * 4;
        int d0 = __ldg(g_sdst + e0 + base);
        int d1 = __ldg(g_sdst + e0 + base + 1);
        int d2 = __ldg(g_sdst + e0 + base + 2);
        int d3 = __ldg(g_sdst + e0 + base + 3);
        int dm1 = (base > 0) ? __ldg(g_sdst + e0 + base - 1) : (d0 ^ 1);
        int h0 = (d0 != dm1), h1 = (d1 != d0), h2 = (d2 != d1), h3 = (d3 != d2);
        int lc0 = h0, lc1 = lc0 + h1, lc2 = lc1 + h2, lc3 = lc2 + h3;
        int c = lc3;
        int v = c;
#pragma unroll
        for (int o = 1; o < 32; o <<= 1) {
            int y = __shfl_up_sync(0xffffffffu, v, o);
            if (t >= o) v += y;
        }
        int off = v - c;
        if (h0) sSstart[off + lc0 - 1] = base;
        if (h1) sSstart[off + lc1 - 1] = base + 1;
        if (h2) sSstart[off + lc2 - 1] = base + 2;
        if (h3) sSstart[off + lc3 - 1] = base + 3;
        if (t == 31) {
            *sNseg = off + c;
            sSstart[off + c] = EB;
        }
    }
    // stage w2 (tf32), float4 loads
#pragma unroll
    for (int r = 0; r < 4; r++) {
        int idx = r * 256 + t;
        int k = idx >> 4, n4 = (idx & 15) << 2;
        float4 wv = *(const float4*)(w2 + k * 64 + n4);
        float* dp = sW + k * SA_ST + n4;
        dp[0] = tf32f(wv.x); dp[1] = tf32f(wv.y);
        dp[2] = tf32f(wv.z); dp[3] = tf32f(wv.w);
    }
    // gather + mish -> sA (tf32)
#pragma unroll
    for (int r = 0; r < 8; r++) {
        int idx = r * 256 + t;
        int el = idx >> 4;
        int k4 = (idx & 15) << 2;
        int d = __ldg(g_sdst + e0 + el);
        int s = __ldg(g_ssrc + e0 + el);
        float4 uu = *(const float4*)(g_u + d * 64 + k4);
        float4 vv = *(const float4*)(g_v + s * 64 + k4);
        float4 o;
        o.x = tf32f(mishf(uu.x + vv.x));
        o.y = tf32f(mishf(uu.y + vv.y));
        o.z = tf32f(mishf(uu.z + vv.z));
        o.w = tf32f(mishf(uu.w + vv.w));
        *(float4*)(sA + el * SA_ST + k4) = o;
    }
    __syncthreads();
    // MMA: warp w -> C[16][64] for edges [w*16, w*16+16)
    int lane = t & 31;
    int gid = lane >> 2, tig = lane & 3;
    int ebase = (t >> 5) * 16;
    float acc[8][4];
#pragma unroll
    for (int i = 0; i < 8; i++)
#pragma unroll
        for (int j = 0; j < 4; j++) acc[i][j] = 0.f;
#pragma unroll
    for (int kt = 0; kt < 8; kt++) {
        int k0 = kt * 8;
        unsigned a0 = __float_as_uint(sA[(ebase + gid)     * SA_ST + k0 + tig]);
        unsigned a1 = __float_as_uint(sA[(ebase + gid + 8) * SA_ST + k0 + tig]);
        unsigned a2 = __float_as_uint(sA[(ebase + gid)     * SA_ST + k0 + tig + 4]);
        unsigned a3 = __float_as_uint(sA[(ebase + gid + 8) * SA_ST + k0 + tig + 4]);
#pragma unroll
        for (int nt = 0; nt < 8; nt++) {
            unsigned b0 = __float_as_uint(sW[(k0 + tig)     * SA_ST + nt * 8 + gid]);
            unsigned b1 = __float_as_uint(sW[(k0 + tig + 4) * SA_ST + nt * 8 + gid]);
            mma_tf32(acc[nt], a0, a1, a2, a3, b0, b1);
        }
    }
    __syncwarp();
    // write C back over sA
#pragma unroll
    for (int nt = 0; nt < 8; nt++) {
        int col = nt * 8 + 2 * tig;
        *(float2*)(sA + (ebase + gid)     * SA_ST + col) = make_float2(acc[nt][0], acc[nt][1]);
        *(float2*)(sA + (ebase + gid + 8) * SA_ST + col) = make_float2(acc[nt][2], acc[nt][3]);
    }
    __syncthreads();
    // per-(segment, colgroup) reduction; interior segments -> plain store
    int S = *sNseg;
    for (int task = t; task < S * 16; task += 256) {
        int s = task >> 4, txx = task & 15;
        int st = sSstart[s], en = sSstart[s + 1];
        const float* aP = sA + st * SA_ST + txx * 4;
        float4 m = *(const float4*)aP;
        for (int i = 1; i < en - st; i++) {
            float4 h = *(const float4*)(aP + i * SA_ST);
            m.x = fmaxf(m.x, h.x);
            m.y = fmaxf(m.y, h.y);
            m.z = fmaxf(m.z, h.z);
            m.w = fmaxf(m.w, h.w);
        }
        int dd = __ldg(g_sdst + e0 + st);
        unsigned int* p = g_agg + dd * 64 + txx * 4;
        unsigned int ex = encf(m.x), ey = encf(m.y), ez = encf(m.z), ew = encf(m.w);
        if (s == 0 || s == S - 1) {
            atomicMax(p + 0, ex);
            atomicMax(p + 1, ey);
            atomicMax(p + 2, ez);
            atomicMax(p + 3, ew);
        } else {
            *(uint4*)p = make_uint4(ex, ey, ez, ew);
        }
    }
}

// edge kernel (dout=8): thread handles 8 consecutive sorted edges (fp32)
__global__ void k_edge8(const float* __restrict__ w2) {
    __shared__ float sW[64];
    int t = threadIdx.x;
    if (t < 64) sW[t] = w2[t];
    __syncthreads();
    int base = (blockIdx.x * blockDim.x + t) * 8;
    if (base >= Ee) return;
    int curd = -1;
    float m[8];
#pragma unroll
    for (int j = 0; j < 8; j++) {
        int e = base + j;
        int d = g_sdst[e], s = g_ssrc[e];
        float4 u0 = *(const float4*)(g_u + d * 8);
        float4 u1 = *(const float4*)(g_u + d * 8 + 4);
        float4 v0 = *(const float4*)(g_v + s * 8);
        float4 v1 = *(const float4*)(g_v + s * 8 + 4);
        float pre[8];
        pre[0] = mishf(u0.x + v0.x); pre[1] = mishf(u0.y + v0.y);
        pre[2] = mishf(u0.z + v0.z); pre[3] = mishf(u0.w + v0.w);
        pre[4] = mishf(u1.x + v1.x); pre[5] = mishf(u1.y + v1.y);
        pre[6] = mishf(u1.z + v1.z); pre[7] = mishf(u1.w + v1.w);
        float h[8];
#pragma unroll
        for (int c = 0; c < 8; c++) {
            float a = 0.f;
#pragma unroll
            for (int k = 0; k < 8; k++) a = fmaf(pre[k], sW[k * 8 + c], a);
            h[c] = a;
        }
        if (d != curd) {
            if (curd >= 0) {
#pragma unroll
                for (int c = 0; c < 8; c++)
                    atomicMax(g_agg + curd * 8 + c, encf(m[c]));
            }
            curd = d;
#pragma unroll
            for (int c = 0; c < 8; c++) m[c] = h[c];
        } else {
#pragma unroll
            for (int c = 0; c < 8; c++) m[c] = fmaxf(m[c], h[c]);
        }
    }
#pragma unroll
    for (int c = 0; c < 8; c++) atomicMax(g_agg + curd * 8 + c, encf(m[c]));
}

// decode agg -> g_x (+b2, empty->0), accumulate BN stats
__global__ void k_decode_stats64(const float* __restrict__ b2) {
    __shared__ float ss[64], sq[64];
    int t = threadIdx.x;
    if (t < 64) { ss[t] = 0.f; sq[t] = 0.f; }
    __syncthreads();
    int c = t & 63;
    float b2c = b2[c];
    float ls = 0.f, lq = 0.f;
    int stride = gridDim.x * blockDim.x;
    for (int i = blockIdx.x * blockDim.x + t; i < Nn * 64; i += stride) {
        unsigned int a = g_agg[i];
        float val = (a == 0u) ? 0.f : (decf(a) + b2c);
        g_x[i] = val;
        ls += val;
        lq += val * val;
    }
    atomicAdd(&ss[c], ls);
    atomicAdd(&sq[c], lq);
    __syncthreads();
    if (t < 64) {
        atomicAdd(&g_sum[t], ss[t]);
        atomicAdd(&g_sumsq[t], sq[t]);
    }
}

__global__ void k_decode_out(float* __restrict__ out, const float* __restrict__ b2) {
    int i = blockIdx.x * blockDim.x + threadIdx.x;
    if (i < Nn * 8) {
        unsigned int a = g_agg[i];
        out[i] = (a == 0u) ? 0.f : (decf(a) + b2[i & 7]);
    }
}

// ---------------- launch ----------------
extern "C" void kernel_launch(void* const* d_in, const int* in_sizes, int n_in,
                              void* d_out, int out_size) {
    const float* x  = (const float*)d_in[0];
    const int*   ei = (const int*)d_in[1];
    const int* src = ei;        // edge_index[0]
    const int* dst = ei + Ee;   // edge_index[1]

    const float* W1[4] = {(const float*)d_in[3], (const float*)d_in[9],
                          (const float*)d_in[15], (const float*)d_in[21]};
    const float* B1[4] = {(const float*)d_in[4], (const float*)d_in[10],
                          (const float*)d_in[16], (const float*)d_in[22]};
    const float* W2[4] = {(const float*)d_in[5], (const float*)d_in[11],
                          (const float*)d_in[17], (const float*)d_in[23]};
    const float* B2[4] = {(const float*)d_in[6], (const float*)d_in[12],
                          (const float*)d_in[18], (const float*)d_in[24]};
    const float* G[3]  = {(const float*)d_in[7], (const float*)d_in[13],
                          (const float*)d_in[19]};
    const float* BE[3] = {(const float*)d_in[8], (const float*)d_in[14],
                          (const float*)d_in[20]};

    cudaFuncSetAttribute(k_edge64, cudaFuncAttributeMaxDynamicSharedMemorySize,
                         EDGE_SMEM);
    cudaFuncSetAttribute(k_node_gemm64, cudaFuncAttributeMaxDynamicSharedMemorySize,
                         NG_SMEM);

    // sort edges by dst (counting sort; g_hist zero at entry by invariant)
    k_hist<<<(Ee + 255) / 256, 256>>>(dst);
    k_scan<<<1, 1024>>>();
    k_scatter<<<(Ee + 255) / 256, 256>>>(src, dst);

    // layers 0..2 (din=dout=64); BN of layer l-1 folded into node GEMM of l
    for (int l = 0; l < 3; l++) {
        k_node_gemm64<<<(Nn + 63) / 64, 256, NG_SMEM>>>(
            l == 0 ? x : nullptr, W1[l], B1[l],
            l == 0 ? nullptr : G[l - 1], l == 0 ? nullptr : BE[l - 1]);
        k_edge64<<<Ee / EB, 256, EDGE_SMEM>>>(W2[l]);
        k_decode_stats64<<<592, 256>>>(B2[l]);
    }

    // layer 3 (din=64, dout=8, BN of layer2 folded) -> d_out
    k_node_gemm8<<<(Nn + 15) / 16, 256>>>(W1[3], B1[3], G[2], BE[2]);
    k_edge8<<<(Ee / 8 + 255) / 256, 256>>>(W2[3]);
    k_decode_out<<<(Nn * 8 + 255) / 256, 256>>>((float*)d_out, B2[3]);
}

// round 11
// speedup vs baseline: 1.0340x; 1.0094x over previous
#include <cuda_runtime.h>
#include <math.h>

#define Nn 50000
#define Ee 800000

// ---------------- device scratch (static, no allocation) ----------------
__device__ float        g_x[Nn * 64];     // current node features (pre-BN)
__device__ float        g_u[Nn * 64];     // u = x@A + b1   (dst side)
__device__ float        g_v[Nn * 64];     // v = x@B        (src side)
__device__ __align__(16) unsigned int g_agg[Nn * 64];  // encoded seg-max acc
__device__ int          g_hist[Nn];
__device__ int          g_cur[Nn];        // segment END offsets after scatter
__device__ int          g_sdst[Ee];       // edges sorted by dst
__device__ int          g_ssrc[Ee];
__device__ float        g_sum[64];
__device__ float        g_sumsq[64];

// ---------------- helpers ----------------
__device__ __forceinline__ unsigned int encf(float f) {
    unsigned int b = __float_as_uint(f);
    return (b & 0x80000000u) ? ~b : (b | 0x80000000u);
}
__device__ __forceinline__ float decf(unsigned int u) {
    return (u & 0x80000000u) ? __uint_as_float(u & 0x7FFFFFFFu)
                             : __uint_as_float(~u);
}
// mish(x) = x * (t^2+2t)/(t^2+2t+2), t=e^x
__device__ __forceinline__ float mishf(float x) {
    float xc = fminf(x, 40.0f);
    float t = __expf(xc);
    float num = fmaf(t, t, 2.0f * t);
    float r = __fdividef(num, num + 2.0f);
    return x * r;
}
__device__ __forceinline__ unsigned int tf32_of(float f) {
    unsigned int r;
    asm("cvt.rna.tf32.f32 %0, %1;" : "=r"(r) : "f"(f));
    return r;
}
__device__ __forceinline__ float tf32f(float f) {
    return __uint_as_float(tf32_of(f));
}
__device__ __forceinline__ void mma_tf32(float c[4],
    unsigned a0, unsigned a1, unsigned a2, unsigned a3,
    unsigned b0, unsigned b1) {
    asm volatile(
        "mma.sync.aligned.m16n8k8.row.col.f32.tf32.tf32.f32 "
        "{%0,%1,%2,%3}, {%4,%5,%6,%7}, {%8,%9}, {%0,%1,%2,%3};"
        : "+f"(c[0]), "+f"(c[1]), "+f"(c[2]), "+f"(c[3])
        : "r"(a0), "r"(a1), "r"(a2), "r"(a3), "r"(b0), "r"(b1));
}

// ---------------- sorting (counting sort by dst, once per call) ----------------
__global__ void k_zero_hist() {
    int i = blockIdx.x * blockDim.x + threadIdx.x;
    if (i < Nn) g_hist[i] = 0;
}
__global__ void k_hist(const int* __restrict__ dst) {
    int e = blockIdx.x * blockDim.x + threadIdx.x;
    if (e < Ee) atomicAdd(&g_hist[dst[e]], 1);
}
__global__ void k_scan() {  // 1 block, 1024 threads
    __shared__ int ssum[1024];
    int t = threadIdx.x;
    const int CH = (Nn + 1023) / 1024;
    int base = t * CH;
    int s = 0;
    for (int i = 0; i < CH; i++) {
        int idx = base + i;
        if (idx < Nn) s += g_hist[idx];
    }
    ssum[t] = s;
    __syncthreads();
    for (int off = 1; off < 1024; off <<= 1) {
        int v = (t >= off) ? ssum[t - off] : 0;
        __syncthreads();
        ssum[t] += v;
        __syncthreads();
    }
    int prefix = (t == 0) ? 0 : ssum[t - 1];
    for (int i = 0; i < CH; i++) {
        int idx = base + i;
        if (idx < Nn) {
            int h = g_hist[idx];
            g_cur[idx] = prefix;
            prefix += h;
        }
    }
}
__global__ void k_scatter(const int* __restrict__ src, const int* __restrict__ dst) {
    int e = blockIdx.x * blockDim.x + threadIdx.x;
    if (e < Ee) {
        int d = dst[e];
        int p = atomicAdd(&g_cur[d], 1);
        g_sdst[p] = d;
        g_ssrc[p] = src[e];
    }
}
// after k_scatter: g_cur[n] == end offset of node n's edge segment (stable).

// ---------------- per-layer kernels ----------------
// node GEMM via TF32 mma: u = xn@(w1top - w1bot) + b1, v = xn@w1bot
// xn = BN(prev stats) folded input. Zeroes ONLY boundary-dst g_agg rows
// (the atomicMax targets of this layer's edge pass); interior rows are
// fully overwritten by plain stores in k_edge64, so they need no init.
#define EB    128
#define NTILE (Ee / EB)   // 6250
#define NG_XST 68
#define NG_WST 132
#define NG_OFF_W   (64 * NG_XST)
#define NG_OFF_SC  (NG_OFF_W + 64 * NG_WST)
#define NG_OFF_SH  (NG_OFF_SC + 64)
#define NG_OFF_B1  (NG_OFF_SH + 64)
#define NG_SMEM    ((NG_OFF_B1 + 64) * 4)
__global__ void __launch_bounds__(256) k_node_gemm64(
    const float* __restrict__ x_in,  // null -> read g_x
    const float* __restrict__ w1, const float* __restrict__ b1,
    const float* __restrict__ g, const float* __restrict__ be) {
    extern __shared__ __align__(16) float smem[];
    float* sX = smem;                 // [64][68] tf32
    float* sW = smem + NG_OFF_W;      // [64][132] tf32 (cols 0-63 A, 64-127 B)
    float* s_sc = smem + NG_OFF_SC;
    float* s_sh = smem + NG_OFF_SH;
    float* s_b1 = smem + NG_OFF_B1;
    const float* x = x_in ? x_in : g_x;
    int t = threadIdx.x;
    int n0 = blockIdx.x * 64;
    // zero boundary-dst rows: dsts of edges tile*EB and tile*EB+EB-1.
    // 2*NTILE rows x 16 uint4 each; ~1 store per thread across the grid.
    {
        uint4 z = make_uint4(0u, 0u, 0u, 0u);
        int stride = gridDim.x * blockDim.x;
        for (int task = blockIdx.x * blockDim.x + t; task < NTILE * 2 * 16;
             task += stride) {
            int b = task >> 4, q = task & 15;
            int tile = b >> 1;
            int e = tile * EB + ((b & 1) ? (EB - 1) : 0);
            int dd = __ldg(g_sdst + e);
            ((uint4*)(g_agg + dd * 64))[q] = z;
        }
    }
    if (t < 64) {
        float sc = 1.0f, sh = 0.0f;
        if (g) {
            float mu = g_sum[t] * (1.0f / Nn);
            float var = g_sumsq[t] * (1.0f / Nn) - mu * mu;
            sc = rsqrtf(var + 1e-5f) * g[t];
            sh = be[t] - mu * sc;
        }
        s_sc[t] = sc;
        s_sh[t] = sh;
        s_b1[t] = b1[t];
    }
    // stage w1 -> sW (tf32)
#pragma unroll
    for (int r = 0; r < 8; r++) {
        int idx = r * 256 + t;           // 2048 float4 tasks
        int k = idx >> 5, c4 = idx & 31;
        float4 val;
        int col;
        if (c4 < 16) {                   // A = w1top - w1bot, cols 0-63
            col = c4 * 4;
            float4 tp = *(const float4*)(w1 + k * 64 + col);
            float4 bt = *(const float4*)(w1 + (k + 64) * 64 + col);
            val.x = tp.x - bt.x; val.y = tp.y - bt.y;
            val.z = tp.z - bt.z; val.w = tp.w - bt.w;
        } else {                         // B = w1bot, cols 64-127
            col = (c4 - 16) * 4;
            val = *(const float4*)(w1 + (k + 64) * 64 + col);
            col += 64;
        }
        float* dp = sW + k * NG_WST + col;
        dp[0] = tf32f(val.x); dp[1] = tf32f(val.y);
        dp[2] = tf32f(val.z); dp[3] = tf32f(val.w);
    }
    __syncthreads();
    // stage x (BN fold, tf32) -> sX
#pragma unroll
    for (int r = 0; r < 4; r++) {
        int idx = r * 256 + t;
        int nl = idx >> 4, k4 = (idx & 15) << 2;
        int n = n0 + nl;
        float4 xv = (n < Nn) ? *(const float4*)(x + n * 64 + k4)
                             : make_float4(0.f, 0.f, 0.f, 0.f);
        float4 scv = *(const float4*)(s_sc + k4);
        float4 shv = *(const float4*)(s_sh + k4);
        float* dp = sX + nl * NG_XST + k4;
        dp[0] = tf32f(fmaf(xv.x, scv.x, shv.x));
        dp[1] = tf32f(fmaf(xv.y, scv.y, shv.y));
        dp[2] = tf32f(fmaf(xv.z, scv.z, shv.z));
        dp[3] = tf32f(fmaf(xv.w, scv.w, shv.w));
    }
    __syncthreads();
    // MMA: warp w handles rows (w&3)*16 and col half (w>>2)*64
    int lane = t & 31;
    int gid = lane >> 2, tig = lane & 3;
    int w = t >> 5;
    int r0 = (w & 3) * 16;
    int ch = (w >> 2) * 64;
    float acc[8][4];
#pragma unroll
    for (int i = 0; i < 8; i++)
#pragma unroll
        for (int j = 0; j < 4; j++) acc[i][j] = 0.f;
#pragma unroll
    for (int kt = 0; kt < 8; kt++) {
        int k0 = kt * 8;
        unsigned a0 = __float_as_uint(sX[(r0 + gid)     * NG_XST + k0 + tig]);
        unsigned a1 = __float_as_uint(sX[(r0 + gid + 8) * NG_XST + k0 + tig]);
        unsigned a2 = __float_as_uint(sX[(r0 + gid)     * NG_XST + k0 + tig + 4]);
        unsigned a3 = __float_as_uint(sX[(r0 + gid + 8) * NG_XST + k0 + tig + 4]);
#pragma unroll
        for (int nt = 0; nt < 8; nt++) {
            unsigned b0 = __float_as_uint(sW[(k0 + tig)     * NG_WST + ch + nt * 8 + gid]);
            unsigned b1v = __float_as_uint(sW[(k0 + tig + 4) * NG_WST + ch + nt * 8 + gid]);
            mma_tf32(acc[nt], a0, a1, a2, a3, b0, b1v);
        }
    }
    // store: cols<64 -> u (+b1), cols>=64 -> v
    int nA = n0 + r0 + gid;
    int nB = nA + 8;
#pragma unroll
    for (int nt = 0; nt < 8; nt++) {
        int col = ch + nt * 8 + 2 * tig;
        float add0 = 0.f, add1 = 0.f;
        float* basep;
        int cc;
        if (col < 64) {
            add0 = s_b1[col]; add1 = s_b1[col + 1];
            basep = g_u; cc = col;
        } else {
            basep = g_v; cc = col - 64;
        }
        if (nA < Nn)
            *(float2*)(basep + nA * 64 + cc) =
                make_float2(acc[nt][0] + add0, acc[nt][1] + add1);
        if (nB < Nn)
            *(float2*)(basep + nB * 64 + cc) =
                make_float2(acc[nt][2] + add0, acc[nt][3] + add1);
    }
}

// layer-3 node GEMM: dout=8, BN(layer2) folded; zeroes g_agg[0..Nn*8)
__global__ void __launch_bounds__(256) k_node_gemm8(
    const float* __restrict__ w1, const float* __restrict__ b1,
    const float* __restrict__ g, const float* __restrict__ be) {
    __shared__ float sW[64 * 16];
    __shared__ float s_sc[64], s_sh[64];
    int t = threadIdx.x;
    {
        int stride = gridDim.x * blockDim.x;
        for (int i = blockIdx.x * blockDim.x + t; i < Nn * 8; i += stride)
            g_agg[i] = 0u;
    }
    if (t < 64) {
        float mu = g_sum[t] * (1.0f / Nn);
        float var = g_sumsq[t] * (1.0f / Nn) - mu * mu;
        float sc = rsqrtf(var + 1e-5f) * g[t];
        s_sc[t] = sc;
        s_sh[t] = be[t] - mu * sc;
    }
#pragma unroll
    for (int r = 0; r < 4; r++) {
        int idx = r * 256 + t;
        int k = idx >> 4, cc = idx & 15;
        float wB = w1[(k + 64) * 8 + (cc & 7)];
        sW[idx] = (cc < 8) ? (w1[k * 8 + cc] - wB) : wB;
    }
    __syncthreads();
    int n = blockIdx.x * 16 + (t >> 4);
    int cc = t & 15;
    if (n >= Nn) return;
    const float* xr = g_x + n * 64;
    float acc = 0.f;
#pragma unroll 16
    for (int k = 0; k < 64; k++) {
        float xn = fmaf(__ldg(xr + k), s_sc[k], s_sh[k]);
        acc = fmaf(xn, sW[k * 16 + cc], acc);
    }
    if (cc < 8) g_u[n * 8 + cc] = acc + b1[cc];
    else        g_v[n * 8 + cc - 8] = acc;
}

// edge kernel (dout=64): 128-edge tile, TF32 mma, per-segment block reduction.
// Interior segments -> plain final store; boundary segments -> atomicMax
// (their g_agg rows were zeroed by k_node_gemm64).
#define SA_ST 68
#define OFF_W    (EB * SA_ST)
#define OFF_SST  (OFF_W + 64 * SA_ST)
#define OFF_NSEG (OFF_SST + 132)
#define EDGE_SMEM ((OFF_NSEG + 4) * 4)
__global__ void __launch_bounds__(256) k_edge64(const float* __restrict__ w2) {
    extern __shared__ __align__(16) float smem[];
    float* sA = smem;
    float* sW = smem + OFF_W;
    int* sSstart = (int*)(smem + OFF_SST);
    int* sNseg = (int*)(smem + OFF_NSEG);
    int t = threadIdx.x;
    int e0 = blockIdx.x * EB;

    // zero BN stat accumulators once per layer (before this layer's decode)
    if (blockIdx.x == 0 && t < 128) {
        if (t < 64) g_sum[t] = 0.f;
        else        g_sumsq[t - 64] = 0.f;
    }
    // warp 0: segment starts via flags + warp scan (dsts sorted)
    if (t < 32) {
        int base = t * 4;
        int d0 = __ldg(g_sdst + e0 + base);
        int d1 = __ldg(g_sdst + e0 + base + 1);
        int d2 = __ldg(g_sdst + e0 + base + 2);
        int d3 = __ldg(g_sdst + e0 + base + 3);
        int dm1 = (base > 0) ? __ldg(g_sdst + e0 + base - 1) : (d0 ^ 1);
        int h0 = (d0 != dm1), h1 = (d1 != d0), h2 = (d2 != d1), h3 = (d3 != d2);
        int lc0 = h0, lc1 = lc0 + h1, lc2 = lc1 + h2, lc3 = lc2 + h3;
        int c = lc3;
        int v = c;
#pragma unroll
        for (int o = 1; o < 32; o <<= 1) {
            int y = __shfl_up_sync(0xffffffffu, v, o);
            if (t >= o) v += y;
        }
        int off = v - c;
        if (h0) sSstart[off + lc0 - 1] = base;
        if (h1) sSstart[off + lc1 - 1] = base + 1;
        if (h2) sSstart[off + lc2 - 1] = base + 2;
        if (h3) sSstart[off + lc3 - 1] = base + 3;
        if (t == 31) {
            *sNseg = off + c;
            sSstart[off + c] = EB;
        }
    }
    // stage w2 (tf32), float4 loads
#pragma unroll
    for (int r = 0; r < 4; r++) {
        int idx = r * 256 + t;
        int k = idx >> 4, n4 = (idx & 15) << 2;
        float4 wv = *(const float4*)(w2 + k * 64 + n4);
        float* dp = sW + k * SA_ST + n4;
        dp[0] = tf32f(wv.x); dp[1] = tf32f(wv.y);
        dp[2] = tf32f(wv.z); dp[3] = tf32f(wv.w);
    }
    // gather + mish -> sA (tf32)
#pragma unroll
    for (int r = 0; r < 8; r++) {
        int idx = r * 256 + t;
        int el = idx >> 4;
        int k4 = (idx & 15) << 2;
        int d = __ldg(g_sdst + e0 + el);
        int s = __ldg(g_ssrc + e0 + el);
        float4 uu = *(const float4*)(g_u + d * 64 + k4);
        float4 vv = *(const float4*)(g_v + s * 64 + k4);
        float4 o;
        o.x = tf32f(mishf(uu.x + vv.x));
        o.y = tf32f(mishf(uu.y + vv.y));
        o.z = tf32f(mishf(uu.z + vv.z));
        o.w = tf32f(mishf(uu.w + vv.w));
        *(float4*)(sA + el * SA_ST + k4) = o;
    }
    __syncthreads();
    // MMA: warp w -> C[16][64] for edges [w*16, w*16+16)
    int lane = t & 31;
    int gid = lane >> 2, tig = lane & 3;
    int ebase = (t >> 5) * 16;
    float acc[8][4];
#pragma unroll
    for (int i = 0; i < 8; i++)
#pragma unroll
        for (int j = 0; j < 4; j++) acc[i][j] = 0.f;
#pragma unroll
    for (int kt = 0; kt < 8; kt++) {
        int k0 = kt * 8;
        unsigned a0 = __float_as_uint(sA[(ebase + gid)     * SA_ST + k0 + tig]);
        unsigned a1 = __float_as_uint(sA[(ebase + gid + 8) * SA_ST + k0 + tig]);
        unsigned a2 = __float_as_uint(sA[(ebase + gid)     * SA_ST + k0 + tig + 4]);
        unsigned a3 = __float_as_uint(sA[(ebase + gid + 8) * SA_ST + k0 + tig + 4]);
#pragma unroll
        for (int nt = 0; nt < 8; nt++) {
            unsigned b0 = __float_as_uint(sW[(k0 + tig)     * SA_ST + nt * 8 + gid]);
            unsigned b1 = __float_as_uint(sW[(k0 + tig + 4) * SA_ST + nt * 8 + gid]);
            mma_tf32(acc[nt], a0, a1, a2, a3, b0, b1);
        }
    }
    __syncwarp();
    // write C back over sA
#pragma unroll
    for (int nt = 0; nt < 8; nt++) {
        int col = nt * 8 + 2 * tig;
        *(float2*)(sA + (ebase + gid)     * SA_ST + col) = make_float2(acc[nt][0], acc[nt][1]);
        *(float2*)(sA + (ebase + gid + 8) * SA_ST + col) = make_float2(acc[nt][2], acc[nt][3]);
    }
    __syncthreads();
    // per-(segment, colgroup) reduction; interior segments -> plain store
    int S = *sNseg;
    for (int task = t; task < S * 16; task += 256) {
        int s = task >> 4, txx = task & 15;
        int st = sSstart[s], en = sSstart[s + 1];
        const float* aP = sA + st * SA_ST + txx * 4;
        float4 m = *(const float4*)aP;
        for (int i = 1; i < en - st; i++) {
            float4 h = *(const float4*)(aP + i * SA_ST);
            m.x = fmaxf(m.x, h.x);
            m.y = fmaxf(m.y, h.y);
            m.z = fmaxf(m.z, h.z);
            m.w = fmaxf(m.w, h.w);
        }
        int dd = __ldg(g_sdst + e0 + st);
        unsigned int* p = g_agg + dd * 64 + txx * 4;
        unsigned int ex = encf(m.x), ey = encf(m.y), ez = encf(m.z), ew = encf(m.w);
        if (s == 0 || s == S - 1) {
            atomicMax(p + 0, ex);
            atomicMax(p + 1, ey);
            atomicMax(p + 2, ez);
            atomicMax(p + 3, ew);
        } else {
            *(uint4*)p = make_uint4(ex, ey, ez, ew);
        }
    }
}

// edge kernel (dout=8): thread handles 8 consecutive sorted edges (fp32)
__global__ void k_edge8(const float* __restrict__ w2) {
    __shared__ float sW[64];
    int t = threadIdx.x;
    if (t < 64) sW[t] = w2[t];
    __syncthreads();
    int base = (blockIdx.x * blockDim.x + t) * 8;
    if (base >= Ee) return;
    int curd = -1;
    float m[8];
#pragma unroll
    for (int j = 0; j < 8; j++) {
        int e = base + j;
        int d = g_sdst[e], s = g_ssrc[e];
        float4 u0 = *(const float4*)(g_u + d * 8);
        float4 u1 = *(const float4*)(g_u + d * 8 + 4);
        float4 v0 = *(const float4*)(g_v + s * 8);
        float4 v1 = *(const float4*)(g_v + s * 8 + 4);
        float pre[8];
        pre[0] = mishf(u0.x + v0.x); pre[1] = mishf(u0.y + v0.y);
        pre[2] = mishf(u0.z + v0.z); pre[3] = mishf(u0.w + v0.w);
        pre[4] = mishf(u1.x + v1.x); pre[5] = mishf(u1.y + v1.y);
        pre[6] = mishf(u1.z + v1.z); pre[7] = mishf(u1.w + v1.w);
        float h[8];
#pragma unroll
        for (int c = 0; c < 8; c++) {
            float a = 0.f;
#pragma unroll
            for (int k = 0; k < 8; k++) a = fmaf(pre[k], sW[k * 8 + c], a);
            h[c] = a;
        }
        if (d != curd) {
            if (curd >= 0) {
#pragma unroll
                for (int c = 0; c < 8; c++)
                    atomicMax(g_agg + curd * 8 + c, encf(m[c]));
            }
            curd = d;
#pragma unroll
            for (int c = 0; c < 8; c++) m[c] = h[c];
        } else {
#pragma unroll
            for (int c = 0; c < 8; c++) m[c] = fmaxf(m[c], h[c]);
        }
    }
#pragma unroll
    for (int c = 0; c < 8; c++) atomicMax(g_agg + curd * 8 + c, encf(m[c]));
}

// decode agg -> g_x (+b2; empty nodes -> 0 via g_cur offsets), BN stats.
// Emptiness is exact: node n has edges iff g_cur[n] != (n ? g_cur[n-1] : 0).
__global__ void k_decode_stats64(const float* __restrict__ b2) {
    __shared__ float ss[64], sq[64];
    int t = threadIdx.x;
    if (t < 64) { ss[t] = 0.f; sq[t] = 0.f; }
    __syncthreads();
    int c = t & 63;
    float b2c = b2[c];
    float ls = 0.f, lq = 0.f;
    int stride = gridDim.x * blockDim.x;
    for (int i = blockIdx.x * blockDim.x + t; i < Nn * 64; i += stride) {
        int n = i >> 6;
        int en = __ldg(g_cur + n);
        int st = (n > 0) ? __ldg(g_cur + n - 1) : 0;
        float val = 0.f;
        if (en != st) val = decf(g_agg[i]) + b2c;
        g_x[i] = val;
        ls += val;
        lq += val * val;
    }
    atomicAdd(&ss[c], ls);
    atomicAdd(&sq[c], lq);
    __syncthreads();
    if (t < 64) {
        atomicAdd(&g_sum[t], ss[t]);
        atomicAdd(&g_sumsq[t], sq[t]);
    }
}

__global__ void k_decode_out(float* __restrict__ out, const float* __restrict__ b2) {
    int i = blockIdx.x * blockDim.x + threadIdx.x;
    if (i < Nn * 8) {
        unsigned int a = g_agg[i];
        out[i] = (a == 0u) ? 0.f : (decf(a) + b2[i & 7]);
    }
}

// ---------------- launch ----------------
extern "C" void kernel_launch(void* const* d_in, const int* in_sizes, int n_in,
                              void* d_out, int out_size) {
    const float* x  = (const float*)d_in[0];
    const int*   ei = (const int*)d_in[1];
    const int* src = ei;        // edge_index[0]
    const int* dst = ei + Ee;   // edge_index[1]

    const float* W1[4] = {(const float*)d_in[3], (const float*)d_in[9],
                          (const float*)d_in[15], (const float*)d_in[21]};
    const float* B1[4] = {(const float*)d_in[4], (const float*)d_in[10],
                          (const float*)d_in[16], (const float*)d_in[22]};
    const float* W2[4] = {(const float*)d_in[5], (const float*)d_in[11],
                          (const float*)d_in[17], (const float*)d_in[23]};
    const float* B2[4] = {(const float*)d_in[6], (const float*)d_in[12],
                          (const float*)d_in[18], (const float*)d_in[24]};
    const float* G[3]  = {(const float*)d_in[7], (const float*)d_in[13],
                          (const float*)d_in[19]};
    const float* BE[3] = {(const float*)d_in[8], (const float*)d_in[14],
                          (const float*)d_in[20]};

    cudaFuncSetAttribute(k_edge64, cudaFuncAttributeMaxDynamicSharedMemorySize,
                         EDGE_SMEM);
    cudaFuncSetAttribute(k_node_gemm64, cudaFuncAttributeMaxDynamicSharedMemorySize,
                         NG_SMEM);

    // sort edges by dst (counting sort)
    k_zero_hist<<<(Nn + 255) / 256, 256>>>();
    k_hist<<<(Ee + 255) / 256, 256>>>(dst);
    k_scan<<<1, 1024>>>();
    k_scatter<<<(Ee + 255) / 256, 256>>>(src, dst);

    // layers 0..2 (din=dout=64); BN of layer l-1 folded into node GEMM of l
    for (int l = 0; l < 3; l++) {
        k_node_gemm64<<<(Nn + 63) / 64, 256, NG_SMEM>>>(
            l == 0 ? x : nullptr, W1[l], B1[l],
            l == 0 ? nullptr : G[l - 1], l == 0 ? nullptr : BE[l - 1]);
        k_edge64<<<Ee / EB, 256, EDGE_SMEM>>>(W2[l]);
        k_decode_stats64<<<592, 256>>>(B2[l]);
    }

    // layer 3 (din=64, dout=8, BN of layer2 folded) -> d_out
    k_node_gemm8<<<(Nn + 15) / 16, 256>>>(W1[3], B1[3], G[2], BE[2]);
    k_edge8<<<(Ee / 8 + 255) / 256, 256>>>(W2[3]);
    k_decode_out<<<(Nn * 8 + 255) / 256, 256>>>((float*)d_out, B2[3]);
}

// round 12
// speedup vs baseline: 1.0443x; 1.0100x over previous
#include <cuda_runtime.h>
#include <math.h>

#define Nn 50000
#define Ee 800000

// ---------------- device scratch (static, no allocation) ----------------
__device__ float        g_x[Nn * 64];     // current node features (pre-BN)
__device__ float        g_u[Nn * 64];     // u = x@A + b1   (dst side)
__device__ float        g_v[Nn * 64];     // v = x@B        (src side)
__device__ __align__(16) unsigned int g_agg[Nn * 64];  // encoded seg-max acc
__device__ int          g_hist[Nn];
__device__ int          g_cur[Nn];
__device__ int          g_sdst[Ee];       // edges sorted by dst
__device__ int          g_ssrc[Ee];
__device__ float        g_sum[64];
__device__ float        g_sumsq[64];

// ---------------- helpers ----------------
__device__ __forceinline__ unsigned int encf(float f) {
    unsigned int b = __float_as_uint(f);
    return (b & 0x80000000u) ? ~b : (b | 0x80000000u);
}
__device__ __forceinline__ float decf(unsigned int u) {
    return (u & 0x80000000u) ? __uint_as_float(u & 0x7FFFFFFFu)
                             : __uint_as_float(~u);
}
// mish(x) = x * (t^2+2t)/(t^2+2t+2), t=e^x
__device__ __forceinline__ float mishf(float x) {
    float xc = fminf(x, 40.0f);
    float t = __expf(xc);
    float num = fmaf(t, t, 2.0f * t);
    float r = __fdividef(num, num + 2.0f);
    return x * r;
}
__device__ __forceinline__ unsigned int tf32_of(float f) {
    unsigned int r;
    asm("cvt.rna.tf32.f32 %0, %1;" : "=r"(r) : "f"(f));
    return r;
}
__device__ __forceinline__ float tf32f(float f) {
    return __uint_as_float(tf32_of(f));
}
__device__ __forceinline__ void mma_tf32(float c[4],
    unsigned a0, unsigned a1, unsigned a2, unsigned a3,
    unsigned b0, unsigned b1) {
    asm volatile(
        "mma.sync.aligned.m16n8k8.row.col.f32.tf32.tf32.f32 "
        "{%0,%1,%2,%3}, {%4,%5,%6,%7}, {%8,%9}, {%0,%1,%2,%3};"
        : "+f"(c[0]), "+f"(c[1]), "+f"(c[2]), "+f"(c[3])
        : "r"(a0), "r"(a1), "r"(a2), "r"(a3), "r"(b0), "r"(b1));
}

// ---------------- sorting (counting sort by dst, once per call) ----------------
__global__ void k_zero_hist() {
    int i = blockIdx.x * blockDim.x + threadIdx.x;
    if (i < Nn) g_hist[i] = 0;
}
__global__ void k_hist(const int* __restrict__ dst) {
    int e = blockIdx.x * blockDim.x + threadIdx.x;
    if (e < Ee) atomicAdd(&g_hist[dst[e]], 1);
}
__global__ void k_scan() {  // 1 block, 1024 threads
    __shared__ int ssum[1024];
    int t = threadIdx.x;
    const int CH = (Nn + 1023) / 1024;
    int base = t * CH;
    int s = 0;
    for (int i = 0; i < CH; i++) {
        int idx = base + i;
        if (idx < Nn) s += g_hist[idx];
    }
    ssum[t] = s;
    __syncthreads();
    for (int off = 1; off < 1024; off <<= 1) {
        int v = (t >= off) ? ssum[t - off] : 0;
        __syncthreads();
        ssum[t] += v;
        __syncthreads();
    }
    int prefix = (t == 0) ? 0 : ssum[t - 1];
    for (int i = 0; i < CH; i++) {
        int idx = base + i;
        if (idx < Nn) {
            int h = g_hist[idx];
            g_cur[idx] = prefix;
            prefix += h;
        }
    }
}
__global__ void k_scatter(const int* __restrict__ src, const int* __restrict__ dst) {
    int e = blockIdx.x * blockDim.x + threadIdx.x;
    if (e < Ee) {
        int d = dst[e];
        int p = atomicAdd(&g_cur[d], 1);
        g_sdst[p] = d;
        g_ssrc[p] = src[e];
    }
}

// ---------------- per-layer kernels ----------------
// node GEMM via TF32 mma: u = xn@(w1top - w1bot) + b1, v = xn@w1bot
// xn = BN(prev stats) folded input. Also zeroes g_agg for this layer.
#define NG_XST 68
#define NG_WST 132
#define NG_OFF_W   (64 * NG_XST)
#define NG_OFF_SC  (NG_OFF_W + 64 * NG_WST)
#define NG_OFF_SH  (NG_OFF_SC + 64)
#define NG_OFF_B1  (NG_OFF_SH + 64)
#define NG_SMEM    ((NG_OFF_B1 + 64) * 4)
__global__ void __launch_bounds__(256) k_node_gemm64(
    const float* __restrict__ x_in,  // null -> read g_x
    const float* __restrict__ w1, const float* __restrict__ b1,
    const float* __restrict__ g, const float* __restrict__ be) {
    extern __shared__ __align__(16) float smem[];
    float* sX = smem;                 // [64][68] tf32
    float* sW = smem + NG_OFF_W;      // [64][132] tf32 (cols 0-63 A, 64-127 B)
    float* s_sc = smem + NG_OFF_SC;
    float* s_sh = smem + NG_OFF_SH;
    float* s_b1 = smem + NG_OFF_B1;
    const float* x = x_in ? x_in : g_x;
    int t = threadIdx.x;
    int n0 = blockIdx.x * 64;
    // fused: zero the segment-max accumulator
    {
        int stride = gridDim.x * blockDim.x;
        for (int i = blockIdx.x * blockDim.x + t; i < Nn * 64; i += stride)
            g_agg[i] = 0u;
    }
    if (t < 64) {
        float sc = 1.0f, sh = 0.0f;
        if (g) {
            float mu = g_sum[t] * (1.0f / Nn);
            float var = g_sumsq[t] * (1.0f / Nn) - mu * mu;
            sc = rsqrtf(var + 1e-5f) * g[t];
            sh = be[t] - mu * sc;
        }
        s_sc[t] = sc;
        s_sh[t] = sh;
        s_b1[t] = b1[t];
    }
    // stage w1 -> sW (tf32)
#pragma unroll
    for (int r = 0; r < 8; r++) {
        int idx = r * 256 + t;           // 2048 float4 tasks
        int k = idx >> 5, c4 = idx & 31;
        float4 val;
        int col;
        if (c4 < 16) {                   // A = w1top - w1bot, cols 0-63
            col = c4 * 4;
            float4 tp = *(const float4*)(w1 + k * 64 + col);
            float4 bt = *(const float4*)(w1 + (k + 64) * 64 + col);
            val.x = tp.x - bt.x; val.y = tp.y - bt.y;
            val.z = tp.z - bt.z; val.w = tp.w - bt.w;
        } else {                         // B = w1bot, cols 64-127
            col = (c4 - 16) * 4;
            val = *(const float4*)(w1 + (k + 64) * 64 + col);
            col += 64;
        }
        float* dp = sW + k * NG_WST + col;
        dp[0] = tf32f(val.x); dp[1] = tf32f(val.y);
        dp[2] = tf32f(val.z); dp[3] = tf32f(val.w);
    }
    __syncthreads();
    // stage x (BN fold, tf32) -> sX
#pragma unroll
    for (int r = 0; r < 4; r++) {
        int idx = r * 256 + t;
        int nl = idx >> 4, k4 = (idx & 15) << 2;
        int n = n0 + nl;
        float4 xv = (n < Nn) ? *(const float4*)(x + n * 64 + k4)
                             : make_float4(0.f, 0.f, 0.f, 0.f);
        float4 scv = *(const float4*)(s_sc + k4);
        float4 shv = *(const float4*)(s_sh + k4);
        float* dp = sX + nl * NG_XST + k4;
        dp[0] = tf32f(fmaf(xv.x, scv.x, shv.x));
        dp[1] = tf32f(fmaf(xv.y, scv.y, shv.y));
        dp[2] = tf32f(fmaf(xv.z, scv.z, shv.z));
        dp[3] = tf32f(fmaf(xv.w, scv.w, shv.w));
    }
    __syncthreads();
    // MMA: warp w handles rows (w&3)*16 and col half (w>>2)*64
    int lane = t & 31;
    int gid = lane >> 2, tig = lane & 3;
    int w = t >> 5;
    int r0 = (w & 3) * 16;
    int ch = (w >> 2) * 64;
    float acc[8][4];
#pragma unroll
    for (int i = 0; i < 8; i++)
#pragma unroll
        for (int j = 0; j < 4; j++) acc[i][j] = 0.f;
#pragma unroll
    for (int kt = 0; kt < 8; kt++) {
        int k0 = kt * 8;
        unsigned a0 = __float_as_uint(sX[(r0 + gid)     * NG_XST + k0 + tig]);
        unsigned a1 = __float_as_uint(sX[(r0 + gid + 8) * NG_XST + k0 + tig]);
        unsigned a2 = __float_as_uint(sX[(r0 + gid)     * NG_XST + k0 + tig + 4]);
        unsigned a3 = __float_as_uint(sX[(r0 + gid + 8) * NG_XST + k0 + tig + 4]);
#pragma unroll
        for (int nt = 0; nt < 8; nt++) {
            unsigned b0 = __float_as_uint(sW[(k0 + tig)     * NG_WST + ch + nt * 8 + gid]);
            unsigned b1v = __float_as_uint(sW[(k0 + tig + 4) * NG_WST + ch + nt * 8 + gid]);
            mma_tf32(acc[nt], a0, a1, a2, a3, b0, b1v);
        }
    }
    // store: cols<64 -> u (+b1), cols>=64 -> v
    int nA = n0 + r0 + gid;
    int nB = nA + 8;
#pragma unroll
    for (int nt = 0; nt < 8; nt++) {
        int col = ch + nt * 8 + 2 * tig;
        float add0 = 0.f, add1 = 0.f;
        float* basep;
        int cc;
        if (col < 64) {
            add0 = s_b1[col]; add1 = s_b1[col + 1];
            basep = g_u; cc = col;
        } else {
            basep = g_v; cc = col - 64;
        }
        if (nA < Nn)
            *(float2*)(basep + nA * 64 + cc) =
                make_float2(acc[nt][0] + add0, acc[nt][1] + add1);
        if (nB < Nn)
            *(float2*)(basep + nB * 64 + cc) =
                make_float2(acc[nt][2] + add0, acc[nt][3] + add1);
    }
}

// layer-3 node GEMM: dout=8, BN(layer2) folded; zeroes g_agg[0..Nn*8)
__global__ void __launch_bounds__(256) k_node_gemm8(
    const float* __restrict__ w1, const float* __restrict__ b1,
    const float* __restrict__ g, const float* __restrict__ be) {
    __shared__ float sW[64 * 16];
    __shared__ float s_sc[64], s_sh[64];
    int t = threadIdx.x;
    {
        int stride = gridDim.x * blockDim.x;
        for (int i = blockIdx.x * blockDim.x + t; i < Nn * 8; i += stride)
            g_agg[i] = 0u;
    }
    if (t < 64) {
        float mu = g_sum[t] * (1.0f / Nn);
        float var = g_sumsq[t] * (1.0f / Nn) - mu * mu;
        float sc = rsqrtf(var + 1e-5f) * g[t];
        s_sc[t] = sc;
        s_sh[t] = be[t] - mu * sc;
    }
#pragma unroll
    for (int r = 0; r < 4; r++) {
        int idx = r * 256 + t;
        int k = idx >> 4, cc = idx & 15;
        float wB = w1[(k + 64) * 8 + (cc & 7)];
        sW[idx] = (cc < 8) ? (w1[k * 8 + cc] - wB) : wB;
    }
    __syncthreads();
    int n = blockIdx.x * 16 + (t >> 4);
    int cc = t & 15;
    if (n >= Nn) return;
    const float* xr = g_x + n * 64;
    float acc = 0.f;
#pragma unroll 16
    for (int k = 0; k < 64; k++) {
        float xn = fmaf(__ldg(xr + k), s_sc[k], s_sh[k]);
        acc = fmaf(xn, sW[k * 16 + cc], acc);
    }
    if (cc < 8) g_u[n * 8 + cc] = acc + b1[cc];
    else        g_v[n * 8 + cc - 8] = acc;
}

// edge kernel (dout=64): 128-edge tile, cp.async v-gather pipeline,
// TF32 mma, per-segment block reduction (interior -> plain store).
#define EB    128
#define SA_ST 68
#define OFF_W    (EB * SA_ST)
#define OFF_SST  (OFF_W + 64 * SA_ST)
#define OFF_NSEG (OFF_SST + 132)
#define EDGE_SMEM ((OFF_NSEG + 4) * 4)
__global__ void __launch_bounds__(256) k_edge64(const float* __restrict__ w2) {
    extern __shared__ __align__(16) float smem[];
    float* sA = smem;
    float* sW = smem + OFF_W;
    int* sSstart = (int*)(smem + OFF_SST);
    int* sNseg = (int*)(smem + OFF_NSEG);
    int t = threadIdx.x;
    int e0 = blockIdx.x * EB;

    // zero BN stat accumulators once per layer (before this layer's decode)
    if (blockIdx.x == 0 && t < 128) {
        if (t < 64) g_sum[t] = 0.f;
        else        g_sumsq[t - 64] = 0.f;
    }
    // phase 1: fire async copies of raw v[src] rows into sA (random L2 gather)
#pragma unroll
    for (int r = 0; r < 8; r++) {
        int idx = r * 256 + t;
        int el = idx >> 4;
        int k4 = (idx & 15) << 2;
        int s = __ldg(g_ssrc + e0 + el);
        unsigned dstp = (unsigned)__cvta_generic_to_shared(sA + el * SA_ST + k4);
        const float* srcp = g_v + s * 64 + k4;
        asm volatile("cp.async.cg.shared.global [%0], [%1], 16;"
                     :: "r"(dstp), "l"(srcp));
    }
    asm volatile("cp.async.commit_group;" ::: "memory");
    // phase 2 (overlapped with in-flight copies): stage w2 (tf32)
#pragma unroll
    for (int r = 0; r < 4; r++) {
        int idx = r * 256 + t;
        int k = idx >> 4, n4 = (idx & 15) << 2;
        float4 wv = *(const float4*)(w2 + k * 64 + n4);
        float* dp = sW + k * SA_ST + n4;
        dp[0] = tf32f(wv.x); dp[1] = tf32f(wv.y);
        dp[2] = tf32f(wv.z); dp[3] = tf32f(wv.w);
    }
    // phase 3 (still overlapped): warp 0 computes segment starts
    if (t < 32) {
        int base = t * 4;
        int d0 = __ldg(g_sdst + e0 + base);
        int d1 = __ldg(g_sdst + e0 + base + 1);
        int d2 = __ldg(g_sdst + e0 + base + 2);
        int d3 = __ldg(g_sdst + e0 + base + 3);
        int dm1 = (base > 0) ? __ldg(g_sdst + e0 + base - 1) : (d0 ^ 1);
        int h0 = (d0 != dm1), h1 = (d1 != d0), h2 = (d2 != d1), h3 = (d3 != d2);
        int lc0 = h0, lc1 = lc0 + h1, lc2 = lc1 + h2, lc3 = lc2 + h3;
        int c = lc3;
        int v = c;
#pragma unroll
        for (int o = 1; o < 32; o <<= 1) {
            int y = __shfl_up_sync(0xffffffffu, v, o);
            if (t >= o) v += y;
        }
        int off = v - c;
        if (h0) sSstart[off + lc0 - 1] = base;
        if (h1) sSstart[off + lc1 - 1] = base + 1;
        if (h2) sSstart[off + lc2 - 1] = base + 2;
        if (h3) sSstart[off + lc3 - 1] = base + 3;
        if (t == 31) {
            *sNseg = off + c;
            sSstart[off + c] = EB;
        }
    }
    asm volatile("cp.async.wait_group 0;" ::: "memory");
    __syncthreads();
    // phase 4: in-place mish: v from smem, u from global (L1-hot: dst-sorted)
#pragma unroll
    for (int r = 0; r < 8; r++) {
        int idx = r * 256 + t;
        int el = idx >> 4;
        int k4 = (idx & 15) << 2;
        int d = __ldg(g_sdst + e0 + el);
        float4 uu = *(const float4*)(g_u + d * 64 + k4);
        float4 vv = *(const float4*)(sA + el * SA_ST + k4);
        float4 o;
        o.x = tf32f(mishf(uu.x + vv.x));
        o.y = tf32f(mishf(uu.y + vv.y));
        o.z = tf32f(mishf(uu.z + vv.z));
        o.w = tf32f(mishf(uu.w + vv.w));
        *(float4*)(sA + el * SA_ST + k4) = o;
    }
    __syncthreads();
    // MMA: warp w -> C[16][64] for edges [w*16, w*16+16)
    int lane = t & 31;
    int gid = lane >> 2, tig = lane & 3;
    int ebase = (t >> 5) * 16;
    float acc[8][4];
#pragma unroll
    for (int i = 0; i < 8; i++)
#pragma unroll
        for (int j = 0; j < 4; j++) acc[i][j] = 0.f;
#pragma unroll
    for (int kt = 0; kt < 8; kt++) {
        int k0 = kt * 8;
        unsigned a0 = __float_as_uint(sA[(ebase + gid)     * SA_ST + k0 + tig]);
        unsigned a1 = __float_as_uint(sA[(ebase + gid + 8) * SA_ST + k0 + tig]);
        unsigned a2 = __float_as_uint(sA[(ebase + gid)     * SA_ST + k0 + tig + 4]);
        unsigned a3 = __float_as_uint(sA[(ebase + gid + 8) * SA_ST + k0 + tig + 4]);
#pragma unroll
        for (int nt = 0; nt < 8; nt++) {
            unsigned b0 = __float_as_uint(sW[(k0 + tig)     * SA_ST + nt * 8 + gid]);
            unsigned b1 = __float_as_uint(sW[(k0 + tig + 4) * SA_ST + nt * 8 + gid]);
            mma_tf32(acc[nt], a0, a1, a2, a3, b0, b1);
        }
    }
    __syncwarp();
    // write C back over sA
#pragma unroll
    for (int nt = 0; nt < 8; nt++) {
        int col = nt * 8 + 2 * tig;
        *(float2*)(sA + (ebase + gid)     * SA_ST + col) = make_float2(acc[nt][0], acc[nt][1]);
        *(float2*)(sA + (ebase + gid + 8) * SA_ST + col) = make_float2(acc[nt][2], acc[nt][3]);
    }
    __syncthreads();
    // per-(segment, colgroup) reduction; interior segments -> plain store
    int S = *sNseg;
    for (int task = t; task < S * 16; task += 256) {
        int s = task >> 4, txx = task & 15;
        int st = sSstart[s], en = sSstart[s + 1];
        const float* aP = sA + st * SA_ST + txx * 4;
        float4 m = *(const float4*)aP;
        for (int i = 1; i < en - st; i++) {
            float4 h = *(const float4*)(aP + i * SA_ST);
            m.x = fmaxf(m.x, h.x);
            m.y = fmaxf(m.y, h.y);
            m.z = fmaxf(m.z, h.z);
            m.w = fmaxf(m.w, h.w);
        }
        int dd = __ldg(g_sdst + e0 + st);
        unsigned int* p = g_agg + dd * 64 + txx * 4;
        unsigned int ex = encf(m.x), ey = encf(m.y), ez = encf(m.z), ew = encf(m.w);
        if (s == 0 || s == S - 1) {
            atomicMax(p + 0, ex);
            atomicMax(p + 1, ey);
            atomicMax(p + 2, ez);
            atomicMax(p + 3, ew);
        } else {
            *(uint4*)p = make_uint4(ex, ey, ez, ew);
        }
    }
}

// edge kernel (dout=8): thread handles 8 consecutive sorted edges (fp32)
__global__ void k_edge8(const float* __restrict__ w2) {
    __shared__ float sW[64];
    int t = threadIdx.x;
    if (t < 64) sW[t] = w2[t];
    __syncthreads();
    int base = (blockIdx.x * blockDim.x + t) * 8;
    if (base >= Ee) return;
    int curd = -1;
    float m[8];
#pragma unroll
    for (int j = 0; j < 8; j++) {
        int e = base + j;
        int d = g_sdst[e], s = g_ssrc[e];
        float4 u0 = *(const float4*)(g_u + d * 8);
        float4 u1 = *(const float4*)(g_u + d * 8 + 4);
        float4 v0 = *(const float4*)(g_v + s * 8);
        float4 v1 = *(const float4*)(g_v + s * 8 + 4);
        float pre[8];
        pre[0] = mishf(u0.x + v0.x); pre[1] = mishf(u0.y + v0.y);
        pre[2] = mishf(u0.z + v0.z); pre[3] = mishf(u0.w + v0.w);
        pre[4] = mishf(u1.x + v1.x); pre[5] = mishf(u1.y + v1.y);
        pre[6] = mishf(u1.z + v1.z); pre[7] = mishf(u1.w + v1.w);
        float h[8];
#pragma unroll
        for (int c = 0; c < 8; c++) {
            float a = 0.f;
#pragma unroll
            for (int k = 0; k < 8; k++) a = fmaf(pre[k], sW[k * 8 + c], a);
            h[c] = a;
        }
        if (d != curd) {
            if (curd >= 0) {
#pragma unroll
                for (int c = 0; c < 8; c++)
                    atomicMax(g_agg + curd * 8 + c, encf(m[c]));
            }
            curd = d;
#pragma unroll
            for (int c = 0; c < 8; c++) m[c] = h[c];
        } else {
#pragma unroll
            for (int c = 0; c < 8; c++) m[c] = fmaxf(m[c], h[c]);
        }
    }
#pragma unroll
    for (int c = 0; c < 8; c++) atomicMax(g_agg + curd * 8 + c, encf(m[c]));
}

// decode agg -> g_x (+b2, empty->0), accumulate BN stats
__global__ void k_decode_stats64(const float* __restrict__ b2) {
    __shared__ float ss[64], sq[64];
    int t = threadIdx.x;
    if (t < 64) { ss[t] = 0.f; sq[t] = 0.f; }
    __syncthreads();
    int c = t & 63;
    float b2c = b2[c];
    float ls = 0.f, lq = 0.f;
    int stride = gridDim.x * blockDim.x;
    for (int i = blockIdx.x * blockDim.x + t; i < Nn * 64; i += stride) {
        unsigned int a = g_agg[i];
        float val = (a == 0u) ? 0.f : (decf(a) + b2c);
        g_x[i] = val;
        ls += val;
        lq += val * val;
    }
    atomicAdd(&ss[c], ls);
    atomicAdd(&sq[c], lq);
    __syncthreads();
    if (t < 64) {
        atomicAdd(&g_sum[t], ss[t]);
        atomicAdd(&g_sumsq[t], sq[t]);
    }
}

__global__ void k_decode_out(float* __restrict__ out, const float* __restrict__ b2) {
    int i = blockIdx.x * blockDim.x + threadIdx.x;
    if (i < Nn * 8) {
        unsigned int a = g_agg[i];
        out[i] = (a == 0u) ? 0.f : (decf(a) + b2[i & 7]);
    }
}

// ---------------- launch ----------------
extern "C" void kernel_launch(void* const* d_in, const int* in_sizes, int n_in,
                              void* d_out, int out_size) {
    const float* x  = (const float*)d_in[0];
    const int*   ei = (const int*)d_in[1];
    const int* src = ei;        // edge_index[0]
    const int* dst = ei + Ee;   // edge_index[1]

    const float* W1[4] = {(const float*)d_in[3], (const float*)d_in[9],
                          (const float*)d_in[15], (const float*)d_in[21]};
    const float* B1[4] = {(const float*)d_in[4], (const float*)d_in[10],
                          (const float*)d_in[16], (const float*)d_in[22]};
    const float* W2[4] = {(const float*)d_in[5], (const float*)d_in[11],
                          (const float*)d_in[17], (const float*)d_in[23]};
    const float* B2[4] = {(const float*)d_in[6], (const float*)d_in[12],
                          (const float*)d_in[18], (const float*)d_in[24]};
    const float* G[3]  = {(const float*)d_in[7], (const float*)d_in[13],
                          (const float*)d_in[19]};
    const float* BE[3] = {(const float*)d_in[8], (const float*)d_in[14],
                          (const float*)d_in[20]};

    cudaFuncSetAttribute(k_edge64, cudaFuncAttributeMaxDynamicSharedMemorySize,
                         EDGE_SMEM);
    cudaFuncSetAttribute(k_node_gemm64, cudaFuncAttributeMaxDynamicSharedMemorySize,
                         NG_SMEM);

    // sort edges by dst (counting sort)
    k_zero_hist<<<(Nn + 255) / 256, 256>>>();
    k_hist<<<(Ee + 255) / 256, 256>>>(dst);
    k_scan<<<1, 1024>>>();
    k_scatter<<<(Ee + 255) / 256, 256>>>(src, dst);

    // layers 0..2 (din=dout=64); BN of layer l-1 folded into node GEMM of l
    for (int l = 0; l < 3; l++) {
        k_node_gemm64<<<(Nn + 63) / 64, 256, NG_SMEM>>>(
            l == 0 ? x : nullptr, W1[l], B1[l],
            l == 0 ? nullptr : G[l - 1], l == 0 ? nullptr : BE[l - 1]);
        k_edge64<<<Ee / EB, 256, EDGE_SMEM>>>(W2[l]);
        k_decode_stats64<<<592, 256>>>(B2[l]);
    }

    // layer 3 (din=64, dout=8, BN of layer2 folded) -> d_out
    k_node_gemm8<<<(Nn + 15) / 16, 256>>>(W1[3], B1[3], G[2], BE[2]);
    k_edge8<<<(Ee / 8 + 255) / 256, 256>>>(W2[3]);
    k_decode_out<<<(Nn * 8 + 255) / 256, 256>>>((float*)d_out, B2[3]);
}

// round 13
// speedup vs baseline: 1.0716x; 1.0261x over previous
#include <cuda_runtime.h>
#include <math.h>

#define Nn 50000
#define Ee 800000

// ---------------- device scratch (static, no allocation) ----------------
__device__ float        g_x[Nn * 64];     // current node features (pre-BN)
__device__ float        g_u[Nn * 64];     // u = x@A + b1   (dst side)
__device__ float        g_v[Nn * 64];     // v = x@B        (src side)
__device__ __align__(16) unsigned int g_agg[Nn * 64];  // encoded seg-max acc
__device__ int          g_hist[Nn];
__device__ int          g_cur[Nn];
__device__ int          g_sdst[Ee];       // edges sorted by dst
__device__ int          g_ssrc[Ee];
__device__ float        g_sum[64];
__device__ float        g_sumsq[64];

// ---------------- helpers ----------------
__device__ __forceinline__ unsigned int encf(float f) {
    unsigned int b = __float_as_uint(f);
    return (b & 0x80000000u) ? ~b : (b | 0x80000000u);
}
__device__ __forceinline__ float decf(unsigned int u) {
    return (u & 0x80000000u) ? __uint_as_float(u & 0x7FFFFFFFu)
                             : __uint_as_float(~u);
}
// mish(x) = x * (t^2+2t)/(t^2+2t+2), t=e^x
__device__ __forceinline__ float mishf(float x) {
    float xc = fminf(x, 40.0f);
    float t = __expf(xc);
    float num = fmaf(t, t, 2.0f * t);
    float r = __fdividef(num, num + 2.0f);
    return x * r;
}
__device__ __forceinline__ unsigned int tf32_of(float f) {
    unsigned int r;
    asm("cvt.rna.tf32.f32 %0, %1;" : "=r"(r) : "f"(f));
    return r;
}
__device__ __forceinline__ float tf32f(float f) {
    return __uint_as_float(tf32_of(f));
}
__device__ __forceinline__ void mma_tf32(float c[4],
    unsigned a0, unsigned a1, unsigned a2, unsigned a3,
    unsigned b0, unsigned b1) {
    asm volatile(
        "mma.sync.aligned.m16n8k8.row.col.f32.tf32.tf32.f32 "
        "{%0,%1,%2,%3}, {%4,%5,%6,%7}, {%8,%9}, {%0,%1,%2,%3};"
        : "+f"(c[0]), "+f"(c[1]), "+f"(c[2]), "+f"(c[3])
        : "r"(a0), "r"(a1), "r"(a2), "r"(a3), "r"(b0), "r"(b1));
}

// ---------------- sorting (counting sort by dst, once per call) ----------------
__global__ void k_zero_hist() {
    int i = blockIdx.x * blockDim.x + threadIdx.x;
    if (i < Nn) g_hist[i] = 0;
}
// 4 edges per thread via int4
__global__ void k_hist(const int* __restrict__ dst) {
    int i = blockIdx.x * blockDim.x + threadIdx.x;
    if (i < Ee / 4) {
        int4 d = ((const int4*)dst)[i];
        atomicAdd(&g_hist[d.x], 1);
        atomicAdd(&g_hist[d.y], 1);
        atomicAdd(&g_hist[d.z], 1);
        atomicAdd(&g_hist[d.w], 1);
    }
}
__global__ void k_scan() {  // 1 block, 1024 threads
    __shared__ int ssum[1024];
    int t = threadIdx.x;
    const int CH = (Nn + 1023) / 1024;
    int base = t * CH;
    int s = 0;
    for (int i = 0; i < CH; i++) {
        int idx = base + i;
        if (idx < Nn) s += g_hist[idx];
    }
    ssum[t] = s;
    __syncthreads();
    for (int off = 1; off < 1024; off <<= 1) {
        int v = (t >= off) ? ssum[t - off] : 0;
        __syncthreads();
        ssum[t] += v;
        __syncthreads();
    }
    int prefix = (t == 0) ? 0 : ssum[t - 1];
    for (int i = 0; i < CH; i++) {
        int idx = base + i;
        if (idx < Nn) {
            int h = g_hist[idx];
            g_cur[idx] = prefix;
            prefix += h;
        }
    }
}
// 4 edges per thread via int4
__global__ void k_scatter(const int* __restrict__ src, const int* __restrict__ dst) {
    int i = blockIdx.x * blockDim.x + threadIdx.x;
    if (i < Ee / 4) {
        int4 d = ((const int4*)dst)[i];
        int4 s = ((const int4*)src)[i];
        int p;
        p = atomicAdd(&g_cur[d.x], 1); g_sdst[p] = d.x; g_ssrc[p] = s.x;
        p = atomicAdd(&g_cur[d.y], 1); g_sdst[p] = d.y; g_ssrc[p] = s.y;
        p = atomicAdd(&g_cur[d.z], 1); g_sdst[p] = d.z; g_ssrc[p] = s.z;
        p = atomicAdd(&g_cur[d.w], 1); g_sdst[p] = d.w; g_ssrc[p] = s.w;
    }
}

// ---------------- per-layer kernels ----------------
// node GEMM via TF32 mma: u = xn@(w1top - w1bot) + b1, v = xn@w1bot
// xn = BN(prev stats) folded input. Also zeroes g_agg for this layer.
#define NG_XST 68
#define NG_WST 132
#define NG_OFF_W   (64 * NG_XST)
#define NG_OFF_SC  (NG_OFF_W + 64 * NG_WST)
#define NG_OFF_SH  (NG_OFF_SC + 64)
#define NG_OFF_B1  (NG_OFF_SH + 64)
#define NG_SMEM    ((NG_OFF_B1 + 64) * 4)
__global__ void __launch_bounds__(256) k_node_gemm64(
    const float* __restrict__ x_in,  // null -> read g_x
    const float* __restrict__ w1, const float* __restrict__ b1,
    const float* __restrict__ g, const float* __restrict__ be) {
    extern __shared__ __align__(16) float smem[];
    float* sX = smem;                 // [64][68] tf32
    float* sW = smem + NG_OFF_W;      // [64][132] tf32 (cols 0-63 A, 64-127 B)
    float* s_sc = smem + NG_OFF_SC;
    float* s_sh = smem + NG_OFF_SH;
    float* s_b1 = smem + NG_OFF_B1;
    const float* x = x_in ? x_in : g_x;
    int t = threadIdx.x;
    int n0 = blockIdx.x * 64;
    // fused: zero the segment-max accumulator
    {
        int stride = gridDim.x * blockDim.x;
        for (int i = blockIdx.x * blockDim.x + t; i < Nn * 64; i += stride)
            g_agg[i] = 0u;
    }
    if (t < 64) {
        float sc = 1.0f, sh = 0.0f;
        if (g) {
            float mu = g_sum[t] * (1.0f / Nn);
            float var = g_sumsq[t] * (1.0f / Nn) - mu * mu;
            sc = rsqrtf(var + 1e-5f) * g[t];
            sh = be[t] - mu * sc;
        }
        s_sc[t] = sc;
        s_sh[t] = sh;
        s_b1[t] = b1[t];
    }
    // stage w1 -> sW (tf32)
#pragma unroll
    for (int r = 0; r < 8; r++) {
        int idx = r * 256 + t;           // 2048 float4 tasks
        int k = idx >> 5, c4 = idx & 31;
        float4 val;
        int col;
        if (c4 < 16) {                   // A = w1top - w1bot, cols 0-63
            col = c4 * 4;
            float4 tp = *(const float4*)(w1 + k * 64 + col);
            float4 bt = *(const float4*)(w1 + (k + 64) * 64 + col);
            val.x = tp.x - bt.x; val.y = tp.y - bt.y;
            val.z = tp.z - bt.z; val.w = tp.w - bt.w;
        } else {                         // B = w1bot, cols 64-127
            col = (c4 - 16) * 4;
            val = *(const float4*)(w1 + (k + 64) * 64 + col);
            col += 64;
        }
        float* dp = sW + k * NG_WST + col;
        dp[0] = tf32f(val.x); dp[1] = tf32f(val.y);
        dp[2] = tf32f(val.z); dp[3] = tf32f(val.w);
    }
    __syncthreads();
    // stage x (BN fold, tf32) -> sX
#pragma unroll
    for (int r = 0; r < 4; r++) {
        int idx = r * 256 + t;
        int nl = idx >> 4, k4 = (idx & 15) << 2;
        int n = n0 + nl;
        float4 xv = (n < Nn) ? *(const float4*)(x + n * 64 + k4)
                             : make_float4(0.f, 0.f, 0.f, 0.f);
        float4 scv = *(const float4*)(s_sc + k4);
        float4 shv = *(const float4*)(s_sh + k4);
        float* dp = sX + nl * NG_XST + k4;
        dp[0] = tf32f(fmaf(xv.x, scv.x, shv.x));
        dp[1] = tf32f(fmaf(xv.y, scv.y, shv.y));
        dp[2] = tf32f(fmaf(xv.z, scv.z, shv.z));
        dp[3] = tf32f(fmaf(xv.w, scv.w, shv.w));
    }
    __syncthreads();
    // MMA: warp w handles rows (w&3)*16 and col half (w>>2)*64
    int lane = t & 31;
    int gid = lane >> 2, tig = lane & 3;
    int w = t >> 5;
    int r0 = (w & 3) * 16;
    int ch = (w >> 2) * 64;
    float acc[8][4];
#pragma unroll
    for (int i = 0; i < 8; i++)
#pragma unroll
        for (int j = 0; j < 4; j++) acc[i][j] = 0.f;
#pragma unroll
    for (int kt = 0; kt < 8; kt++) {
        int k0 = kt * 8;
        unsigned a0 = __float_as_uint(sX[(r0 + gid)     * NG_XST + k0 + tig]);
        unsigned a1 = __float_as_uint(sX[(r0 + gid + 8) * NG_XST + k0 + tig]);
        unsigned a2 = __float_as_uint(sX[(r0 + gid)     * NG_XST + k0 + tig + 4]);
        unsigned a3 = __float_as_uint(sX[(r0 + gid + 8) * NG_XST + k0 + tig + 4]);
#pragma unroll
        for (int nt = 0; nt < 8; nt++) {
            unsigned b0 = __float_as_uint(sW[(k0 + tig)     * NG_WST + ch + nt * 8 + gid]);
            unsigned b1v = __float_as_uint(sW[(k0 + tig + 4) * NG_WST + ch + nt * 8 + gid]);
            mma_tf32(acc[nt], a0, a1, a2, a3, b0, b1v);
        }
    }
    // store: cols<64 -> u (+b1), cols>=64 -> v
    int nA = n0 + r0 + gid;
    int nB = nA + 8;
#pragma unroll
    for (int nt = 0; nt < 8; nt++) {
        int col = ch + nt * 8 + 2 * tig;
        float add0 = 0.f, add1 = 0.f;
        float* basep;
        int cc;
        if (col < 64) {
            add0 = s_b1[col]; add1 = s_b1[col + 1];
            basep = g_u; cc = col;
        } else {
            basep = g_v; cc = col - 64;
        }
        if (nA < Nn)
            *(float2*)(basep + nA * 64 + cc) =
                make_float2(acc[nt][0] + add0, acc[nt][1] + add1);
        if (nB < Nn)
            *(float2*)(basep + nB * 64 + cc) =
                make_float2(acc[nt][2] + add0, acc[nt][3] + add1);
    }
}

// layer-3 node GEMM: dout=8, BN(layer2) folded; zeroes g_agg[0..Nn*8)
__global__ void __launch_bounds__(256) k_node_gemm8(
    const float* __restrict__ w1, const float* __restrict__ b1,
    const float* __restrict__ g, const float* __restrict__ be) {
    __shared__ float sW[64 * 16];
    __shared__ float s_sc[64], s_sh[64];
    int t = threadIdx.x;
    {
        int stride = gridDim.x * blockDim.x;
        for (int i = blockIdx.x * blockDim.x + t; i < Nn * 8; i += stride)
            g_agg[i] = 0u;
    }
    if (t < 64) {
        float mu = g_sum[t] * (1.0f / Nn);
        float var = g_sumsq[t] * (1.0f / Nn) - mu * mu;
        float sc = rsqrtf(var + 1e-5f) * g[t];
        s_sc[t] = sc;
        s_sh[t] = be[t] - mu * sc;
    }
#pragma unroll
    for (int r = 0; r < 4; r++) {
        int idx = r * 256 + t;
        int k = idx >> 4, cc = idx & 15;
        float wB = w1[(k + 64) * 8 + (cc & 7)];
        sW[idx] = (cc < 8) ? (w1[k * 8 + cc] - wB) : wB;
    }
    __syncthreads();
    int n = blockIdx.x * 16 + (t >> 4);
    int cc = t & 15;
    if (n >= Nn) return;
    const float* xr = g_x + n * 64;
    float acc = 0.f;
#pragma unroll 16
    for (int k = 0; k < 64; k++) {
        float xn = fmaf(__ldg(xr + k), s_sc[k], s_sh[k]);
        acc = fmaf(xn, sW[k * 16 + cc], acc);
    }
    if (cc < 8) g_u[n * 8 + cc] = acc + b1[cc];
    else        g_v[n * 8 + cc - 8] = acc;
}

// edge kernel (dout=64): 128-edge tile, TF32 mma, per-segment block reduction.
// Interior segments -> plain final store; boundary segments -> atomicMax.
#define EB    128
#define SA_ST 68
#define OFF_W    (EB * SA_ST)
#define OFF_SST  (OFF_W + 64 * SA_ST)
#define OFF_NSEG (OFF_SST + 132)
#define EDGE_SMEM ((OFF_NSEG + 4) * 4)
__global__ void __launch_bounds__(256) k_edge64(const float* __restrict__ w2) {
    extern __shared__ __align__(16) float smem[];
    float* sA = smem;
    float* sW = smem + OFF_W;
    int* sSstart = (int*)(smem + OFF_SST);
    int* sNseg = (int*)(smem + OFF_NSEG);
    int t = threadIdx.x;
    int e0 = blockIdx.x * EB;

    // zero BN stat accumulators once per layer (before this layer's decode)
    if (blockIdx.x == 0 && t < 128) {
        if (t < 64) g_sum[t] = 0.f;
        else        g_sumsq[t - 64] = 0.f;
    }
    // warp 0: segment starts via flags + warp scan (dsts sorted)
    if (t < 32) {
        int base = t * 4;
        int d0 = __ldg(g_sdst + e0 + base);
        int d1 = __ldg(g_sdst + e0 + base + 1);
        int d2 = __ldg(g_sdst + e0 + base + 2);
        int d3 = __ldg(g_sdst + e0 + base + 3);
        int dm1 = (base > 0) ? __ldg(g_sdst + e0 + base - 1) : (d0 ^ 1);
        int h0 = (d0 != dm1), h1 = (d1 != d0), h2 = (d2 != d1), h3 = (d3 != d2);
        int lc0 = h0, lc1 = lc0 + h1, lc2 = lc1 + h2, lc3 = lc2 + h3;
        int c = lc3;
        int v = c;
#pragma unroll
        for (int o = 1; o < 32; o <<= 1) {
            int y = __shfl_up_sync(0xffffffffu, v, o);
            if (t >= o) v += y;
        }
        int off = v - c;
        if (h0) sSstart[off + lc0 - 1] = base;
        if (h1) sSstart[off + lc1 - 1] = base + 1;
        if (h2) sSstart[off + lc2 - 1] = base + 2;
        if (h3) sSstart[off + lc3 - 1] = base + 3;
        if (t == 31) {
            *sNseg = off + c;
            sSstart[off + c] = EB;
        }
    }
    // stage w2 (tf32), float4 loads
#pragma unroll
    for (int r = 0; r < 4; r++) {
        int idx = r * 256 + t;
        int k = idx >> 4, n4 = (idx & 15) << 2;
        float4 wv = *(const float4*)(w2 + k * 64 + n4);
        float* dp = sW + k * SA_ST + n4;
        dp[0] = tf32f(wv.x); dp[1] = tf32f(wv.y);
        dp[2] = tf32f(wv.z); dp[3] = tf32f(wv.w);
    }
    // gather + mish -> sA (tf32)
#pragma unroll
    for (int r = 0; r < 8; r++) {
        int idx = r * 256 + t;
        int el = idx >> 4;
        int k4 = (idx & 15) << 2;
        int d = __ldg(g_sdst + e0 + el);
        int s = __ldg(g_ssrc + e0 + el);
        float4 uu = *(const float4*)(g_u + d * 64 + k4);
        float4 vv = *(const float4*)(g_v + s * 64 + k4);
        float4 o;
        o.x = tf32f(mishf(uu.x + vv.x));
        o.y = tf32f(mishf(uu.y + vv.y));
        o.z = tf32f(mishf(uu.z + vv.z));
        o.w = tf32f(mishf(uu.w + vv.w));
        *(float4*)(sA + el * SA_ST + k4) = o;
    }
    __syncthreads();
    // MMA: warp w -> C[16][64] for edges [w*16, w*16+16)
    int lane = t & 31;
    int gid = lane >> 2, tig = lane & 3;
    int ebase = (t >> 5) * 16;
    float acc[8][4];
#pragma unroll
    for (int i = 0; i < 8; i++)
#pragma unroll
        for (int j = 0; j < 4; j++) acc[i][j] = 0.f;
#pragma unroll
    for (int kt = 0; kt < 8; kt++) {
        int k0 = kt * 8;
        unsigned a0 = __float_as_uint(sA[(ebase + gid)     * SA_ST + k0 + tig]);
        unsigned a1 = __float_as_uint(sA[(ebase + gid + 8) * SA_ST + k0 + tig]);
        unsigned a2 = __float_as_uint(sA[(ebase + gid)     * SA_ST + k0 + tig + 4]);
        unsigned a3 = __float_as_uint(sA[(ebase + gid + 8) * SA_ST + k0 + tig + 4]);
#pragma unroll
        for (int nt = 0; nt < 8; nt++) {
            unsigned b0 = __float_as_uint(sW[(k0 + tig)     * SA_ST + nt * 8 + gid]);
            unsigned b1 = __float_as_uint(sW[(k0 + tig + 4) * SA_ST + nt * 8 + gid]);
            mma_tf32(acc[nt], a0, a1, a2, a3, b0, b1);
        }
    }
    __syncwarp();
    // write C back over sA
#pragma unroll
    for (int nt = 0; nt < 8; nt++) {
        int col = nt * 8 + 2 * tig;
        *(float2*)(sA + (ebase + gid)     * SA_ST + col) = make_float2(acc[nt][0], acc[nt][1]);
        *(float2*)(sA + (ebase + gid + 8) * SA_ST + col) = make_float2(acc[nt][2], acc[nt][3]);
    }
    __syncthreads();
    // per-(segment, colgroup) reduction; interior segments -> plain store
    int S = *sNseg;
    for (int task = t; task < S * 16; task += 256) {
        int s = task >> 4, txx = task & 15;
        int st = sSstart[s], en = sSstart[s + 1];
        const float* aP = sA + st * SA_ST + txx * 4;
        float4 m = *(const float4*)aP;
        for (int i = 1; i < en - st; i++) {
            float4 h = *(const float4*)(aP + i * SA_ST);
            m.x = fmaxf(m.x, h.x);
            m.y = fmaxf(m.y, h.y);
            m.z = fmaxf(m.z, h.z);
            m.w = fmaxf(m.w, h.w);
        }
        int dd = __ldg(g_sdst + e0 + st);
        unsigned int* p = g_agg + dd * 64 + txx * 4;
        unsigned int ex = encf(m.x), ey = encf(m.y), ez = encf(m.z), ew = encf(m.w);
        if (s == 0 || s == S - 1) {
            atomicMax(p + 0, ex);
            atomicMax(p + 1, ey);
            atomicMax(p + 2, ez);
            atomicMax(p + 3, ew);
        } else {
            *(uint4*)p = make_uint4(ex, ey, ez, ew);
        }
    }
}

// edge kernel (dout=8): thread handles 8 consecutive sorted edges (fp32)
__global__ void k_edge8(const float* __restrict__ w2) {
    __shared__ float sW[64];
    int t = threadIdx.x;
    if (t < 64) sW[t] = w2[t];
    __syncthreads();
    int base = (blockIdx.x * blockDim.x + t) * 8;
    if (base >= Ee) return;
    int curd = -1;
    float m[8];
#pragma unroll
    for (int j = 0; j < 8; j++) {
        int e = base + j;
        int d = g_sdst[e], s = g_ssrc[e];
        float4 u0 = *(const float4*)(g_u + d * 8);
        float4 u1 = *(const float4*)(g_u + d * 8 + 4);
        float4 v0 = *(const float4*)(g_v + s * 8);
        float4 v1 = *(const float4*)(g_v + s * 8 + 4);
        float pre[8];
        pre[0] = mishf(u0.x + v0.x); pre[1] = mishf(u0.y + v0.y);
        pre[2] = mishf(u0.z + v0.z); pre[3] = mishf(u0.w + v0.w);
        pre[4] = mishf(u1.x + v1.x); pre[5] = mishf(u1.y + v1.y);
        pre[6] = mishf(u1.z + v1.z); pre[7] = mishf(u1.w + v1.w);
        float h[8];
#pragma unroll
        for (int c = 0; c < 8; c++) {
            float a = 0.f;
#pragma unroll
            for (int k = 0; k < 8; k++) a = fmaf(pre[k], sW[k * 8 + c], a);
            h[c] = a;
        }
        if (d != curd) {
            if (curd >= 0) {
#pragma unroll
                for (int c = 0; c < 8; c++)
                    atomicMax(g_agg + curd * 8 + c, encf(m[c]));
            }
            curd = d;
#pragma unroll
            for (int c = 0; c < 8; c++) m[c] = h[c];
        } else {
#pragma unroll
            for (int c = 0; c < 8; c++) m[c] = fmaxf(m[c], h[c]);
        }
    }
#pragma unroll
    for (int c = 0; c < 8; c++) atomicMax(g_agg + curd * 8 + c, encf(m[c]));
}

// decode agg -> g_x (+b2, empty->0), accumulate BN stats. uint4/float4 I/O.
// Per-thread channel group (i*4 & 63) is loop-invariant because the grid
// stride in floats (grid*256*4) is a multiple of 64.
__global__ void k_decode_stats64(const float* __restrict__ b2) {
    __shared__ float ss[64], sq[64];
    int t = threadIdx.x;
    if (t < 64) { ss[t] = 0.f; sq[t] = 0.f; }
    __syncthreads();
    int tid = blockIdx.x * blockDim.x + t;
    int c0 = (tid * 4) & 63;
    float4 b2v = *(const float4*)(b2 + c0);
    float4 lsum = make_float4(0.f, 0.f, 0.f, 0.f);
    float4 lsq  = make_float4(0.f, 0.f, 0.f, 0.f);
    int stride = gridDim.x * blockDim.x;
    for (int i = tid; i < Nn * 16; i += stride) {
        uint4 a = ((const uint4*)g_agg)[i];
        float4 val;
        val.x = (a.x == 0u) ? 0.f : (decf(a.x) + b2v.x);
        val.y = (a.y == 0u) ? 0.f : (decf(a.y) + b2v.y);
        val.z = (a.z == 0u) ? 0.f : (decf(a.z) + b2v.z);
        val.w = (a.w == 0u) ? 0.f : (decf(a.w) + b2v.w);
        ((float4*)g_x)[i] = val;
        lsum.x += val.x; lsum.y += val.y; lsum.z += val.z; lsum.w += val.w;
        lsq.x += val.x * val.x; lsq.y += val.y * val.y;
        lsq.z += val.z * val.z; lsq.w += val.w * val.w;
    }
    atomicAdd(&ss[c0 + 0], lsum.x);
    atomicAdd(&ss[c0 + 1], lsum.y);
    atomicAdd(&ss[c0 + 2], lsum.z);
    atomicAdd(&ss[c0 + 3], lsum.w);
    atomicAdd(&sq[c0 + 0], lsq.x);
    atomicAdd(&sq[c0 + 1], lsq.y);
    atomicAdd(&sq[c0 + 2], lsq.z);
    atomicAdd(&sq[c0 + 3], lsq.w);
    __syncthreads();
    if (t < 64) {
        atomicAdd(&g_sum[t], ss[t]);
        atomicAdd(&g_sumsq[t], sq[t]);
    }
}

__global__ void k_decode_out(float* __restrict__ out, const float* __restrict__ b2) {
    int i = blockIdx.x * blockDim.x + threadIdx.x;
    if (i < Nn * 8) {
        unsigned int a = g_agg[i];
        out[i] = (a == 0u) ? 0.f : (decf(a) + b2[i & 7]);
    }
}

// ---------------- launch ----------------
extern "C" void kernel_launch(void* const* d_in, const int* in_sizes, int n_in,
                              void* d_out, int out_size) {
    const float* x  = (const float*)d_in[0];
    const int*   ei = (const int*)d_in[1];
    const int* src = ei;        // edge_index[0]
    const int* dst = ei + Ee;   // edge_index[1]

    const float* W1[4] = {(const float*)d_in[3], (const float*)d_in[9],
                          (const float*)d_in[15], (const float*)d_in[21]};
    const float* B1[4] = {(const float*)d_in[4], (const float*)d_in[10],
                          (const float*)d_in[16], (const float*)d_in[22]};
    const float* W2[4] = {(const float*)d_in[5], (const float*)d_in[11],
                          (const float*)d_in[17], (const float*)d_in[23]};
    const float* B2[4] = {(const float*)d_in[6], (const float*)d_in[12],
                          (const float*)d_in[18], (const float*)d_in[24]};
    const float* G[3]  = {(const float*)d_in[7], (const float*)d_in[13],
                          (const float*)d_in[19]};
    const float* BE[3] = {(const float*)d_in[8], (const float*)d_in[14],
                          (const float*)d_in[20]};

    cudaFuncSetAttribute(k_edge64, cudaFuncAttributeMaxDynamicSharedMemorySize,
                         EDGE_SMEM);
    cudaFuncSetAttribute(k_node_gemm64, cudaFuncAttributeMaxDynamicSharedMemorySize,
                         NG_SMEM);

    // sort edges by dst (counting sort)
    k_zero_hist<<<(Nn + 255) / 256, 256>>>();
    k_hist<<<(Ee / 4 + 255) / 256, 256>>>(dst);
    k_scan<<<1, 1024>>>();
    k_scatter<<<(Ee / 4 + 255) / 256, 256>>>(src, dst);

    // layers 0..2 (din=dout=64); BN of layer l-1 folded into node GEMM of l
    for (int l = 0; l < 3; l++) {
        k_node_gemm64<<<(Nn + 63) / 64, 256, NG_SMEM>>>(
            l == 0 ? x : nullptr, W1[l], B1[l],
            l == 0 ? nullptr : G[l - 1], l == 0 ? nullptr : BE[l - 1]);
        k_edge64<<<Ee / EB, 256, EDGE_SMEM>>>(W2[l]);
        k_decode_stats64<<<592, 256>>>(B2[l]);
    }

    // layer 3 (din=64, dout=8, BN of layer2 folded) -> d_out
    k_node_gemm8<<<(Nn + 15) / 16, 256>>>(W1[3], B1[3], G[2], BE[2]);
    k_edge8<<<(Ee / 8 + 255) / 256, 256>>>(W2[3]);
    k_decode_out<<<(Nn * 8 + 255) / 256, 256>>>((float*)d_out, B2[3]);
}

// round 14
// speedup vs baseline: 1.1794x; 1.1007x over previous
#include <cuda_runtime.h>
#include <math.h>

#define Nn 50000
#define Ee 800000

// ---------------- device scratch (static, no allocation) ----------------
__device__ float        g_x[Nn * 64];     // current node features (pre-BN)
__device__ float        g_u[Nn * 64];     // u = x@A + b1   (dst side)
__device__ float        g_v[Nn * 64];     // v = x@B        (src side)
__device__ __align__(16) unsigned int g_agg[Nn * 64];  // encoded seg-max acc
__device__ int          g_hist[Nn];
__device__ int          g_cur[Nn];
__device__ int          g_sdst[Ee];       // edges sorted by dst
__device__ int          g_ssrc[Ee];
__device__ float        g_sum[64];
__device__ float        g_sumsq[64];

// ---------------- helpers ----------------
__device__ __forceinline__ unsigned int encf(float f) {
    unsigned int b = __float_as_uint(f);
    return (b & 0x80000000u) ? ~b : (b | 0x80000000u);
}
__device__ __forceinline__ float decf(unsigned int u) {
    return (u & 0x80000000u) ? __uint_as_float(u & 0x7FFFFFFFu)
                             : __uint_as_float(~u);
}
// mish(x) = x * (t^2+2t)/(t^2+2t+2), t=e^x
__device__ __forceinline__ float mishf(float x) {
    float xc = fminf(x, 40.0f);
    float t = __expf(xc);
    float num = fmaf(t, t, 2.0f * t);
    float r = __fdividef(num, num + 2.0f);
    return x * r;
}
__device__ __forceinline__ unsigned int tf32_of(float f) {
    unsigned int r;
    asm("cvt.rna.tf32.f32 %0, %1;" : "=r"(r) : "f"(f));
    return r;
}
__device__ __forceinline__ float tf32f(float f) {
    return __uint_as_float(tf32_of(f));
}
__device__ __forceinline__ void mma_tf32(float c[4],
    unsigned a0, unsigned a1, unsigned a2, unsigned a3,
    unsigned b0, unsigned b1) {
    asm volatile(
        "mma.sync.aligned.m16n8k8.row.col.f32.tf32.tf32.f32 "
        "{%0,%1,%2,%3}, {%4,%5,%6,%7}, {%8,%9}, {%0,%1,%2,%3};"
        : "+f"(c[0]), "+f"(c[1]), "+f"(c[2]), "+f"(c[3])
        : "r"(a0), "r"(a1), "r"(a2), "r"(a3), "r"(b0), "r"(b1));
}

// ---------------- sorting (counting sort by dst, once per call) ----------------
__global__ void k_zero_hist() {
    int i = blockIdx.x * blockDim.x + threadIdx.x;
    if (i < Nn) g_hist[i] = 0;
}
// 4 edges per thread via int4
__global__ void k_hist(const int* __restrict__ dst) {
    int i = blockIdx.x * blockDim.x + threadIdx.x;
    if (i < Ee / 4) {
        int4 d = ((const int4*)dst)[i];
        atomicAdd(&g_hist[d.x], 1);
        atomicAdd(&g_hist[d.y], 1);
        atomicAdd(&g_hist[d.z], 1);
        atomicAdd(&g_hist[d.w], 1);
    }
}
__global__ void k_scan() {  // 1 block, 1024 threads
    __shared__ int ssum[1024];
    int t = threadIdx.x;
    const int CH = (Nn + 1023) / 1024;
    int base = t * CH;
    int s = 0;
    for (int i = 0; i < CH; i++) {
        int idx = base + i;
        if (idx < Nn) s += g_hist[idx];
    }
    ssum[t] = s;
    __syncthreads();
    for (int off = 1; off < 1024; off <<= 1) {
        int v = (t >= off) ? ssum[t - off] : 0;
        __syncthreads();
        ssum[t] += v;
        __syncthreads();
    }
    int prefix = (t == 0) ? 0 : ssum[t - 1];
    for (int i = 0; i < CH; i++) {
        int idx = base + i;
        if (idx < Nn) {
            int h = g_hist[idx];
            g_cur[idx] = prefix;
            prefix += h;
        }
    }
}
// 4 edges per thread via int4
__global__ void k_scatter(const int* __restrict__ src, const int* __restrict__ dst) {
    int i = blockIdx.x * blockDim.x + threadIdx.x;
    if (i < Ee / 4) {
        int4 d = ((const int4*)dst)[i];
        int4 s = ((const int4*)src)[i];
        int p;
        p = atomicAdd(&g_cur[d.x], 1); g_sdst[p] = d.x; g_ssrc[p] = s.x;
        p = atomicAdd(&g_cur[d.y], 1); g_sdst[p] = d.y; g_ssrc[p] = s.y;
        p = atomicAdd(&g_cur[d.z], 1); g_sdst[p] = d.z; g_ssrc[p] = s.z;
        p = atomicAdd(&g_cur[d.w], 1); g_sdst[p] = d.w; g_ssrc[p] = s.w;
    }
}

// ---------------- per-layer kernels ----------------
// node GEMM via TF32 mma: u = xn@(w1top - w1bot) + b1, v = xn@w1bot
// xn = BN(prev stats) folded input. Also zeroes g_agg for this layer.
// NG_WST = 136 (== 8 mod 32): B-fragment LDS lane pattern tig*8+gid is a
// bijection over the 32 banks -> conflict-free (132 gave 2-way conflicts).
#define NG_XST 68
#define NG_WST 136
#define NG_OFF_W   (64 * NG_XST)
#define NG_OFF_SC  (NG_OFF_W + 64 * NG_WST)
#define NG_OFF_SH  (NG_OFF_SC + 64)
#define NG_OFF_B1  (NG_OFF_SH + 64)
#define NG_SMEM    ((NG_OFF_B1 + 64) * 4)
__global__ void __launch_bounds__(256) k_node_gemm64(
    const float* __restrict__ x_in,  // null -> read g_x
    const float* __restrict__ w1, const float* __restrict__ b1,
    const float* __restrict__ g, const float* __restrict__ be) {
    extern __shared__ __align__(16) float smem[];
    float* sX = smem;                 // [64][68] tf32
    float* sW = smem + NG_OFF_W;      // [64][136] tf32 (cols 0-63 A, 64-127 B)
    float* s_sc = smem + NG_OFF_SC;
    float* s_sh = smem + NG_OFF_SH;
    float* s_b1 = smem + NG_OFF_B1;
    const float* x = x_in ? x_in : g_x;
    int t = threadIdx.x;
    int n0 = blockIdx.x * 64;
    // fused: zero the segment-max accumulator
    {
        int stride = gridDim.x * blockDim.x;
        for (int i = blockIdx.x * blockDim.x + t; i < Nn * 64; i += stride)
            g_agg[i] = 0u;
    }
    if (t < 64) {
        float sc = 1.0f, sh = 0.0f;
        if (g) {
            float mu = g_sum[t] * (1.0f / Nn);
            float var = g_sumsq[t] * (1.0f / Nn) - mu * mu;
            sc = rsqrtf(var + 1e-5f) * g[t];
            sh = be[t] - mu * sc;
        }
        s_sc[t] = sc;
        s_sh[t] = sh;
        s_b1[t] = b1[t];
    }
    // stage w1 -> sW (tf32)
#pragma unroll
    for (int r = 0; r < 8; r++) {
        int idx = r * 256 + t;           // 2048 float4 tasks
        int k = idx >> 5, c4 = idx & 31;
        float4 val;
        int col;
        if (c4 < 16) {                   // A = w1top - w1bot, cols 0-63
            col = c4 * 4;
            float4 tp = *(const float4*)(w1 + k * 64 + col);
            float4 bt = *(const float4*)(w1 + (k + 64) * 64 + col);
            val.x = tp.x - bt.x; val.y = tp.y - bt.y;
            val.z = tp.z - bt.z; val.w = tp.w - bt.w;
        } else {                         // B = w1bot, cols 64-127
            col = (c4 - 16) * 4;
            val = *(const float4*)(w1 + (k + 64) * 64 + col);
            col += 64;
        }
        float* dp = sW + k * NG_WST + col;
        dp[0] = tf32f(val.x); dp[1] = tf32f(val.y);
        dp[2] = tf32f(val.z); dp[3] = tf32f(val.w);
    }
    __syncthreads();
    // stage x (BN fold, tf32) -> sX
#pragma unroll
    for (int r = 0; r < 4; r++) {
        int idx = r * 256 + t;
        int nl = idx >> 4, k4 = (idx & 15) << 2;
        int n = n0 + nl;
        float4 xv = (n < Nn) ? *(const float4*)(x + n * 64 + k4)
                             : make_float4(0.f, 0.f, 0.f, 0.f);
        float4 scv = *(const float4*)(s_sc + k4);
        float4 shv = *(const float4*)(s_sh + k4);
        float* dp = sX + nl * NG_XST + k4;
        dp[0] = tf32f(fmaf(xv.x, scv.x, shv.x));
        dp[1] = tf32f(fmaf(xv.y, scv.y, shv.y));
        dp[2] = tf32f(fmaf(xv.z, scv.z, shv.z));
        dp[3] = tf32f(fmaf(xv.w, scv.w, shv.w));
    }
    __syncthreads();
    // MMA: warp w handles rows (w&3)*16 and col half (w>>2)*64
    int lane = t & 31;
    int gid = lane >> 2, tig = lane & 3;
    int w = t >> 5;
    int r0 = (w & 3) * 16;
    int ch = (w >> 2) * 64;
    float acc[8][4];
#pragma unroll
    for (int i = 0; i < 8; i++)
#pragma unroll
        for (int j = 0; j < 4; j++) acc[i][j] = 0.f;
#pragma unroll
    for (int kt = 0; kt < 8; kt++) {
        int k0 = kt * 8;
        unsigned a0 = __float_as_uint(sX[(r0 + gid)     * NG_XST + k0 + tig]);
        unsigned a1 = __float_as_uint(sX[(r0 + gid + 8) * NG_XST + k0 + tig]);
        unsigned a2 = __float_as_uint(sX[(r0 + gid)     * NG_XST + k0 + tig + 4]);
        unsigned a3 = __float_as_uint(sX[(r0 + gid + 8) * NG_XST + k0 + tig + 4]);
#pragma unroll
        for (int nt = 0; nt < 8; nt++) {
            unsigned b0 = __float_as_uint(sW[(k0 + tig)     * NG_WST + ch + nt * 8 + gid]);
            unsigned b1v = __float_as_uint(sW[(k0 + tig + 4) * NG_WST + ch + nt * 8 + gid]);
            mma_tf32(acc[nt], a0, a1, a2, a3, b0, b1v);
        }
    }
    // store: cols<64 -> u (+b1), cols>=64 -> v
    int nA = n0 + r0 + gid;
    int nB = nA + 8;
#pragma unroll
    for (int nt = 0; nt < 8; nt++) {
        int col = ch + nt * 8 + 2 * tig;
        float add0 = 0.f, add1 = 0.f;
        float* basep;
        int cc;
        if (col < 64) {
            add0 = s_b1[col]; add1 = s_b1[col + 1];
            basep = g_u; cc = col;
        } else {
            basep = g_v; cc = col - 64;
        }
        if (nA < Nn)
            *(float2*)(basep + nA * 64 + cc) =
                make_float2(acc[nt][0] + add0, acc[nt][1] + add1);
        if (nB < Nn)
            *(float2*)(basep + nB * 64 + cc) =
                make_float2(acc[nt][2] + add0, acc[nt][3] + add1);
    }
}

// layer-3 node GEMM: dout=8, BN(layer2) folded; zeroes g_agg[0..Nn*8)
__global__ void __launch_bounds__(256) k_node_gemm8(
    const float* __restrict__ w1, const float* __restrict__ b1,
    const float* __restrict__ g, const float* __restrict__ be) {
    __shared__ float sW[64 * 16];
    __shared__ float s_sc[64], s_sh[64];
    int t = threadIdx.x;
    {
        int stride = gridDim.x * blockDim.x;
        for (int i = blockIdx.x * blockDim.x + t; i < Nn * 8; i += stride)
            g_agg[i] = 0u;
    }
    if (t < 64) {
        float mu = g_sum[t] * (1.0f / Nn);
        float var = g_sumsq[t] * (1.0f / Nn) - mu * mu;
        float sc = rsqrtf(var + 1e-5f) * g[t];
        s_sc[t] = sc;
        s_sh[t] = be[t] - mu * sc;
    }
#pragma unroll
    for (int r = 0; r < 4; r++) {
        int idx = r * 256 + t;
        int k = idx >> 4, cc = idx & 15;
        float wB = w1[(k + 64) * 8 + (cc & 7)];
        sW[idx] = (cc < 8) ? (w1[k * 8 + cc] - wB) : wB;
    }
    __syncthreads();
    int n = blockIdx.x * 16 + (t >> 4);
    int cc = t & 15;
    if (n >= Nn) return;
    const float* xr = g_x + n * 64;
    float acc = 0.f;
#pragma unroll 16
    for (int k = 0; k < 64; k++) {
        float xn = fmaf(__ldg(xr + k), s_sc[k], s_sh[k]);
        acc = fmaf(xn, sW[k * 16 + cc], acc);
    }
    if (cc < 8) g_u[n * 8 + cc] = acc + b1[cc];
    else        g_v[n * 8 + cc - 8] = acc;
}

// edge kernel (dout=64): 128-edge tile, TF32 mma, per-segment block reduction.
// sA stride 68 (A reads conflict-free: gid*4+tig bijection);
// sW stride 72 (B reads conflict-free: tig*8+gid bijection; 68 gave 2-way).
#define EB    128
#define SA_ST 68
#define SW_ST 72
#define OFF_W    (EB * SA_ST)
#define OFF_SST  (OFF_W + 64 * SW_ST)
#define OFF_NSEG (OFF_SST + 132)
#define EDGE_SMEM ((OFF_NSEG + 4) * 4)
__global__ void __launch_bounds__(256) k_edge64(const float* __restrict__ w2) {
    extern __shared__ __align__(16) float smem[];
    float* sA = smem;
    float* sW = smem + OFF_W;
    int* sSstart = (int*)(smem + OFF_SST);
    int* sNseg = (int*)(smem + OFF_NSEG);
    int t = threadIdx.x;
    int e0 = blockIdx.x * EB;

    // zero BN stat accumulators once per layer (before this layer's decode)
    if (blockIdx.x == 0 && t < 128) {
        if (t < 64) g_sum[t] = 0.f;
        else        g_sumsq[t - 64] = 0.f;
    }
    // warp 0: segment starts via flags + warp scan (dsts sorted)
    if (t < 32) {
        int base = t * 4;
        int d0 = __ldg(g_sdst + e0 + base);
        int d1 = __ldg(g_sdst + e0 + base + 1);
        int d2 = __ldg(g_sdst + e0 + base + 2);
        int d3 = __ldg(g_sdst + e0 + base + 3);
        int dm1 = (base > 0) ? __ldg(g_sdst + e0 + base - 1) : (d0 ^ 1);
        int h0 = (d0 != dm1), h1 = (d1 != d0), h2 = (d2 != d1), h3 = (d3 != d2);
        int lc0 = h0, lc1 = lc0 + h1, lc2 = lc1 + h2, lc3 = lc2 + h3;
        int c = lc3;
        int v = c;
#pragma unroll
        for (int o = 1; o < 32; o <<= 1) {
            int y = __shfl_up_sync(0xffffffffu, v, o);
            if (t >= o) v += y;
        }
        int off = v - c;
        if (h0) sSstart[off + lc0 - 1] = base;
        if (h1) sSstart[off + lc1 - 1] = base + 1;
        if (h2) sSstart[off + lc2 - 1] = base + 2;
        if (h3) sSstart[off + lc3 - 1] = base + 3;
        if (t == 31) {
            *sNseg = off + c;
            sSstart[off + c] = EB;
        }
    }
    // stage w2 (tf32), float4 loads
#pragma unroll
    for (int r = 0; r < 4; r++) {
        int idx = r * 256 + t;
        int k = idx >> 4, n4 = (idx & 15) << 2;
        float4 wv = *(const float4*)(w2 + k * 64 + n4);
        float* dp = sW + k * SW_ST + n4;
        dp[0] = tf32f(wv.x); dp[1] = tf32f(wv.y);
        dp[2] = tf32f(wv.z); dp[3] = tf32f(wv.w);
    }
    // gather + mish -> sA (tf32)
#pragma unroll
    for (int r = 0; r < 8; r++) {
        int idx = r * 256 + t;
        int el = idx >> 4;
        int k4 = (idx & 15) << 2;
        int d = __ldg(g_sdst + e0 + el);
        int s = __ldg(g_ssrc + e0 + el);
        float4 uu = *(const float4*)(g_u + d * 64 + k4);
        float4 vv = *(const float4*)(g_v + s * 64 + k4);
        float4 o;
        o.x = tf32f(mishf(uu.x + vv.x));
        o.y = tf32f(mishf(uu.y + vv.y));
        o.z = tf32f(mishf(uu.z + vv.z));
        o.w = tf32f(mishf(uu.w + vv.w));
        *(float4*)(sA + el * SA_ST + k4) = o;
    }
    __syncthreads();
    // MMA: warp w -> C[16][64] for edges [w*16, w*16+16)
    int lane = t & 31;
    int gid = lane >> 2, tig = lane & 3;
    int ebase = (t >> 5) * 16;
    float acc[8][4];
#pragma unroll
    for (int i = 0; i < 8; i++)
#pragma unroll
        for (int j = 0; j < 4; j++) acc[i][j] = 0.f;
#pragma unroll
    for (int kt = 0; kt < 8; kt++) {
        int k0 = kt * 8;
        unsigned a0 = __float_as_uint(sA[(ebase + gid)     * SA_ST + k0 + tig]);
        unsigned a1 = __float_as_uint(sA[(ebase + gid + 8) * SA_ST + k0 + tig]);
        unsigned a2 = __float_as_uint(sA[(ebase + gid)     * SA_ST + k0 + tig + 4]);
        unsigned a3 = __float_as_uint(sA[(ebase + gid + 8) * SA_ST + k0 + tig + 4]);
#pragma unroll
        for (int nt = 0; nt < 8; nt++) {
            unsigned b0 = __float_as_uint(sW[(k0 + tig)     * SW_ST + nt * 8 + gid]);
            unsigned b1 = __float_as_uint(sW[(k0 + tig + 4) * SW_ST + nt * 8 + gid]);
            mma_tf32(acc[nt], a0, a1, a2, a3, b0, b1);
        }
    }
    __syncwarp();
    // write C back over sA
#pragma unroll
    for (int nt = 0; nt < 8; nt++) {
        int col = nt * 8 + 2 * tig;
        *(float2*)(sA + (ebase + gid)     * SA_ST + col) = make_float2(acc[nt][0], acc[nt][1]);
        *(float2*)(sA + (ebase + gid + 8) * SA_ST + col) = make_float2(acc[nt][2], acc[nt][3]);
    }
    __syncthreads();
    // per-(segment, colgroup) reduction; interior segments -> plain store
    int S = *sNseg;
    for (int task = t; task < S * 16; task += 256) {
        int s = task >> 4, txx = task & 15;
        int st = sSstart[s], en = sSstart[s + 1];
        const float* aP = sA + st * SA_ST + txx * 4;
        float4 m = *(const float4*)aP;
        for (int i = 1; i < en - st; i++) {
            float4 h = *(const float4*)(aP + i * SA_ST);
            m.x = fmaxf(m.x, h.x);
            m.y = fmaxf(m.y, h.y);
            m.z = fmaxf(m.z, h.z);
            m.w = fmaxf(m.w, h.w);
        }
        int dd = __ldg(g_sdst + e0 + st);
        unsigned int* p = g_agg + dd * 64 + txx * 4;
        unsigned int ex = encf(m.x), ey = encf(m.y), ez = encf(m.z), ew = encf(m.w);
        if (s == 0 || s == S - 1) {
            atomicMax(p + 0, ex);
            atomicMax(p + 1, ey);
            atomicMax(p + 2, ez);
            atomicMax(p + 3, ew);
        } else {
            *(uint4*)p = make_uint4(ex, ey, ez, ew);
        }
    }
}

// edge kernel (dout=8): thread handles 8 consecutive sorted edges (fp32)
__global__ void k_edge8(const float* __restrict__ w2) {
    __shared__ float sW[64];
    int t = threadIdx.x;
    if (t < 64) sW[t] = w2[t];
    __syncthreads();
    int base = (blockIdx.x * blockDim.x + t) * 8;
    if (base >= Ee) return;
    int curd = -1;
    float m[8];
#pragma unroll
    for (int j = 0; j < 8; j++) {
        int e = base + j;
        int d = g_sdst[e], s = g_ssrc[e];
        float4 u0 = *(const float4*)(g_u + d * 8);
        float4 u1 = *(const float4*)(g_u + d * 8 + 4);
        float4 v0 = *(const float4*)(g_v + s * 8);
        float4 v1 = *(const float4*)(g_v + s * 8 + 4);
        float pre[8];
        pre[0] = mishf(u0.x + v0.x); pre[1] = mishf(u0.y + v0.y);
        pre[2] = mishf(u0.z + v0.z); pre[3] = mishf(u0.w + v0.w);
        pre[4] = mishf(u1.x + v1.x); pre[5] = mishf(u1.y + v1.y);
        pre[6] = mishf(u1.z + v1.z); pre[7] = mishf(u1.w + v1.w);
        float h[8];
#pragma unroll
        for (int c = 0; c < 8; c++) {
            float a = 0.f;
#pragma unroll
            for (int k = 0; k < 8; k++) a = fmaf(pre[k], sW[k * 8 + c], a);
            h[c] = a;
        }
        if (d != curd) {
            if (curd >= 0) {
#pragma unroll
                for (int c = 0; c < 8; c++)
                    atomicMax(g_agg + curd * 8 + c, encf(m[c]));
            }
            curd = d;
#pragma unroll
            for (int c = 0; c < 8; c++) m[c] = h[c];
        } else {
#pragma unroll
            for (int c = 0; c < 8; c++) m[c] = fmaxf(m[c], h[c]);
        }
    }
#pragma unroll
    for (int c = 0; c < 8; c++) atomicMax(g_agg + curd * 8 + c, encf(m[c]));
}

// decode agg -> g_x (+b2, empty->0), accumulate BN stats. uint4/float4 I/O.
__global__ void k_decode_stats64(const float* __restrict__ b2) {
    __shared__ float ss[64], sq[64];
    int t = threadIdx.x;
    if (t < 64) { ss[t] = 0.f; sq[t] = 0.f; }
    __syncthreads();
    int tid = blockIdx.x * blockDim.x + t;
    int c0 = (tid * 4) & 63;
    float4 b2v = *(const float4*)(b2 + c0);
    float4 lsum = make_float4(0.f, 0.f, 0.f, 0.f);
    float4 lsq  = make_float4(0.f, 0.f, 0.f, 0.f);
    int stride = gridDim.x * blockDim.x;
    for (int i = tid; i < Nn * 16; i += stride) {
        uint4 a = ((const uint4*)g_agg)[i];
        float4 val;
        val.x = (a.x == 0u) ? 0.f : (decf(a.x) + b2v.x);
        val.y = (a.y == 0u) ? 0.f : (decf(a.y) + b2v.y);
        val.z = (a.z == 0u) ? 0.f : (decf(a.z) + b2v.z);
        val.w = (a.w == 0u) ? 0.f : (decf(a.w) + b2v.w);
        ((float4*)g_x)[i] = val;
        lsum.x += val.x; lsum.y += val.y; lsum.z += val.z; lsum.w += val.w;
        lsq.x += val.x * val.x; lsq.y += val.y * val.y;
        lsq.z += val.z * val.z; lsq.w += val.w * val.w;
    }
    atomicAdd(&ss[c0 + 0], lsum.x);
    atomicAdd(&ss[c0 + 1], lsum.y);
    atomicAdd(&ss[c0 + 2], lsum.z);
    atomicAdd(&ss[c0 + 3], lsum.w);
    atomicAdd(&sq[c0 + 0], lsq.x);
    atomicAdd(&sq[c0 + 1], lsq.y);
    atomicAdd(&sq[c0 + 2], lsq.z);
    atomicAdd(&sq[c0 + 3], lsq.w);
    __syncthreads();
    if (t < 64) {
        atomicAdd(&g_sum[t], ss[t]);
        atomicAdd(&g_sumsq[t], sq[t]);
    }
}

__global__ void k_decode_out(float* __restrict__ out, const float* __restrict__ b2) {
    int i = blockIdx.x * blockDim.x + threadIdx.x;
    if (i < Nn * 8) {
        unsigned int a = g_agg[i];
        out[i] = (a == 0u) ? 0.f : (decf(a) + b2[i & 7]);
    }
}

// ---------------- launch ----------------
extern "C" void kernel_launch(void* const* d_in, const int* in_sizes, int n_in,
                              void* d_out, int out_size) {
    const float* x  = (const float*)d_in[0];
    const int*   ei = (const int*)d_in[1];
    const int* src = ei;        // edge_index[0]
    const int* dst = ei + Ee;   // edge_index[1]

    const float* W1[4] = {(const float*)d_in[3], (const float*)d_in[9],
                          (const float*)d_in[15], (const float*)d_in[21]};
    const float* B1[4] = {(const float*)d_in[4], (const float*)d_in[10],
                          (const float*)d_in[16], (const float*)d_in[22]};
    const float* W2[4] = {(const float*)d_in[5], (const float*)d_in[11],
                          (const float*)d_in[17], (const float*)d_in[23]};
    const float* B2[4] = {(const float*)d_in[6], (const float*)d_in[12],
                          (const float*)d_in[18], (const float*)d_in[24]};
    const float* G[3]  = {(const float*)d_in[7], (const float*)d_in[13],
                          (const float*)d_in[19]};
    const float* BE[3] = {(const float*)d_in[8], (const float*)d_in[14],
                          (const float*)d_in[20]};

    cudaFuncSetAttribute(k_edge64, cudaFuncAttributeMaxDynamicSharedMemorySize,
                         EDGE_SMEM);
    cudaFuncSetAttribute(k_node_gemm64, cudaFuncAttributeMaxDynamicSharedMemorySize,
                         NG_SMEM);

    // sort edges by dst (counting sort)
    k_zero_hist<<<(Nn + 255) / 256, 256>>>();
    k_hist<<<(Ee / 4 + 255) / 256, 256>>>(dst);
    k_scan<<<1, 1024>>>();
    k_scatter<<<(Ee / 4 + 255) / 256, 256>>>(src, dst);

    // layers 0..2 (din=dout=64); BN of layer l-1 folded into node GEMM of l
    for (int l = 0; l < 3; l++) {
        k_node_gemm64<<<(Nn + 63) / 64, 256, NG_SMEM>>>(
            l == 0 ? x : nullptr, W1[l], B1[l],
            l == 0 ? nullptr : G[l - 1], l == 0 ? nullptr : BE[l - 1]);
        k_edge64<<<Ee / EB, 256, EDGE_SMEM>>>(W2[l]);
        k_decode_stats64<<<592, 256>>>(B2[l]);
    }

    // layer 3 (din=64, dout=8, BN of layer2 folded) -> d_out
    k_node_gemm8<<<(Nn + 15) / 16, 256>>>(W1[3], B1[3], G[2], BE[2]);
    k_edge8<<<(Ee / 8 + 255) / 256, 256>>>(W2[3]);
    k_decode_out<<<(Nn * 8 + 255) / 256, 256>>>((float*)d_out, B2[3]);
}

// round 15
// speedup vs baseline: 1.1948x; 1.0131x over previous
#include <cuda_runtime.h>
#include <math.h>

#define Nn 50000
#define Ee 800000

// ---------------- device scratch (static, no allocation) ----------------
__device__ float        g_x[Nn * 64];     // current node features (pre-BN)
__device__ float        g_u[Nn * 64];     // u = x@A + b1   (dst side)
__device__ float        g_v[Nn * 64];     // v = x@B        (src side)
__device__ __align__(16) unsigned int g_agg[Nn * 64];  // encoded seg-max acc
__device__ int          g_hist[Nn];
__device__ int          g_cur[Nn];
__device__ int          g_sdst[Ee];       // edges sorted by dst
__device__ int          g_ssrc[Ee];
__device__ float        g_sum[64];
__device__ float        g_sumsq[64];
// precomputed tf32 weights (layers 0-2)
__device__ __align__(16) float g_w1t[3 * 64 * 128];  // [l][k][c]: c<64 A=top-bot, c>=64 B=bot
__device__ __align__(16) float g_w2t[3 * 64 * 64];   // [l][k][n]

// ---------------- helpers ----------------
__device__ __forceinline__ unsigned int encf(float f) {
    unsigned int b = __float_as_uint(f);
    return (b & 0x80000000u) ? ~b : (b | 0x80000000u);
}
__device__ __forceinline__ float decf(unsigned int u) {
    return (u & 0x80000000u) ? __uint_as_float(u & 0x7FFFFFFFu)
                             : __uint_as_float(~u);
}
// mish(x) = x * (t^2+2t)/(t^2+2t+2), t=e^x
__device__ __forceinline__ float mishf(float x) {
    float xc = fminf(x, 40.0f);
    float t = __expf(xc);
    float num = fmaf(t, t, 2.0f * t);
    float r = __fdividef(num, num + 2.0f);
    return x * r;
}
__device__ __forceinline__ unsigned int tf32_of(float f) {
    unsigned int r;
    asm("cvt.rna.tf32.f32 %0, %1;" : "=r"(r) : "f"(f));
    return r;
}
__device__ __forceinline__ float tf32f(float f) {
    return __uint_as_float(tf32_of(f));
}
__device__ __forceinline__ void mma_tf32(float c[4],
    unsigned a0, unsigned a1, unsigned a2, unsigned a3,
    unsigned b0, unsigned b1) {
    asm volatile(
        "mma.sync.aligned.m16n8k8.row.col.f32.tf32.tf32.f32 "
        "{%0,%1,%2,%3}, {%4,%5,%6,%7}, {%8,%9}, {%0,%1,%2,%3};"
        : "+f"(c[0]), "+f"(c[1]), "+f"(c[2]), "+f"(c[3])
        : "r"(a0), "r"(a1), "r"(a2), "r"(a3), "r"(b0), "r"(b1));
}

// ---------------- weight prep: convert all layer weights to tf32 ONCE ----------------
__global__ void k_prep_weights(
    const float* __restrict__ w1_0, const float* __restrict__ w2_0,
    const float* __restrict__ w1_1, const float* __restrict__ w2_1,
    const float* __restrict__ w1_2, const float* __restrict__ w2_2) {
    const float* W1[3] = {w1_0, w1_1, w1_2};
    const float* W2[3] = {w2_0, w2_1, w2_2};
    int i = blockIdx.x * blockDim.x + threadIdx.x;
    if (i < 3 * 64 * 128) {               // w1t
        int l = i >> 13, r = i & 8191;
        int k = r >> 7, c = r & 127;
        const float* w1 = W1[l];
        float val;
        if (c < 64) val = w1[k * 64 + c] - w1[(k + 64) * 64 + c];
        else        val = w1[(k + 64) * 64 + (c - 64)];
        g_w1t[i] = tf32f(val);
    } else {
        int j = i - 3 * 64 * 128;
        if (j < 3 * 64 * 64) {
            int l = j >> 12;
            g_w2t[j] = tf32f(W2[l][j & 4095]);
        }
    }
}

// ---------------- sorting (counting sort by dst, once per call) ----------------
__global__ void k_zero_hist() {
    int i = blockIdx.x * blockDim.x + threadIdx.x;
    if (i < Nn) g_hist[i] = 0;
}
__global__ void k_hist(const int* __restrict__ dst) {
    int i = blockIdx.x * blockDim.x + threadIdx.x;
    if (i < Ee / 4) {
        int4 d = ((const int4*)dst)[i];
        atomicAdd(&g_hist[d.x], 1);
        atomicAdd(&g_hist[d.y], 1);
        atomicAdd(&g_hist[d.z], 1);
        atomicAdd(&g_hist[d.w], 1);
    }
}
__global__ void k_scan() {  // 1 block, 1024 threads
    __shared__ int ssum[1024];
    int t = threadIdx.x;
    const int CH = (Nn + 1023) / 1024;
    int base = t * CH;
    int s = 0;
    for (int i = 0; i < CH; i++) {
        int idx = base + i;
        if (idx < Nn) s += g_hist[idx];
    }
    ssum[t] = s;
    __syncthreads();
    for (int off = 1; off < 1024; off <<= 1) {
        int v = (t >= off) ? ssum[t - off] : 0;
        __syncthreads();
        ssum[t] += v;
        __syncthreads();
    }
    int prefix = (t == 0) ? 0 : ssum[t - 1];
    for (int i = 0; i < CH; i++) {
        int idx = base + i;
        if (idx < Nn) {
            int h = g_hist[idx];
            g_cur[idx] = prefix;
            prefix += h;
        }
    }
}
__global__ void k_scatter(const int* __restrict__ src, const int* __restrict__ dst) {
    int i = blockIdx.x * blockDim.x + threadIdx.x;
    if (i < Ee / 4) {
        int4 d = ((const int4*)dst)[i];
        int4 s = ((const int4*)src)[i];
        int p;
        p = atomicAdd(&g_cur[d.x], 1); g_sdst[p] = d.x; g_ssrc[p] = s.x;
        p = atomicAdd(&g_cur[d.y], 1); g_sdst[p] = d.y; g_ssrc[p] = s.y;
        p = atomicAdd(&g_cur[d.z], 1); g_sdst[p] = d.z; g_ssrc[p] = s.z;
        p = atomicAdd(&g_cur[d.w], 1); g_sdst[p] = d.w; g_ssrc[p] = s.w;
    }
}

// ---------------- per-layer kernels ----------------
#define NG_XST 68
#define NG_WST 136
#define NG_OFF_W   (64 * NG_XST)
#define NG_OFF_SC  (NG_OFF_W + 64 * NG_WST)
#define NG_OFF_SH  (NG_OFF_SC + 64)
#define NG_OFF_B1  (NG_OFF_SH + 64)
#define NG_SMEM    ((NG_OFF_B1 + 64) * 4)
__global__ void __launch_bounds__(256) k_node_gemm64(
    const float* __restrict__ x_in,  // null -> read g_x
    const float* __restrict__ w1t,   // precomputed tf32 [64][128]
    const float* __restrict__ b1,
    const float* __restrict__ g, const float* __restrict__ be) {
    extern __shared__ __align__(16) float smem[];
    float* sX = smem;
    float* sW = smem + NG_OFF_W;
    float* s_sc = smem + NG_OFF_SC;
    float* s_sh = smem + NG_OFF_SH;
    float* s_b1 = smem + NG_OFF_B1;
    const float* x = x_in ? x_in : g_x;
    int t = threadIdx.x;
    int n0 = blockIdx.x * 64;
    {
        int stride = gridDim.x * blockDim.x;
        for (int i = blockIdx.x * blockDim.x + t; i < Nn * 64; i += stride)
            g_agg[i] = 0u;
    }
    if (t < 64) {
        float sc = 1.0f, sh = 0.0f;
        if (g) {
            float mu = g_sum[t] * (1.0f / Nn);
            float var = g_sumsq[t] * (1.0f / Nn) - mu * mu;
            sc = rsqrtf(var + 1e-5f) * g[t];
            sh = be[t] - mu * sc;
        }
        s_sc[t] = sc;
        s_sh[t] = sh;
        s_b1[t] = b1[t];
    }
#pragma unroll
    for (int r = 0; r < 8; r++) {
        int idx = r * 256 + t;
        int k = idx >> 5, c4 = (idx & 31) << 2;
        float4 val = *(const float4*)(w1t + k * 128 + c4);
        *(float4*)(sW + k * NG_WST + c4) = val;
    }
    __syncthreads();
#pragma unroll
    for (int r = 0; r < 4; r++) {
        int idx = r * 256 + t;
        int nl = idx >> 4, k4 = (idx & 15) << 2;
        int n = n0 + nl;
        float4 xv = (n < Nn) ? *(const float4*)(x + n * 64 + k4)
                             : make_float4(0.f, 0.f, 0.f, 0.f);
        float4 scv = *(const float4*)(s_sc + k4);
        float4 shv = *(const float4*)(s_sh + k4);
        float* dp = sX + nl * NG_XST + k4;
        dp[0] = tf32f(fmaf(xv.x, scv.x, shv.x));
        dp[1] = tf32f(fmaf(xv.y, scv.y, shv.y));
        dp[2] = tf32f(fmaf(xv.z, scv.z, shv.z));
        dp[3] = tf32f(fmaf(xv.w, scv.w, shv.w));
    }
    __syncthreads();
    int lane = t & 31;
    int gid = lane >> 2, tig = lane & 3;
    int w = t >> 5;
    int r0 = (w & 3) * 16;
    int ch = (w >> 2) * 64;
    float acc[8][4];
#pragma unroll
    for (int i = 0; i < 8; i++)
#pragma unroll
        for (int j = 0; j < 4; j++) acc[i][j] = 0.f;
#pragma unroll
    for (int kt = 0; kt < 8; kt++) {
        int k0 = kt * 8;
        unsigned a0 = __float_as_uint(sX[(r0 + gid)     * NG_XST + k0 + tig]);
        unsigned a1 = __float_as_uint(sX[(r0 + gid + 8) * NG_XST + k0 + tig]);
        unsigned a2 = __float_as_uint(sX[(r0 + gid)     * NG_XST + k0 + tig + 4]);
        unsigned a3 = __float_as_uint(sX[(r0 + gid + 8) * NG_XST + k0 + tig + 4]);
#pragma unroll
        for (int nt = 0; nt < 8; nt++) {
            unsigned b0 = __float_as_uint(sW[(k0 + tig)     * NG_WST + ch + nt * 8 + gid]);
            unsigned b1v = __float_as_uint(sW[(k0 + tig + 4) * NG_WST + ch + nt * 8 + gid]);
            mma_tf32(acc[nt], a0, a1, a2, a3, b0, b1v);
        }
    }
    int nA = n0 + r0 + gid;
    int nB = nA + 8;
#pragma unroll
    for (int nt = 0; nt < 8; nt++) {
        int col = ch + nt * 8 + 2 * tig;
        float add0 = 0.f, add1 = 0.f;
        float* basep;
        int cc;
        if (col < 64) {
            add0 = s_b1[col]; add1 = s_b1[col + 1];
            basep = g_u; cc = col;
        } else {
            basep = g_v; cc = col - 64;
        }
        if (nA < Nn)
            *(float2*)(basep + nA * 64 + cc) =
                make_float2(acc[nt][0] + add0, acc[nt][1] + add1);
        if (nB < Nn)
            *(float2*)(basep + nB * 64 + cc) =
                make_float2(acc[nt][2] + add0, acc[nt][3] + add1);
    }
}

__global__ void __launch_bounds__(256) k_node_gemm8(
    const float* __restrict__ w1, const float* __restrict__ b1,
    const float* __restrict__ g, const float* __restrict__ be) {
    __shared__ float sW[64 * 16];
    __shared__ float s_sc[64], s_sh[64];
    int t = threadIdx.x;
    {
        int stride = gridDim.x * blockDim.x;
        for (int i = blockIdx.x * blockDim.x + t; i < Nn * 8; i += stride)
            g_agg[i] = 0u;
    }
    if (t < 64) {
        float mu = g_sum[t] * (1.0f / Nn);
        float var = g_sumsq[t] * (1.0f / Nn) - mu * mu;
        float sc = rsqrtf(var + 1e-5f) * g[t];
        s_sc[t] = sc;
        s_sh[t] = be[t] - mu * sc;
    }
#pragma unroll
    for (int r = 0; r < 4; r++) {
        int idx = r * 256 + t;
        int k = idx >> 4, cc = idx & 15;
        float wB = w1[(k + 64) * 8 + (cc & 7)];
        sW[idx] = (cc < 8) ? (w1[k * 8 + cc] - wB) : wB;
    }
    __syncthreads();
    int n = blockIdx.x * 16 + (t >> 4);
    int cc = t & 15;
    if (n >= Nn) return;
    const float* xr = g_x + n * 64;
    float acc = 0.f;
#pragma unroll 16
    for (int k = 0; k < 64; k++) {
        float xn = fmaf(__ldg(xr + k), s_sc[k], s_sh[k]);
        acc = fmaf(xn, sW[k * 16 + cc], acc);
    }
    if (cc < 8) g_u[n * 8 + cc] = acc + b1[cc];
    else        g_v[n * 8 + cc - 8] = acc;
}

#define EB    128
#define SA_ST 68
#define SW_ST 72
#define OFF_W    (EB * SA_ST)
#define OFF_SST  (OFF_W + 64 * SW_ST)
#define OFF_NSEG (OFF_SST + 132)
#define EDGE_SMEM ((OFF_NSEG + 4) * 4)
__global__ void __launch_bounds__(256) k_edge64(const float* __restrict__ w2t) {
    extern __shared__ __align__(16) float smem[];
    float* sA = smem;
    float* sW = smem + OFF_W;
    int* sSstart = (int*)(smem + OFF_SST);
    int* sNseg = (int*)(smem + OFF_NSEG);
    int t = threadIdx.x;
    int e0 = blockIdx.x * EB;

    if (blockIdx.x == 0 && t < 128) {
        if (t < 64) g_sum[t] = 0.f;
        else        g_sumsq[t - 64] = 0.f;
    }
    if (t < 32) {
        int base = t * 4;
        int d0 = __ldg(g_sdst + e0 + base);
        int d1 = __ldg(g_sdst + e0 + base + 1);
        int d2 = __ldg(g_sdst + e0 + base + 2);
        int d3 = __ldg(g_sdst + e0 + base + 3);
        int dm1 = (base > 0) ? __ldg(g_sdst + e0 + base - 1) : (d0 ^ 1);
        int h0 = (d0 != dm1), h1 = (d1 != d0), h2 = (d2 != d1), h3 = (d3 != d2);
        int lc0 = h0, lc1 = lc0 + h1, lc2 = lc1 + h2, lc3 = lc2 + h3;
        int c = lc3;
        int v = c;
#pragma unroll
        for (int o = 1; o < 32; o <<= 1) {
            int y = __shfl_up_sync(0xffffffffu, v, o);
            if (t >= o) v += y;
        }
        int off = v - c;
        if (h0) sSstart[off + lc0 - 1] = base;
        if (h1) sSstart[off + lc1 - 1] = base + 1;
        if (h2) sSstart[off + lc2 - 1] = base + 2;
        if (h3) sSstart[off + lc3 - 1] = base + 3;
        if (t == 31) {
            *sNseg = off + c;
            sSstart[off + c] = EB;
        }
    }
#pragma unroll
    for (int r = 0; r < 4; r++) {
        int idx = r * 256 + t;
        int k = idx >> 4, n4 = (idx & 15) << 2;
        float4 wv = *(const float4*)(w2t + k * 64 + n4);
        *(float4*)(sW + k * SW_ST + n4) = wv;
    }
#pragma unroll
    for (int r = 0; r < 8; r++) {
        int idx = r * 256 + t;
        int el = idx >> 4;
        int k4 = (idx & 15) << 2;
        int d = __ldg(g_sdst + e0 + el);
        int s = __ldg(g_ssrc + e0 + el);
        float4 uu = *(const float4*)(g_u + d * 64 + k4);
        float4 vv = *(const float4*)(g_v + s * 64 + k4);
        float4 o;
        o.x = tf32f(mishf(uu.x + vv.x));
        o.y = tf32f(mishf(uu.y + vv.y));
        o.z = tf32f(mishf(uu.z + vv.z));
        o.w = tf32f(mishf(uu.w + vv.w));
        *(float4*)(sA + el * SA_ST + k4) = o;
    }
    __syncthreads();
    int lane = t & 31;
    int gid = lane >> 2, tig = lane & 3;
    int ebase = (t >> 5) * 16;
    float acc[8][4];
#pragma unroll
    for (int i = 0; i < 8; i++)
#pragma unroll
        for (int j = 0; j < 4; j++) acc[i][j] = 0.f;
#pragma unroll
    for (int kt = 0; kt < 8; kt++) {
        int k0 = kt * 8;
        unsigned a0 = __float_as_uint(sA[(ebase + gid)     * SA_ST + k0 + tig]);
        unsigned a1 = __float_as_uint(sA[(ebase + gid + 8) * SA_ST + k0 + tig]);
        unsigned a2 = __float_as_uint(sA[(ebase + gid)     * SA_ST + k0 + tig + 4]);
        unsigned a3 = __float_as_uint(sA[(ebase + gid + 8) * SA_ST + k0 + tig + 4]);
#pragma unroll
        for (int nt = 0; nt < 8; nt++) {
            unsigned b0 = __float_as_uint(sW[(k0 + tig)     * SW_ST + nt * 8 + gid]);
            unsigned b1 = __float_as_uint(sW[(k0 + tig + 4) * SW_ST + nt * 8 + gid]);
            mma_tf32(acc[nt], a0, a1, a2, a3, b0, b1);
        }
    }
    __syncwarp();
#pragma unroll
    for (int nt = 0; nt < 8; nt++) {
        int col = nt * 8 + 2 * tig;
        *(float2*)(sA + (ebase + gid)     * SA_ST + col) = make_float2(acc[nt][0], acc[nt][1]);
        *(float2*)(sA + (ebase + gid + 8) * SA_ST + col) = make_float2(acc[nt][2], acc[nt][3]);
    }
    __syncthreads();
    int S = *sNseg;
    for (int task = t; task < S * 16; task += 256) {
        int s = task >> 4, txx = task & 15;
        int st = sSstart[s], en = sSstart[s + 1];
        const float* aP = sA + st * SA_ST + txx * 4;
        float4 m = *(const float4*)aP;
        for (int i = 1; i < en - st; i++) {
            float4 h = *(const float4*)(aP + i * SA_ST);
            m.x = fmaxf(m.x, h.x);
            m.y = fmaxf(m.y, h.y);
            m.z = fmaxf(m.z, h.z);
            m.w = fmaxf(m.w, h.w);
        }
        int dd = __ldg(g_sdst + e0 + st);
        unsigned int* p = g_agg + dd * 64 + txx * 4;
        unsigned int ex = encf(m.x), ey = encf(m.y), ez = encf(m.z), ew = encf(m.w);
        if (s == 0 || s == S - 1) {
            atomicMax(p + 0, ex);
            atomicMax(p + 1, ey);
            atomicMax(p + 2, ez);
            atomicMax(p + 3, ew);
        } else {
            *(uint4*)p = make_uint4(ex, ey, ez, ew);
        }
    }
}

__global__ void k_edge8(const float* __restrict__ w2) {
    __shared__ float sW[64];
    int t = threadIdx.x;
    if (t < 64) sW[t] = w2[t];
    __syncthreads();
    int base = (blockIdx.x * blockDim.x + t) * 8;
    if (base >= Ee) return;
    int curd = -1;
    float m[8];
#pragma unroll
    for (int j = 0; j < 8; j++) {
        int e = base + j;
        int d = g_sdst[e], s = g_ssrc[e];
        float4 u0 = *(const float4*)(g_u + d * 8);
        float4 u1 = *(const float4*)(g_u + d * 8 + 4);
        float4 v0 = *(const float4*)(g_v + s * 8);
        float4 v1 = *(const float4*)(g_v + s * 8 + 4);
        float pre[8];
        pre[0] = mishf(u0.x + v0.x); pre[1] = mishf(u0.y + v0.y);
        pre[2] = mishf(u0.z + v0.z); pre[3] = mishf(u0.w + v0.w);
        pre[4] = mishf(u1.x + v1.x); pre[5] = mishf(u1.y + v1.y);
        pre[6] = mishf(u1.z + v1.z); pre[7] = mishf(u1.w + v1.w);
        float h[8];
#pragma unroll
        for (int c = 0; c < 8; c++) {
            float a = 0.f;
#pragma unroll
            for (int k = 0; k < 8; k++) a = fmaf(pre[k], sW[k * 8 + c], a);
            h[c] = a;
        }
        if (d != curd) {
            if (curd >= 0) {
#pragma unroll
                for (int c = 0; c < 8; c++)
                    atomicMax(g_agg + curd * 8 + c, encf(m[c]));
            }
            curd = d;
#pragma unroll
            for (int c = 0; c < 8; c++) m[c] = h[c];
        } else {
#pragma unroll
            for (int c = 0; c < 8; c++) m[c] = fmaxf(m[c], h[c]);
        }
    }
#pragma unroll
    for (int c = 0; c < 8; c++) atomicMax(g_agg + curd * 8 + c, encf(m[c]));
}

__global__ void k_decode_stats64(const float* __restrict__ b2) {
    __shared__ float ss[64], sq[64];
    int t = threadIdx.x;
    if (t < 64) { ss[t] = 0.f; sq[t] = 0.f; }
    __syncthreads();
    int tid = blockIdx.x * blockDim.x + t;
    int c0 = (tid * 4) & 63;
    float4 b2v = *(const float4*)(b2 + c0);
    float4 lsum = make_float4(0.f, 0.f, 0.f, 0.f);
    float4 lsq  = make_float4(0.f, 0.f, 0.f, 0.f);
    int stride = gridDim.x * blockDim.x;
    for (int i = tid; i < Nn * 16; i += stride) {
        uint4 a = ((const uint4*)g_agg)[i];
        float4 val;
        val.x = (a.x == 0u) ? 0.f : (decf(a.x) + b2v.x);
        val.y = (a.y == 0u) ? 0.f : (decf(a.y) + b2v.y);
        val.z = (a.z == 0u) ? 0.f : (decf(a.z) + b2v.z);
        val.w = (a.w == 0u) ? 0.f : (decf(a.w) + b2v.w);
        ((float4*)g_x)[i] = val;
        lsum.x += val.x; lsum.y += val.y; lsum.z += val.z; lsum.w += val.w;
        lsq.x += val.x * val.x; lsq.y += val.y * val.y;
        lsq.z += val.z * val.z; lsq.w += val.w * val.w;
    }
    atomicAdd(&ss[c0 + 0], lsum.x);
    atomicAdd(&ss[c0 + 1], lsum.y);
    atomicAdd(&ss[c0 + 2], lsum.z);
    atomicAdd(&ss[c0 + 3], lsum.w);
    atomicAdd(&sq[c0 + 0], lsq.x);
    atomicAdd(&sq[c0 + 1], lsq.y);
    atomicAdd(&sq[c0 + 2], lsq.z);
    atomicAdd(&sq[c0 + 3], lsq.w);
    __syncthreads();
    if (t < 64) {
        atomicAdd(&g_sum[t], ss[t]);
        atomicAdd(&g_sumsq[t], sq[t]);
    }
}

__global__ void k_decode_out(float* __restrict__ out, const float* __restrict__ b2) {
    int i = blockIdx.x * blockDim.x + threadIdx.x;
    if (i < Nn * 8) {
        unsigned int a = g_agg[i];
        out[i] = (a == 0u) ? 0.f : (decf(a) + b2[i & 7]);
    }
}

// ---------------- launch ----------------
extern "C" void kernel_launch(void* const* d_in, const int* in_sizes, int n_in,
                              void* d_out, int out_size) {
    const float* x  = (const float*)d_in[0];
    const int*   ei = (const int*)d_in[1];
    const int* src = ei;
    const int* dst = ei + Ee;

    const float* W1[4] = {(const float*)d_in[3], (const float*)d_in[9],
                          (const float*)d_in[15], (const float*)d_in[21]};
    const float* B1[4] = {(const float*)d_in[4], (const float*)d_in[10],
                          (const float*)d_in[16], (const float*)d_in[22]};
    const float* W2[4] = {(const float*)d_in[5], (const float*)d_in[11],
                          (const float*)d_in[17], (const float*)d_in[23]};
    const float* B2[4] = {(const float*)d_in[6], (const float*)d_in[12],
                          (const float*)d_in[18], (const float*)d_in[24]};
    const float* G[3]  = {(const float*)d_in[7], (const float*)d_in[13],
                          (const float*)d_in[19]};
    const float* BE[3] = {(const float*)d_in[8], (const float*)d_in[14],
                          (const float*)d_in[20]};

    cudaFuncSetAttribute(k_edge64, cudaFuncAttributeMaxDynamicSharedMemorySize,
                         EDGE_SMEM);
    cudaFuncSetAttribute(k_node_gemm64, cudaFuncAttributeMaxDynamicSharedMemorySize,
                         NG_SMEM);

    float* w1t_base = nullptr;
    float* w2t_base = nullptr;
    cudaGetSymbolAddress((void**)&w1t_base, g_w1t);
    cudaGetSymbolAddress((void**)&w2t_base, g_w2t);

    // convert all layer weights to tf32 once
    k_prep_weights<<<(3 * 64 * 128 + 3 * 64 * 64 + 255) / 256, 256>>>(
        W1[0], W2[0], W1[1], W2[1], W1[2], W2[2]);

    // sort edges by dst (counting sort)
    k_zero_hist<<<(Nn + 255) / 256, 256>>>();
    k_hist<<<(Ee / 4 + 255) / 256, 256>>>(dst);
    k_scan<<<1, 1024>>>();
    k_scatter<<<(Ee / 4 + 255) / 256, 256>>>(src, dst);

    // layers 0..2 (din=dout=64); BN of layer l-1 folded into node GEMM of l
    for (int l = 0; l < 3; l++) {
        k_node_gemm64<<<(Nn + 63) / 64, 256, NG_SMEM>>>(
            l == 0 ? x : nullptr, w1t_base + l * 64 * 128, B1[l],
            l == 0 ? nullptr : G[l - 1], l == 0 ? nullptr : BE[l - 1]);
        k_edge64<<<Ee / EB, 256, EDGE_SMEM>>>(w2t_base + l * 64 * 64);
        k_decode_stats64<<<592, 256>>>(B2[l]);
    }

    // layer 3 (din=64, dout=8, BN of layer2 folded) -> d_out
    k_node_gemm8<<<(Nn + 15) / 16, 256>>>(W1[3], B1[3], G[2], BE[2]);
    k_edge8<<<(Ee / 8 + 255) / 256, 256>>>(W2[3]);
    k_decode_out<<<(Nn * 8 + 255) / 256, 256>>>((float*)d_out, B2[3]);
}

// round 16
// speedup vs baseline: 1.3170x; 1.1022x over previous
#include <cuda_runtime.h>
#include <math.h>

#define Nn 50000
#define Ee 800000
#define NBLK 196   // ceil(Nn/256)

// ---------------- device scratch (static, no allocation) ----------------
__device__ float        g_x[Nn * 64];     // current node features (pre-BN)
__device__ float        g_u[Nn * 64];     // u = x@A + b1   (dst side)
__device__ float        g_v[Nn * 64];     // v = x@B        (src side)
__device__ __align__(16) unsigned int g_agg[Nn * 64];  // encoded seg-max acc
__device__ int          g_hist[Nn];
__device__ int          g_cur[Nn];        // within-block exclusive prefix
__device__ int          g_blksum[NBLK + 64];  // block offsets (exclusive)
__device__ int          g_sdst[Ee];       // edges sorted by dst
__device__ int          g_ssrc[Ee];
__device__ float        g_sum[64];
__device__ float        g_sumsq[64];
// precomputed tf32 weights (layers 0-2)
__device__ __align__(16) float g_w1t[3 * 64 * 128];  // [l][k][c]: c<64 A=top-bot, c>=64 B=bot
__device__ __align__(16) float g_w2t[3 * 64 * 64];   // [l][k][n]

// ---------------- helpers ----------------
__device__ __forceinline__ unsigned int encf(float f) {
    unsigned int b = __float_as_uint(f);
    return (b & 0x80000000u) ? ~b : (b | 0x80000000u);
}
__device__ __forceinline__ float decf(unsigned int u) {
    return (u & 0x80000000u) ? __uint_as_float(u & 0x7FFFFFFFu)
                             : __uint_as_float(~u);
}
// mish(x) = x * (t^2+2t)/(t^2+2t+2), t=e^x
__device__ __forceinline__ float mishf(float x) {
    float xc = fminf(x, 40.0f);
    float t = __expf(xc);
    float num = fmaf(t, t, 2.0f * t);
    float r = __fdividef(num, num + 2.0f);
    return x * r;
}
__device__ __forceinline__ unsigned int tf32_of(float f) {
    unsigned int r;
    asm("cvt.rna.tf32.f32 %0, %1;" : "=r"(r) : "f"(f));
    return r;
}
__device__ __forceinline__ float tf32f(float f) {
    return __uint_as_float(tf32_of(f));
}
__device__ __forceinline__ void mma_tf32(float c[4],
    unsigned a0, unsigned a1, unsigned a2, unsigned a3,
    unsigned b0, unsigned b1) {
    asm volatile(
        "mma.sync.aligned.m16n8k8.row.col.f32.tf32.tf32.f32 "
        "{%0,%1,%2,%3}, {%4,%5,%6,%7}, {%8,%9}, {%0,%1,%2,%3};"
        : "+f"(c[0]), "+f"(c[1]), "+f"(c[2]), "+f"(c[3])
        : "r"(a0), "r"(a1), "r"(a2), "r"(a3), "r"(b0), "r"(b1));
}

// ---------------- weight prep: convert all layer weights to tf32 ONCE ----------------
__global__ void k_prep_weights(
    const float* __restrict__ w1_0, const float* __restrict__ w2_0,
    const float* __restrict__ w1_1, const float* __restrict__ w2_1,
    const float* __restrict__ w1_2, const float* __restrict__ w2_2) {
    const float* W1[3] = {w1_0, w1_1, w1_2};
    const float* W2[3] = {w2_0, w2_1, w2_2};
    int i = blockIdx.x * blockDim.x + threadIdx.x;
    if (i < 3 * 64 * 128) {               // w1t
        int l = i >> 13, r = i & 8191;
        int k = r >> 7, c = r & 127;
        const float* w1 = W1[l];
        float val;
        if (c < 64) val = w1[k * 64 + c] - w1[(k + 64) * 64 + c];
        else        val = w1[(k + 64) * 64 + (c - 64)];
        g_w1t[i] = tf32f(val);
    } else {
        int j = i - 3 * 64 * 128;
        if (j < 3 * 64 * 64) {
            int l = j >> 12;
            g_w2t[j] = tf32f(W2[l][j & 4095]);
        }
    }
}

// ---------------- sorting (counting sort by dst, once per call) ----------------
__global__ void k_zero_hist() {
    int i = blockIdx.x * blockDim.x + threadIdx.x;
    if (i < Nn) g_hist[i] = 0;
}
__global__ void k_hist(const int* __restrict__ dst) {
    int i = blockIdx.x * blockDim.x + threadIdx.x;
    if (i < Ee / 4) {
        int4 d = ((const int4*)dst)[i];
        atomicAdd(&g_hist[d.x], 1);
        atomicAdd(&g_hist[d.y], 1);
        atomicAdd(&g_hist[d.z], 1);
        atomicAdd(&g_hist[d.w], 1);
    }
}
// parallel scan stage 1: per-block exclusive prefix + block total
__global__ void k_scan_local() {
    __shared__ int sv[256];
    int t = threadIdx.x;
    int i = blockIdx.x * 256 + t;
    int h = (i < Nn) ? g_hist[i] : 0;
    sv[t] = h;
    __syncthreads();
#pragma unroll
    for (int off = 1; off < 256; off <<= 1) {
        int v = (t >= off) ? sv[t - off] : 0;
        __syncthreads();
        sv[t] += v;
        __syncthreads();
    }
    if (i < Nn) g_cur[i] = sv[t] - h;          // within-block exclusive
    if (t == 255) g_blksum[blockIdx.x] = sv[255];
}
// parallel scan stage 2: exclusive scan of block totals (1 block)
__global__ void k_scan_block() {
    __shared__ int sv[256];
    int t = threadIdx.x;
    int v = (t < NBLK) ? g_blksum[t] : 0;
    sv[t] = v;
    __syncthreads();
#pragma unroll
    for (int off = 1; off < 256; off <<= 1) {
        int y = (t >= off) ? sv[t - off] : 0;
        __syncthreads();
        sv[t] += y;
        __syncthreads();
    }
    if (t < NBLK) g_blksum[t] = sv[t] - v;     // exclusive block offset
}
// scatter: global position = blk offset + local prefix counter
__global__ void k_scatter(const int* __restrict__ src, const int* __restrict__ dst) {
    int i = blockIdx.x * blockDim.x + threadIdx.x;
    if (i < Ee / 4) {
        int4 d = ((const int4*)dst)[i];
        int4 s = ((const int4*)src)[i];
        int p;
        p = atomicAdd(&g_cur[d.x], 1) + __ldg(g_blksum + (d.x >> 8));
        g_sdst[p] = d.x; g_ssrc[p] = s.x;
        p = atomicAdd(&g_cur[d.y], 1) + __ldg(g_blksum + (d.y >> 8));
        g_sdst[p] = d.y; g_ssrc[p] = s.y;
        p = atomicAdd(&g_cur[d.z], 1) + __ldg(g_blksum + (d.z >> 8));
        g_sdst[p] = d.z; g_ssrc[p] = s.z;
        p = atomicAdd(&g_cur[d.w], 1) + __ldg(g_blksum + (d.w >> 8));
        g_sdst[p] = d.w; g_ssrc[p] = s.w;
    }
}

// ---------------- per-layer kernels ----------------
#define NG_XST 68
#define NG_WST 136
#define NG_OFF_W   (64 * NG_XST)
#define NG_OFF_SC  (NG_OFF_W + 64 * NG_WST)
#define NG_OFF_SH  (NG_OFF_SC + 64)
#define NG_OFF_B1  (NG_OFF_SH + 64)
#define NG_SMEM    ((NG_OFF_B1 + 64) * 4)
__global__ void __launch_bounds__(256) k_node_gemm64(
    const float* __restrict__ x_in,  // null -> read g_x
    const float* __restrict__ w1t,   // precomputed tf32 [64][128]
    const float* __restrict__ b1,
    const float* __restrict__ g, const float* __restrict__ be) {
    extern __shared__ __align__(16) float smem[];
    float* sX = smem;
    float* sW = smem + NG_OFF_W;
    float* s_sc = smem + NG_OFF_SC;
    float* s_sh = smem + NG_OFF_SH;
    float* s_b1 = smem + NG_OFF_B1;
    const float* x = x_in ? x_in : g_x;
    int t = threadIdx.x;
    int n0 = blockIdx.x * 64;
    {
        int stride = gridDim.x * blockDim.x;
        for (int i = blockIdx.x * blockDim.x + t; i < Nn * 64; i += stride)
            g_agg[i] = 0u;
    }
    if (t < 64) {
        float sc = 1.0f, sh = 0.0f;
        if (g) {
            float mu = g_sum[t] * (1.0f / Nn);
            float var = g_sumsq[t] * (1.0f / Nn) - mu * mu;
            sc = rsqrtf(var + 1e-5f) * g[t];
            sh = be[t] - mu * sc;
        }
        s_sc[t] = sc;
        s_sh[t] = sh;
        s_b1[t] = b1[t];
    }
#pragma unroll
    for (int r = 0; r < 8; r++) {
        int idx = r * 256 + t;
        int k = idx >> 5, c4 = (idx & 31) << 2;
        float4 val = *(const float4*)(w1t + k * 128 + c4);
        *(float4*)(sW + k * NG_WST + c4) = val;
    }
    __syncthreads();
#pragma unroll
    for (int r = 0; r < 4; r++) {
        int idx = r * 256 + t;
        int nl = idx >> 4, k4 = (idx & 15) << 2;
        int n = n0 + nl;
        float4 xv = (n < Nn) ? *(const float4*)(x + n * 64 + k4)
                             : make_float4(0.f, 0.f, 0.f, 0.f);
        float4 scv = *(const float4*)(s_sc + k4);
        float4 shv = *(const float4*)(s_sh + k4);
        float* dp = sX + nl * NG_XST + k4;
        dp[0] = tf32f(fmaf(xv.x, scv.x, shv.x));
        dp[1] = tf32f(fmaf(xv.y, scv.y, shv.y));
        dp[2] = tf32f(fmaf(xv.z, scv.z, shv.z));
        dp[3] = tf32f(fmaf(xv.w, scv.w, shv.w));
    }
    __syncthreads();
    int lane = t & 31;
    int gid = lane >> 2, tig = lane & 3;
    int w = t >> 5;
    int r0 = (w & 3) * 16;
    int ch = (w >> 2) * 64;
    float acc[8][4];
#pragma unroll
    for (int i = 0; i < 8; i++)
#pragma unroll
        for (int j = 0; j < 4; j++) acc[i][j] = 0.f;
#pragma unroll
    for (int kt = 0; kt < 8; kt++) {
        int k0 = kt * 8;
        unsigned a0 = __float_as_uint(sX[(r0 + gid)     * NG_XST + k0 + tig]);
        unsigned a1 = __float_as_uint(sX[(r0 + gid + 8) * NG_XST + k0 + tig]);
        unsigned a2 = __float_as_uint(sX[(r0 + gid)     * NG_XST + k0 + tig + 4]);
        unsigned a3 = __float_as_uint(sX[(r0 + gid + 8) * NG_XST + k0 + tig + 4]);
#pragma unroll
        for (int nt = 0; nt < 8; nt++) {
            unsigned b0 = __float_as_uint(sW[(k0 + tig)     * NG_WST + ch + nt * 8 + gid]);
            unsigned b1v = __float_as_uint(sW[(k0 + tig + 4) * NG_WST + ch + nt * 8 + gid]);
            mma_tf32(acc[nt], a0, a1, a2, a3, b0, b1v);
        }
    }
    int nA = n0 + r0 + gid;
    int nB = nA + 8;
#pragma unroll
    for (int nt = 0; nt < 8; nt++) {
        int col = ch + nt * 8 + 2 * tig;
        float add0 = 0.f, add1 = 0.f;
        float* basep;
        int cc;
        if (col < 64) {
            add0 = s_b1[col]; add1 = s_b1[col + 1];
            basep = g_u; cc = col;
        } else {
            basep = g_v; cc = col - 64;
        }
        if (nA < Nn)
            *(float2*)(basep + nA * 64 + cc) =
                make_float2(acc[nt][0] + add0, acc[nt][1] + add1);
        if (nB < Nn)
            *(float2*)(basep + nB * 64 + cc) =
                make_float2(acc[nt][2] + add0, acc[nt][3] + add1);
    }
}

__global__ void __launch_bounds__(256) k_node_gemm8(
    const float* __restrict__ w1, const float* __restrict__ b1,
    const float* __restrict__ g, const float* __restrict__ be) {
    __shared__ float sW[64 * 16];
    __shared__ float s_sc[64], s_sh[64];
    int t = threadIdx.x;
    {
        int stride = gridDim.x * blockDim.x;
        for (int i = blockIdx.x * blockDim.x + t; i < Nn * 8; i += stride)
            g_agg[i] = 0u;
    }
    if (t < 64) {
        float mu = g_sum[t] * (1.0f / Nn);
        float var = g_sumsq[t] * (1.0f / Nn) - mu * mu;
        float sc = rsqrtf(var + 1e-5f) * g[t];
        s_sc[t] = sc;
        s_sh[t] = be[t] - mu * sc;
    }
#pragma unroll
    for (int r = 0; r < 4; r++) {
        int idx = r * 256 + t;
        int k = idx >> 4, cc = idx & 15;
        float wB = w1[(k + 64) * 8 + (cc & 7)];
        sW[idx] = (cc < 8) ? (w1[k * 8 + cc] - wB) : wB;
    }
    __syncthreads();
    int n = blockIdx.x * 16 + (t >> 4);
    int cc = t & 15;
    if (n >= Nn) return;
    const float* xr = g_x + n * 64;
    float acc = 0.f;
#pragma unroll 16
    for (int k = 0; k < 64; k++) {
        float xn = fmaf(__ldg(xr + k), s_sc[k], s_sh[k]);
        acc = fmaf(xn, sW[k * 16 + cc], acc);
    }
    if (cc < 8) g_u[n * 8 + cc] = acc + b1[cc];
    else        g_v[n * 8 + cc - 8] = acc;
}

#define EB    128
#define SA_ST 68
#define SW_ST 72
#define OFF_W    (EB * SA_ST)
#define OFF_SST  (OFF_W + 64 * SW_ST)
#define OFF_NSEG (OFF_SST + 132)
#define EDGE_SMEM ((OFF_NSEG + 4) * 4)
__global__ void __launch_bounds__(256) k_edge64(const float* __restrict__ w2t) {
    extern __shared__ __align__(16) float smem[];
    float* sA = smem;
    float* sW = smem + OFF_W;
    int* sSstart = (int*)(smem + OFF_SST);
    int* sNseg = (int*)(smem + OFF_NSEG);
    int t = threadIdx.x;
    int e0 = blockIdx.x * EB;

    if (blockIdx.x == 0 && t < 128) {
        if (t < 64) g_sum[t] = 0.f;
        else        g_sumsq[t - 64] = 0.f;
    }
    if (t < 32) {
        int base = t * 4;
        int d0 = __ldg(g_sdst + e0 + base);
        int d1 = __ldg(g_sdst + e0 + base + 1);
        int d2 = __ldg(g_sdst + e0 + base + 2);
        int d3 = __ldg(g_sdst + e0 + base + 3);
        int dm1 = (base > 0) ? __ldg(g_sdst + e0 + base - 1) : (d0 ^ 1);
        int h0 = (d0 != dm1), h1 = (d1 != d0), h2 = (d2 != d1), h3 = (d3 != d2);
        int lc0 = h0, lc1 = lc0 + h1, lc2 = lc1 + h2, lc3 = lc2 + h3;
        int c = lc3;
        int v = c;
#pragma unroll
        for (int o = 1; o < 32; o <<= 1) {
            int y = __shfl_up_sync(0xffffffffu, v, o);
            if (t >= o) v += y;
        }
        int off = v - c;
        if (h0) sSstart[off + lc0 - 1] = base;
        if (h1) sSstart[off + lc1 - 1] = base + 1;
        if (h2) sSstart[off + lc2 - 1] = base + 2;
        if (h3) sSstart[off + lc3 - 1] = base + 3;
        if (t == 31) {
            *sNseg = off + c;
            sSstart[off + c] = EB;
        }
    }
#pragma unroll
    for (int r = 0; r < 4; r++) {
        int idx = r * 256 + t;
        int k = idx >> 4, n4 = (idx & 15) << 2;
        float4 wv = *(const float4*)(w2t + k * 64 + n4);
        *(float4*)(sW + k * SW_ST + n4) = wv;
    }
#pragma unroll
    for (int r = 0; r < 8; r++) {
        int idx = r * 256 + t;
        int el = idx >> 4;
        int k4 = (idx & 15) << 2;
        int d = __ldg(g_sdst + e0 + el);
        int s = __ldg(g_ssrc + e0 + el);
        float4 uu = *(const float4*)(g_u + d * 64 + k4);
        float4 vv = *(const float4*)(g_v + s * 64 + k4);
        float4 o;
        o.x = tf32f(mishf(uu.x + vv.x));
        o.y = tf32f(mishf(uu.y + vv.y));
        o.z = tf32f(mishf(uu.z + vv.z));
        o.w = tf32f(mishf(uu.w + vv.w));
        *(float4*)(sA + el * SA_ST + k4) = o;
    }
    __syncthreads();
    int lane = t & 31;
    int gid = lane >> 2, tig = lane & 3;
    int ebase = (t >> 5) * 16;
    float acc[8][4];
#pragma unroll
    for (int i = 0; i < 8; i++)
#pragma unroll
        for (int j = 0; j < 4; j++) acc[i][j] = 0.f;
#pragma unroll
    for (int kt = 0; kt < 8; kt++) {
        int k0 = kt * 8;
        unsigned a0 = __float_as_uint(sA[(ebase + gid)     * SA_ST + k0 + tig]);
        unsigned a1 = __float_as_uint(sA[(ebase + gid + 8) * SA_ST + k0 + tig]);
        unsigned a2 = __float_as_uint(sA[(ebase + gid)     * SA_ST + k0 + tig + 4]);
        unsigned a3 = __float_as_uint(sA[(ebase + gid + 8) * SA_ST + k0 + tig + 4]);
#pragma unroll
        for (int nt = 0; nt < 8; nt++) {
            unsigned b0 = __float_as_uint(sW[(k0 + tig)     * SW_ST + nt * 8 + gid]);
            unsigned b1 = __float_as_uint(sW[(k0 + tig + 4) * SW_ST + nt * 8 + gid]);
            mma_tf32(acc[nt], a0, a1, a2, a3, b0, b1);
        }
    }
    __syncwarp();
#pragma unroll
    for (int nt = 0; nt < 8; nt++) {
        int col = nt * 8 + 2 * tig;
        *(float2*)(sA + (ebase + gid)     * SA_ST + col) = make_float2(acc[nt][0], acc[nt][1]);
        *(float2*)(sA + (ebase + gid + 8) * SA_ST + col) = make_float2(acc[nt][2], acc[nt][3]);
    }
    __syncthreads();
    int S = *sNseg;
    for (int task = t; task < S * 16; task += 256) {
        int s = task >> 4, txx = task & 15;
        int st = sSstart[s], en = sSstart[s + 1];
        const float* aP = sA + st * SA_ST + txx * 4;
        float4 m = *(const float4*)aP;
        for (int i = 1; i < en - st; i++) {
            float4 h = *(const float4*)(aP + i * SA_ST);
            m.x = fmaxf(m.x, h.x);
            m.y = fmaxf(m.y, h.y);
            m.z = fmaxf(m.z, h.z);
            m.w = fmaxf(m.w, h.w);
        }
        int dd = __ldg(g_sdst + e0 + st);
        unsigned int* p = g_agg + dd * 64 + txx * 4;
        unsigned int ex = encf(m.x), ey = encf(m.y), ez = encf(m.z), ew = encf(m.w);
        if (s == 0 || s == S - 1) {
            atomicMax(p + 0, ex);
            atomicMax(p + 1, ey);
            atomicMax(p + 2, ez);
            atomicMax(p + 3, ew);
        } else {
            *(uint4*)p = make_uint4(ex, ey, ez, ew);
        }
    }
}

__global__ void k_edge8(const float* __restrict__ w2) {
    __shared__ float sW[64];
    int t = threadIdx.x;
    if (t < 64) sW[t] = w2[t];
    __syncthreads();
    int base = (blockIdx.x * blockDim.x + t) * 8;
    if (base >= Ee) return;
    int curd = -1;
    float m[8];
#pragma unroll
    for (int j = 0; j < 8; j++) {
        int e = base + j;
        int d = g_sdst[e], s = g_ssrc[e];
        float4 u0 = *(const float4*)(g_u + d * 8);
        float4 u1 = *(const float4*)(g_u + d * 8 + 4);
        float4 v0 = *(const float4*)(g_v + s * 8);
        float4 v1 = *(const float4*)(g_v + s * 8 + 4);
        float pre[8];
        pre[0] = mishf(u0.x + v0.x); pre[1] = mishf(u0.y + v0.y);
        pre[2] = mishf(u0.z + v0.z); pre[3] = mishf(u0.w + v0.w);
        pre[4] = mishf(u1.x + v1.x); pre[5] = mishf(u1.y + v1.y);
        pre[6] = mishf(u1.z + v1.z); pre[7] = mishf(u1.w + v1.w);
        float h[8];
#pragma unroll
        for (int c = 0; c < 8; c++) {
            float a = 0.f;
#pragma unroll
            for (int k = 0; k < 8; k++) a = fmaf(pre[k], sW[k * 8 + c], a);
            h[c] = a;
        }
        if (d != curd) {
            if (curd >= 0) {
#pragma unroll
                for (int c = 0; c < 8; c++)
                    atomicMax(g_agg + curd * 8 + c, encf(m[c]));
            }
            curd = d;
#pragma unroll
            for (int c = 0; c < 8; c++) m[c] = h[c];
        } else {
#pragma unroll
            for (int c = 0; c < 8; c++) m[c] = fmaxf(m[c], h[c]);
        }
    }
#pragma unroll
    for (int c = 0; c < 8; c++) atomicMax(g_agg + curd * 8 + c, encf(m[c]));
}

__global__ void k_decode_stats64(const float* __restrict__ b2) {
    __shared__ float ss[64], sq[64];
    int t = threadIdx.x;
    if (t < 64) { ss[t] = 0.f; sq[t] = 0.f; }
    __syncthreads();
    int tid = blockIdx.x * blockDim.x + t;
    int c0 = (tid * 4) & 63;
    float4 b2v = *(const float4*)(b2 + c0);
    float4 lsum = make_float4(0.f, 0.f, 0.f, 0.f);
    float4 lsq  = make_float4(0.f, 0.f, 0.f, 0.f);
    int stride = gridDim.x * blockDim.x;
    for (int i = tid; i < Nn * 16; i += stride) {
        uint4 a = ((const uint4*)g_agg)[i];
        float4 val;
        val.x = (a.x == 0u) ? 0.f : (decf(a.x) + b2v.x);
        val.y = (a.y == 0u) ? 0.f : (decf(a.y) + b2v.y);
        val.z = (a.z == 0u) ? 0.f : (decf(a.z) + b2v.z);
        val.w = (a.w == 0u) ? 0.f : (decf(a.w) + b2v.w);
        ((float4*)g_x)[i] = val;
        lsum.x += val.x; lsum.y += val.y; lsum.z += val.z; lsum.w += val.w;
        lsq.x += val.x * val.x; lsq.y += val.y * val.y;
        lsq.z += val.z * val.z; lsq.w += val.w * val.w;
    }
    atomicAdd(&ss[c0 + 0], lsum.x);
    atomicAdd(&ss[c0 + 1], lsum.y);
    atomicAdd(&ss[c0 + 2], lsum.z);
    atomicAdd(&ss[c0 + 3], lsum.w);
    atomicAdd(&sq[c0 + 0], lsq.x);
    atomicAdd(&sq[c0 + 1], lsq.y);
    atomicAdd(&sq[c0 + 2], lsq.z);
    atomicAdd(&sq[c0 + 3], lsq.w);
    __syncthreads();
    if (t < 64) {
        atomicAdd(&g_sum[t], ss[t]);
        atomicAdd(&g_sumsq[t], sq[t]);
    }
}

__global__ void k_decode_out(float* __restrict__ out, const float* __restrict__ b2) {
    int i = blockIdx.x * blockDim.x + threadIdx.x;
    if (i < Nn * 8) {
        unsigned int a = g_agg[i];
        out[i] = (a == 0u) ? 0.f : (decf(a) + b2[i & 7]);
    }
}

// ---------------- launch ----------------
extern "C" void kernel_launch(void* const* d_in, const int* in_sizes, int n_in,
                              void* d_out, int out_size) {
    const float* x  = (const float*)d_in[0];
    const int*   ei = (const int*)d_in[1];
    const int* src = ei;
    const int* dst = ei + Ee;

    const float* W1[4] = {(const float*)d_in[3], (const float*)d_in[9],
                          (const float*)d_in[15], (const float*)d_in[21]};
    const float* B1[4] = {(const float*)d_in[4], (const float*)d_in[10],
                          (const float*)d_in[16], (const float*)d_in[22]};
    const float* W2[4] = {(const float*)d_in[5], (const float*)d_in[11],
                          (const float*)d_in[17], (const float*)d_in[23]};
    const float* B2[4] = {(const float*)d_in[6], (const float*)d_in[12],
                          (const float*)d_in[18], (const float*)d_in[24]};
    const float* G[3]  = {(const float*)d_in[7], (const float*)d_in[13],
                          (const float*)d_in[19]};
    const float* BE[3] = {(const float*)d_in[8], (const float*)d_in[14],
                          (const float*)d_in[20]};

    cudaFuncSetAttribute(k_edge64, cudaFuncAttributeMaxDynamicSharedMemorySize,
                         EDGE_SMEM);
    cudaFuncSetAttribute(k_node_gemm64, cudaFuncAttributeMaxDynamicSharedMemorySize,
                         NG_SMEM);

    float* w1t_base = nullptr;
    float* w2t_base = nullptr;
    cudaGetSymbolAddress((void**)&w1t_base, g_w1t);
    cudaGetSymbolAddress((void**)&w2t_base, g_w2t);

    // convert all layer weights to tf32 once
    k_prep_weights<<<(3 * 64 * 128 + 3 * 64 * 64 + 255) / 256, 256>>>(
        W1[0], W2[0], W1[1], W2[1], W1[2], W2[2]);

    // sort edges by dst (counting sort, parallel two-level scan)
    k_zero_hist<<<(Nn + 255) / 256, 256>>>();
    k_hist<<<(Ee / 4 + 255) / 256, 256>>>(dst);
    k_scan_local<<<NBLK, 256>>>();
    k_scan_block<<<1, 256>>>();
    k_scatter<<<(Ee / 4 + 255) / 256, 256>>>(src, dst);

    // layers 0..2 (din=dout=64); BN of layer l-1 folded into node GEMM of l
    for (int l = 0; l < 3; l++) {
        k_node_gemm64<<<(Nn + 63) / 64, 256, NG_SMEM>>>(
            l == 0 ? x : nullptr, w1t_base + l * 64 * 128, B1[l],
            l == 0 ? nullptr : G[l - 1], l == 0 ? nullptr : BE[l - 1]);
        k_edge64<<<Ee / EB, 256, EDGE_SMEM>>>(w2t_base + l * 64 * 64);
        k_decode_stats64<<<592, 256>>>(B2[l]);
    }

    // layer 3 (din=64, dout=8, BN of layer2 folded) -> d_out
    k_node_gemm8<<<(Nn + 15) / 16, 256>>>(W1[3], B1[3], G[2], BE[2]);
    k_edge8<<<(Ee / 8 + 255) / 256, 256>>>(W2[3]);
    k_decode_out<<<(Nn * 8 + 255) / 256, 256>>>((float*)d_out, B2[3]);
}

// round 17
// speedup vs baseline: 1.3241x; 1.0054x over previous
#include <cuda_runtime.h>
#include <math.h>

#define Nn 50000
#define Ee 800000
#define NBLK 196   // ceil(Nn/256)

// ---------------- device scratch (static, no allocation) ----------------
__device__ float        g_x[Nn * 64];     // current node features (pre-BN)
__device__ float        g_u[Nn * 64];     // u = x@A + b1   (dst side)
__device__ float        g_v[Nn * 64];     // v = x@B        (src side)
__device__ __align__(16) unsigned int g_agg[Nn * 64];  // encoded seg-max acc
__device__ int          g_hist[Nn];       // zero at entry (invariant)
__device__ int          g_cur[Nn];        // within-block prefix counters
__device__ int          g_blksum[NBLK + 64];  // block offsets (exclusive)
__device__ int          g_sdst[Ee];       // edges sorted by dst
__device__ int          g_ssrc[Ee];
__device__ float        g_sum[64];
__device__ float        g_sumsq[64];
// precomputed tf32 weights (layers 0-2)
__device__ __align__(16) float g_w1t[3 * 64 * 128];  // [l][k][c]: c<64 A=top-bot, c>=64 B=bot
__device__ __align__(16) float g_w2t[3 * 64 * 64];   // [l][k][n]

// ---------------- helpers ----------------
__device__ __forceinline__ unsigned int encf(float f) {
    unsigned int b = __float_as_uint(f);
    return (b & 0x80000000u) ? ~b : (b | 0x80000000u);
}
__device__ __forceinline__ float decf(unsigned int u) {
    return (u & 0x80000000u) ? __uint_as_float(u & 0x7FFFFFFFu)
                             : __uint_as_float(~u);
}
// mish(x) = x * (t^2+2t)/(t^2+2t+2), t=e^x
__device__ __forceinline__ float mishf(float x) {
    float xc = fminf(x, 40.0f);
    float t = __expf(xc);
    float num = fmaf(t, t, 2.0f * t);
    float r = __fdividef(num, num + 2.0f);
    return x * r;
}
__device__ __forceinline__ unsigned int tf32_of(float f) {
    unsigned int r;
    asm("cvt.rna.tf32.f32 %0, %1;" : "=r"(r) : "f"(f));
    return r;
}
__device__ __forceinline__ float tf32f(float f) {
    return __uint_as_float(tf32_of(f));
}
__device__ __forceinline__ void mma_tf32(float c[4],
    unsigned a0, unsigned a1, unsigned a2, unsigned a3,
    unsigned b0, unsigned b1) {
    asm volatile(
        "mma.sync.aligned.m16n8k8.row.col.f32.tf32.tf32.f32 "
        "{%0,%1,%2,%3}, {%4,%5,%6,%7}, {%8,%9}, {%0,%1,%2,%3};"
        : "+f"(c[0]), "+f"(c[1]), "+f"(c[2]), "+f"(c[3])
        : "r"(a0), "r"(a1), "r"(a2), "r"(a3), "r"(b0), "r"(b1));
}

// ---------------- fused hist + weight prep ----------------
// Histogram of dst (4 edges/thread, int4) PLUS one-time tf32 weight
// conversion riding along in the low-index threads (independent work).
#define PREPN (3 * 64 * 128 + 3 * 64 * 64)   // 36864
__global__ void k_hist_prep(const int* __restrict__ dst,
    const float* __restrict__ w1_0, const float* __restrict__ w2_0,
    const float* __restrict__ w1_1, const float* __restrict__ w2_1,
    const float* __restrict__ w1_2, const float* __restrict__ w2_2) {
    int i = blockIdx.x * blockDim.x + threadIdx.x;
    if (i < PREPN) {
        if (i < 3 * 64 * 128) {            // w1t
            int l = i >> 13, r = i & 8191;
            int k = r >> 7, c = r & 127;
            const float* w1 = (l == 0) ? w1_0 : (l == 1) ? w1_1 : w1_2;
            float val;
            if (c < 64) val = w1[k * 64 + c] - w1[(k + 64) * 64 + c];
            else        val = w1[(k + 64) * 64 + (c - 64)];
            g_w1t[i] = tf32f(val);
        } else {
            int j = i - 3 * 64 * 128;
            int l = j >> 12;
            const float* w2 = (l == 0) ? w2_0 : (l == 1) ? w2_1 : w2_2;
            g_w2t[j] = tf32f(w2[j & 4095]);
        }
    }
    if (i < Ee / 4) {
        int4 d = ((const int4*)dst)[i];
        atomicAdd(&g_hist[d.x], 1);
        atomicAdd(&g_hist[d.y], 1);
        atomicAdd(&g_hist[d.z], 1);
        atomicAdd(&g_hist[d.w], 1);
    }
}
// parallel scan stage 1: per-block exclusive prefix + block total.
// Also re-zeroes g_hist (entry invariant for the next call).
__global__ void k_scan_local() {
    __shared__ int sv[256];
    int t = threadIdx.x;
    int i = blockIdx.x * 256 + t;
    int h = 0;
    if (i < Nn) {
        h = g_hist[i];
        g_hist[i] = 0;                     // restore zero for next call
    }
    sv[t] = h;
    __syncthreads();
#pragma unroll
    for (int off = 1; off < 256; off <<= 1) {
        int v = (t >= off) ? sv[t - off] : 0;
        __syncthreads();
        sv[t] += v;
        __syncthreads();
    }
    if (i < Nn) g_cur[i] = sv[t] - h;          // within-block exclusive
    if (t == 255) g_blksum[blockIdx.x] = sv[255];
}
// parallel scan stage 2: exclusive scan of block totals (1 block)
__global__ void k_scan_block() {
    __shared__ int sv[256];
    int t = threadIdx.x;
    int v = (t < NBLK) ? g_blksum[t] : 0;
    sv[t] = v;
    __syncthreads();
#pragma unroll
    for (int off = 1; off < 256; off <<= 1) {
        int y = (t >= off) ? sv[t - off] : 0;
        __syncthreads();
        sv[t] += y;
        __syncthreads();
    }
    if (t < NBLK) g_blksum[t] = sv[t] - v;     // exclusive block offset
}
// scatter: global position = blk offset + local prefix counter
__global__ void k_scatter(const int* __restrict__ src, const int* __restrict__ dst) {
    int i = blockIdx.x * blockDim.x + threadIdx.x;
    if (i < Ee / 4) {
        int4 d = ((const int4*)dst)[i];
        int4 s = ((const int4*)src)[i];
        int p;
        p = atomicAdd(&g_cur[d.x], 1) + __ldg(g_blksum + (d.x >> 8));
        g_sdst[p] = d.x; g_ssrc[p] = s.x;
        p = atomicAdd(&g_cur[d.y], 1) + __ldg(g_blksum + (d.y >> 8));
        g_sdst[p] = d.y; g_ssrc[p] = s.y;
        p = atomicAdd(&g_cur[d.z], 1) + __ldg(g_blksum + (d.z >> 8));
        g_sdst[p] = d.z; g_ssrc[p] = s.z;
        p = atomicAdd(&g_cur[d.w], 1) + __ldg(g_blksum + (d.w >> 8));
        g_sdst[p] = d.w; g_ssrc[p] = s.w;
    }
}

// ---------------- per-layer kernels ----------------
#define NG_XST 68
#define NG_WST 136
#define NG_OFF_W   (64 * NG_XST)
#define NG_OFF_SC  (NG_OFF_W + 64 * NG_WST)
#define NG_OFF_SH  (NG_OFF_SC + 64)
#define NG_OFF_B1  (NG_OFF_SH + 64)
#define NG_SMEM    ((NG_OFF_B1 + 64) * 4)
__global__ void __launch_bounds__(256) k_node_gemm64(
    const float* __restrict__ x_in,  // null -> read g_x
    const float* __restrict__ w1t,   // precomputed tf32 [64][128]
    const float* __restrict__ b1,
    const float* __restrict__ g, const float* __restrict__ be) {
    extern __shared__ __align__(16) float smem[];
    float* sX = smem;
    float* sW = smem + NG_OFF_W;
    float* s_sc = smem + NG_OFF_SC;
    float* s_sh = smem + NG_OFF_SH;
    float* s_b1 = smem + NG_OFF_B1;
    const float* x = x_in ? x_in : g_x;
    int t = threadIdx.x;
    int n0 = blockIdx.x * 64;
    {
        int stride = gridDim.x * blockDim.x;
        for (int i = blockIdx.x * blockDim.x + t; i < Nn * 64; i += stride)
            g_agg[i] = 0u;
    }
    if (t < 64) {
        float sc = 1.0f, sh = 0.0f;
        if (g) {
            float mu = g_sum[t] * (1.0f / Nn);
            float var = g_sumsq[t] * (1.0f / Nn) - mu * mu;
            sc = rsqrtf(var + 1e-5f) * g[t];
            sh = be[t] - mu * sc;
        }
        s_sc[t] = sc;
        s_sh[t] = sh;
        s_b1[t] = b1[t];
    }
#pragma unroll
    for (int r = 0; r < 8; r++) {
        int idx = r * 256 + t;
        int k = idx >> 5, c4 = (idx & 31) << 2;
        float4 val = *(const float4*)(w1t + k * 128 + c4);
        *(float4*)(sW + k * NG_WST + c4) = val;
    }
    __syncthreads();
#pragma unroll
    for (int r = 0; r < 4; r++) {
        int idx = r * 256 + t;
        int nl = idx >> 4, k4 = (idx & 15) << 2;
        int n = n0 + nl;
        float4 xv = (n < Nn) ? *(const float4*)(x + n * 64 + k4)
                             : make_float4(0.f, 0.f, 0.f, 0.f);
        float4 scv = *(const float4*)(s_sc + k4);
        float4 shv = *(const float4*)(s_sh + k4);
        float* dp = sX + nl * NG_XST + k4;
        dp[0] = tf32f(fmaf(xv.x, scv.x, shv.x));
        dp[1] = tf32f(fmaf(xv.y, scv.y, shv.y));
        dp[2] = tf32f(fmaf(xv.z, scv.z, shv.z));
        dp[3] = tf32f(fmaf(xv.w, scv.w, shv.w));
    }
    __syncthreads();
    int lane = t & 31;
    int gid = lane >> 2, tig = lane & 3;
    int w = t >> 5;
    int r0 = (w & 3) * 16;
    int ch = (w >> 2) * 64;
    float acc[8][4];
#pragma unroll
    for (int i = 0; i < 8; i++)
#pragma unroll
        for (int j = 0; j < 4; j++) acc[i][j] = 0.f;
#pragma unroll
    for (int kt = 0; kt < 8; kt++) {
        int k0 = kt * 8;
        unsigned a0 = __float_as_uint(sX[(r0 + gid)     * NG_XST + k0 + tig]);
        unsigned a1 = __float_as_uint(sX[(r0 + gid + 8) * NG_XST + k0 + tig]);
        unsigned a2 = __float_as_uint(sX[(r0 + gid)     * NG_XST + k0 + tig + 4]);
        unsigned a3 = __float_as_uint(sX[(r0 + gid + 8) * NG_XST + k0 + tig + 4]);
#pragma unroll
        for (int nt = 0; nt < 8; nt++) {
            unsigned b0 = __float_as_uint(sW[(k0 + tig)     * NG_WST + ch + nt * 8 + gid]);
            unsigned b1v = __float_as_uint(sW[(k0 + tig + 4) * NG_WST + ch + nt * 8 + gid]);
            mma_tf32(acc[nt], a0, a1, a2, a3, b0, b1v);
        }
    }
    int nA = n0 + r0 + gid;
    int nB = nA + 8;
#pragma unroll
    for (int nt = 0; nt < 8; nt++) {
        int col = ch + nt * 8 + 2 * tig;
        float add0 = 0.f, add1 = 0.f;
        float* basep;
        int cc;
        if (col < 64) {
            add0 = s_b1[col]; add1 = s_b1[col + 1];
            basep = g_u; cc = col;
        } else {
            basep = g_v; cc = col - 64;
        }
        if (nA < Nn)
            *(float2*)(basep + nA * 64 + cc) =
                make_float2(acc[nt][0] + add0, acc[nt][1] + add1);
        if (nB < Nn)
            *(float2*)(basep + nB * 64 + cc) =
                make_float2(acc[nt][2] + add0, acc[nt][3] + add1);
    }
}

__global__ void __launch_bounds__(256) k_node_gemm8(
    const float* __restrict__ w1, const float* __restrict__ b1,
    const float* __restrict__ g, const float* __restrict__ be) {
    __shared__ float sW[64 * 16];
    __shared__ float s_sc[64], s_sh[64];
    int t = threadIdx.x;
    {
        int stride = gridDim.x * blockDim.x;
        for (int i = blockIdx.x * blockDim.x + t; i < Nn * 8; i += stride)
            g_agg[i] = 0u;
    }
    if (t < 64) {
        float mu = g_sum[t] * (1.0f / Nn);
        float var = g_sumsq[t] * (1.0f / Nn) - mu * mu;
        float sc = rsqrtf(var + 1e-5f) * g[t];
        s_sc[t] = sc;
        s_sh[t] = be[t] - mu * sc;
    }
#pragma unroll
    for (int r = 0; r < 4; r++) {
        int idx = r * 256 + t;
        int k = idx >> 4, cc = idx & 15;
        float wB = w1[(k + 64) * 8 + (cc & 7)];
        sW[idx] = (cc < 8) ? (w1[k * 8 + cc] - wB) : wB;
    }
    __syncthreads();
    int n = blockIdx.x * 16 + (t >> 4);
    int cc = t & 15;
    if (n >= Nn) return;
    const float* xr = g_x + n * 64;
    float acc = 0.f;
#pragma unroll 16
    for (int k = 0; k < 64; k++) {
        float xn = fmaf(__ldg(xr + k), s_sc[k], s_sh[k]);
        acc = fmaf(xn, sW[k * 16 + cc], acc);
    }
    if (cc < 8) g_u[n * 8 + cc] = acc + b1[cc];
    else        g_v[n * 8 + cc - 8] = acc;
}

#define EB    128
#define SA_ST 68
#define SW_ST 72
#define OFF_W    (EB * SA_ST)
#define OFF_SST  (OFF_W + 64 * SW_ST)
#define OFF_NSEG (OFF_SST + 132)
#define EDGE_SMEM ((OFF_NSEG + 4) * 4)
__global__ void __launch_bounds__(256) k_edge64(const float* __restrict__ w2t) {
    extern __shared__ __align__(16) float smem[];
    float* sA = smem;
    float* sW = smem + OFF_W;
    int* sSstart = (int*)(smem + OFF_SST);
    int* sNseg = (int*)(smem + OFF_NSEG);
    int t = threadIdx.x;
    int e0 = blockIdx.x * EB;

    if (blockIdx.x == 0 && t < 128) {
        if (t < 64) g_sum[t] = 0.f;
        else        g_sumsq[t - 64] = 0.f;
    }
    if (t < 32) {
        int base = t * 4;
        int d0 = __ldg(g_sdst + e0 + base);
        int d1 = __ldg(g_sdst + e0 + base + 1);
        int d2 = __ldg(g_sdst + e0 + base + 2);
        int d3 = __ldg(g_sdst + e0 + base + 3);
        int dm1 = (base > 0) ? __ldg(g_sdst + e0 + base - 1) : (d0 ^ 1);
        int h0 = (d0 != dm1), h1 = (d1 != d0), h2 = (d2 != d1), h3 = (d3 != d2);
        int lc0 = h0, lc1 = lc0 + h1, lc2 = lc1 + h2, lc3 = lc2 + h3;
        int c = lc3;
        int v = c;
#pragma unroll
        for (int o = 1; o < 32; o <<= 1) {
            int y = __shfl_up_sync(0xffffffffu, v, o);
            if (t >= o) v += y;
        }
        int off = v - c;
        if (h0) sSstart[off + lc0 - 1] = base;
        if (h1) sSstart[off + lc1 - 1] = base + 1;
        if (h2) sSstart[off + lc2 - 1] = base + 2;
        if (h3) sSstart[off + lc3 - 1] = base + 3;
        if (t == 31) {
            *sNseg = off + c;
            sSstart[off + c] = EB;
        }
    }
#pragma unroll
    for (int r = 0; r < 4; r++) {
        int idx = r * 256 + t;
        int k = idx >> 4, n4 = (idx & 15) << 2;
        float4 wv = *(const float4*)(w2t + k * 64 + n4);
        *(float4*)(sW + k * SW_ST + n4) = wv;
    }
#pragma unroll
    for (int r = 0; r < 8; r++) {
        int idx = r * 256 + t;
        int el = idx >> 4;
        int k4 = (idx & 15) << 2;
        int d = __ldg(g_sdst + e0 + el);
        int s = __ldg(g_ssrc + e0 + el);
        float4 uu = *(const float4*)(g_u + d * 64 + k4);
        float4 vv = *(const float4*)(g_v + s * 64 + k4);
        float4 o;
        o.x = tf32f(mishf(uu.x + vv.x));
        o.y = tf32f(mishf(uu.y + vv.y));
        o.z = tf32f(mishf(uu.z + vv.z));
        o.w = tf32f(mishf(uu.w + vv.w));
        *(float4*)(sA + el * SA_ST + k4) = o;
    }
    __syncthreads();
    int lane = t & 31;
    int gid = lane >> 2, tig = lane & 3;
    int ebase = (t >> 5) * 16;
    float acc[8][4];
#pragma unroll
    for (int i = 0; i < 8; i++)
#pragma unroll
        for (int j = 0; j < 4; j++) acc[i][j] = 0.f;
#pragma unroll
    for (int kt = 0; kt < 8; kt++) {
        int k0 = kt * 8;
        unsigned a0 = __float_as_uint(sA[(ebase + gid)     * SA_ST + k0 + tig]);
        unsigned a1 = __float_as_uint(sA[(ebase + gid + 8) * SA_ST + k0 + tig]);
        unsigned a2 = __float_as_uint(sA[(ebase + gid)     * SA_ST + k0 + tig + 4]);
        unsigned a3 = __float_as_uint(sA[(ebase + gid + 8) * SA_ST + k0 + tig + 4]);
#pragma unroll
        for (int nt = 0; nt < 8; nt++) {
            unsigned b0 = __float_as_uint(sW[(k0 + tig)     * SW_ST + nt * 8 + gid]);
            unsigned b1 = __float_as_uint(sW[(k0 + tig + 4) * SW_ST + nt * 8 + gid]);
            mma_tf32(acc[nt], a0, a1, a2, a3, b0, b1);
        }
    }
    __syncwarp();
#pragma unroll
    for (int nt = 0; nt < 8; nt++) {
        int col = nt * 8 + 2 * tig;
        *(float2*)(sA + (ebase + gid)     * SA_ST + col) = make_float2(acc[nt][0], acc[nt][1]);
        *(float2*)(sA + (ebase + gid + 8) * SA_ST + col) = make_float2(acc[nt][2], acc[nt][3]);
    }
    __syncthreads();
    int S = *sNseg;
    for (int task = t; task < S * 16; task += 256) {
        int s = task >> 4, txx = task & 15;
        int st = sSstart[s], en = sSstart[s + 1];
        const float* aP = sA + st * SA_ST + txx * 4;
        float4 m = *(const float4*)aP;
        for (int i = 1; i < en - st; i++) {
            float4 h = *(const float4*)(aP + i * SA_ST);
            m.x = fmaxf(m.x, h.x);
            m.y = fmaxf(m.y, h.y);
            m.z = fmaxf(m.z, h.z);
            m.w = fmaxf(m.w, h.w);
        }
        int dd = __ldg(g_sdst + e0 + st);
        unsigned int* p = g_agg + dd * 64 + txx * 4;
        unsigned int ex = encf(m.x), ey = encf(m.y), ez = encf(m.z), ew = encf(m.w);
        if (s == 0 || s == S - 1) {
            atomicMax(p + 0, ex);
            atomicMax(p + 1, ey);
            atomicMax(p + 2, ez);
            atomicMax(p + 3, ew);
        } else {
            *(uint4*)p = make_uint4(ex, ey, ez, ew);
        }
    }
}

__global__ void k_edge8(const float* __restrict__ w2) {
    __shared__ float sW[64];
    int t = threadIdx.x;
    if (t < 64) sW[t] = w2[t];
    __syncthreads();
    int base = (blockIdx.x * blockDim.x + t) * 8;
    if (base >= Ee) return;
    int curd = -1;
    float m[8];
#pragma unroll
    for (int j = 0; j < 8; j++) {
        int e = base + j;
        int d = g_sdst[e], s = g_ssrc[e];
        float4 u0 = *(const float4*)(g_u + d * 8);
        float4 u1 = *(const float4*)(g_u + d * 8 + 4);
        float4 v0 = *(const float4*)(g_v + s * 8);
        float4 v1 = *(const float4*)(g_v + s * 8 + 4);
        float pre[8];
        pre[0] = mishf(u0.x + v0.x); pre[1] = mishf(u0.y + v0.y);
        pre[2] = mishf(u0.z + v0.z); pre[3] = mishf(u0.w + v0.w);
        pre[4] = mishf(u1.x + v1.x); pre[5] = mishf(u1.y + v1.y);
        pre[6] = mishf(u1.z + v1.z); pre[7] = mishf(u1.w + v1.w);
        float h[8];
#pragma unroll
        for (int c = 0; c < 8; c++) {
            float a = 0.f;
#pragma unroll
            for (int k = 0; k < 8; k++) a = fmaf(pre[k], sW[k * 8 + c], a);
            h[c] = a;
        }
        if (d != curd) {
            if (curd >= 0) {
#pragma unroll
                for (int c = 0; c < 8; c++)
                    atomicMax(g_agg + curd * 8 + c, encf(m[c]));
            }
            curd = d;
#pragma unroll
            for (int c = 0; c < 8; c++) m[c] = h[c];
        } else {
#pragma unroll
            for (int c = 0; c < 8; c++) m[c] = fmaxf(m[c], h[c]);
        }
    }
#pragma unroll
    for (int c = 0; c < 8; c++) atomicMax(g_agg + curd * 8 + c, encf(m[c]));
}

__global__ void k_decode_stats64(const float* __restrict__ b2) {
    __shared__ float ss[64], sq[64];
    int t = threadIdx.x;
    if (t < 64) { ss[t] = 0.f; sq[t] = 0.f; }
    __syncthreads();
    int tid = blockIdx.x * blockDim.x + t;
    int c0 = (tid * 4) & 63;
    float4 b2v = *(const float4*)(b2 + c0);
    float4 lsum = make_float4(0.f, 0.f, 0.f, 0.f);
    float4 lsq  = make_float4(0.f, 0.f, 0.f, 0.f);
    int stride = gridDim.x * blockDim.x;
    for (int i = tid; i < Nn * 16; i += stride) {
        uint4 a = ((const uint4*)g_agg)[i];
        float4 val;
        val.x = (a.x == 0u) ? 0.f : (decf(a.x) + b2v.x);
        val.y = (a.y == 0u) ? 0.f : (decf(a.y) + b2v.y);
        val.z = (a.z == 0u) ? 0.f : (decf(a.z) + b2v.z);
        val.w = (a.w == 0u) ? 0.f : (decf(a.w) + b2v.w);
        ((float4*)g_x)[i] = val;
        lsum.x += val.x; lsum.y += val.y; lsum.z += val.z; lsum.w += val.w;
        lsq.x += val.x * val.x; lsq.y += val.y * val.y;
        lsq.z += val.z * val.z; lsq.w += val.w * val.w;
    }
    atomicAdd(&ss[c0 + 0], lsum.x);
    atomicAdd(&ss[c0 + 1], lsum.y);
    atomicAdd(&ss[c0 + 2], lsum.z);
    atomicAdd(&ss[c0 + 3], lsum.w);
    atomicAdd(&sq[c0 + 0], lsq.x);
    atomicAdd(&sq[c0 + 1], lsq.y);
    atomicAdd(&sq[c0 + 2], lsq.z);
    atomicAdd(&sq[c0 + 3], lsq.w);
    __syncthreads();
    if (t < 64) {
        atomicAdd(&g_sum[t], ss[t]);
        atomicAdd(&g_sumsq[t], sq[t]);
    }
}

// final decode to output (float4, 4 elems/thread; channel group invariant)
__global__ void k_decode_out(float* __restrict__ out, const float* __restrict__ b2) {
    int i = blockIdx.x * blockDim.x + threadIdx.x;
    if (i < Nn * 2) {                       // Nn*8 / 4
        int c0 = (i * 4) & 7;
        float b20 = b2[c0 + 0], b21 = b2[c0 + 1];
        float b22 = b2[c0 + 2], b23 = b2[c0 + 3];
        uint4 a = ((const uint4*)g_agg)[i];
        float4 val;
        val.x = (a.x == 0u) ? 0.f : (decf(a.x) + b20);
        val.y = (a.y == 0u) ? 0.f : (decf(a.y) + b21);
        val.z = (a.z == 0u) ? 0.f : (decf(a.z) + b22);
        val.w = (a.w == 0u) ? 0.f : (decf(a.w) + b23);
        ((float4*)out)[i] = val;
    }
}

// ---------------- launch ----------------
extern "C" void kernel_launch(void* const* d_in, const int* in_sizes, int n_in,
                              void* d_out, int out_size) {
    const float* x  = (const float*)d_in[0];
    const int*   ei = (const int*)d_in[1];
    const int* src = ei;
    const int* dst = ei + Ee;

    const float* W1[4] = {(const float*)d_in[3], (const float*)d_in[9],
                          (const float*)d_in[15], (const float*)d_in[21]};
    const float* B1[4] = {(const float*)d_in[4], (const float*)d_in[10],
                          (const float*)d_in[16], (const float*)d_in[22]};
    const float* W2[4] = {(const float*)d_in[5], (const float*)d_in[11],
                          (const float*)d_in[17], (const float*)d_in[23]};
    const float* B2[4] = {(const float*)d_in[6], (const float*)d_in[12],
                          (const float*)d_in[18], (const float*)d_in[24]};
    const float* G[3]  = {(const float*)d_in[7], (const float*)d_in[13],
                          (const float*)d_in[19]};
    const float* BE[3] = {(const float*)d_in[8], (const float*)d_in[14],
                          (const float*)d_in[20]};

    cudaFuncSetAttribute(k_edge64, cudaFuncAttributeMaxDynamicSharedMemorySize,
                         EDGE_SMEM);
    cudaFuncSetAttribute(k_node_gemm64, cudaFuncAttributeMaxDynamicSharedMemorySize,
                         NG_SMEM);

    float* w1t_base = nullptr;
    float* w2t_base = nullptr;
    cudaGetSymbolAddress((void**)&w1t_base, g_w1t);
    cudaGetSymbolAddress((void**)&w2t_base, g_w2t);

    // fused: histogram + one-time tf32 weight conversion
    k_hist_prep<<<(Ee / 4 + 255) / 256, 256>>>(
        dst, W1[0], W2[0], W1[1], W2[1], W1[2], W2[2]);
    // parallel two-level scan (scan_local also re-zeroes g_hist)
    k_scan_local<<<NBLK, 256>>>();
    k_scan_block<<<1, 256>>>();
    k_scatter<<<(Ee / 4 + 255) / 256, 256>>>(src, dst);

    // layers 0..2 (din=dout=64); BN of layer l-1 folded into node GEMM of l
    for (int l = 0; l < 3; l++) {
        k_node_gemm64<<<(Nn + 63) / 64, 256, NG_SMEM>>>(
            l == 0 ? x : nullptr, w1t_base + l * 64 * 128, B1[l],
            l == 0 ? nullptr : G[l - 1], l == 0 ? nullptr : BE[l - 1]);
        k_edge64<<<Ee / EB, 256, EDGE_SMEM>>>(w2t_base + l * 64 * 64);
        k_decode_stats64<<<592, 256>>>(B2[l]);
    }

    // layer 3 (din=64, dout=8, BN of layer2 folded) -> d_out
    k_node_gemm8<<<(Nn + 15) / 16, 256>>>(W1[3], B1[3], G[2], BE[2]);
    k_edge8<<<(Ee / 8 + 255) / 256, 256>>>(W2[3]);
    k_decode_out<<<(Nn * 2 + 255) / 256, 256>>>((float*)d_out, B2[3]);
}